// round 7
// baseline (speedup 1.0000x reference)
#include <cuda_runtime.h>
#include <cuda_bf16.h>
#include <cuda_fp16.h>
#include <cstdint>
#include <math.h>

// ---------------------------------------------------------------------------
// CapsNet forward. B=512.
//   conv1:  [512,1,28,28] -> relu -> channel-last fp16 [b,iy,ix,ic]
//   pcconv: fp16 mma.sync implicit GEMM (cp.async 3-stage, M=128 N=256 /CTA)
//   squash over 1152 -> hT; u_hat (fp16); routing x3 (no b-logit storage:
//   logits == u.vsum, vsum = running sum of v); decoder FCs; probs
// Output: [probs (512*10)] then [dec (512*784)]
// ---------------------------------------------------------------------------

#define BATCH 512

__device__ __half g_cl[BATCH * 400 * 256];        // conv1 out, channel-last fp16
__device__ __half g_wr[256 * 81 * 256];           // pc weights [oc][tap][ic] fp16
__device__ float g_pc[BATCH * 256 * 36];
__device__ float g_hT[BATCH * 1152 * 8];
__device__ __half g_uhat[BATCH * 1152 * 160];     // fp16 storage
__device__ float g_v[BATCH * 160];
__device__ float g_vsum[BATCH * 160];
__device__ float g_m[BATCH * 160];
__device__ float g_fc1[BATCH * 512];
__device__ float g_fc2[BATCH * 1024];

// ---------------- helpers ---------------------------------------------------
__device__ __forceinline__ uint32_t smem_u32(const void* p) {
    uint32_t a;
    asm("{ .reg .u64 t; cvta.to.shared.u64 t, %1; cvt.u32.u64 %0, t; }"
        : "=r"(a) : "l"(p));
    return a;
}
__device__ __forceinline__ void ldsm_x4(uint32_t& d0, uint32_t& d1,
                                        uint32_t& d2, uint32_t& d3,
                                        uint32_t addr) {
    asm volatile("ldmatrix.sync.aligned.m8n8.x4.shared.b16 {%0,%1,%2,%3}, [%4];"
                 : "=r"(d0), "=r"(d1), "=r"(d2), "=r"(d3) : "r"(addr));
}
__device__ __forceinline__ void mma16816h(float* c, const uint32_t* a,
                                          const uint32_t* b) {
    asm volatile(
        "mma.sync.aligned.m16n8k16.row.col.f32.f16.f16.f32 "
        "{%0,%1,%2,%3}, {%4,%5,%6,%7}, {%8,%9}, {%0,%1,%2,%3};"
        : "+f"(c[0]), "+f"(c[1]), "+f"(c[2]), "+f"(c[3])
        : "r"(a[0]), "r"(a[1]), "r"(a[2]), "r"(a[3]), "r"(b[0]), "r"(b[1]));
}
#define CP16(dst, src) \
    asm volatile("cp.async.cg.shared.global [%0], [%1], 16;" \
                 :: "r"(dst), "l"(src) : "memory")
#define CP_COMMIT() asm volatile("cp.async.commit_group;" ::: "memory")
#define CP_WAIT1() asm volatile("cp.async.wait_group 1;" ::: "memory")
#define CP_WAIT0() asm volatile("cp.async.wait_group 0;" ::: "memory")

// fp32x2 helpers for conv1
__device__ __forceinline__ void ffma2(unsigned long long& d,
                                      unsigned long long a,
                                      unsigned long long b) {
    asm("fma.rn.f32x2 %0, %1, %2, %0;" : "+l"(d) : "l"(a), "l"(b));
}
__device__ __forceinline__ unsigned long long pack2(float v) {
    unsigned long long r;
    asm("mov.b64 %0, {%1, %2};" : "=l"(r) : "f"(v), "f"(v));
    return r;
}
__device__ __forceinline__ void unpack2(unsigned long long p, float& lo, float& hi) {
    asm("mov.b64 {%0, %1}, %2;" : "=f"(lo), "=f"(hi) : "l"(p));
}

#define CW 68

// ---------------------------------------------------------------------------
// conv1: 1->256, 9x9, valid, relu -> channel-last fp16. grid (512,4), blk 128.
// ---------------------------------------------------------------------------
__global__ __launch_bounds__(128, 4) void conv1_kernel(
    const float* __restrict__ x, const float* __restrict__ w,
    const float* __restrict__ bias)
{
    int b = blockIdx.x;
    int ocg = blockIdx.y;
    __shared__ float s_img[784];
    __shared__ float s_w[81 * CW];
    int tid = threadIdx.x;

    for (int i = tid; i < 196; i += 128)
        *(float4*)&s_img[i * 4] = *(const float4*)&x[b * 784 + i * 4];
    for (int i = tid; i < 64 * 81; i += 128) {
        int r = i / 81;
        int e = i - r * 81;
        s_w[e * CW + r] = w[(ocg * 64 + r) * 81 + e];
    }
    __syncthreads();

    int ocp = tid & 31;
    int yg = tid >> 5;
    int oc0 = ocg * 64 + ocp * 2;
    float bv0 = bias[oc0], bv1 = bias[oc0 + 1];

    for (int yi = 0; yi < 5; yi++) {
        int y = yg * 5 + yi;
        unsigned long long acc[20];
        #pragma unroll
        for (int xx = 0; xx < 20; xx++) acc[xx] = 0ull;

        for (int ky = 0; ky < 9; ky++) {
            const float* rowp = s_img + (y + ky) * 28;
            unsigned long long rp[28];
            #pragma unroll
            for (int q = 0; q < 7; q++) {
                float4 r4 = *(const float4*)(rowp + q * 4);
                rp[q * 4 + 0] = pack2(r4.x);
                rp[q * 4 + 1] = pack2(r4.y);
                rp[q * 4 + 2] = pack2(r4.z);
                rp[q * 4 + 3] = pack2(r4.w);
            }
            #pragma unroll
            for (int kx = 0; kx < 9; kx++) {
                unsigned long long wp =
                    *(const unsigned long long*)(s_w + (ky * 9 + kx) * CW + ocp * 2);
                #pragma unroll
                for (int xx = 0; xx < 20; xx++) ffma2(acc[xx], wp, rp[xx + kx]);
            }
        }
        #pragma unroll
        for (int xx = 0; xx < 20; xx++) {
            float v0, v1;
            unpack2(acc[xx], v0, v1);
            v0 = fmaxf(v0 + bv0, 0.f);
            v1 = fmaxf(v1 + bv1, 0.f);
            int idx32 = ((b * 20 + y) * 20 + xx) * 128 + ocg * 32 + ocp;
            ((__half2*)g_cl)[idx32] = __floats2half2_rn(v0, v1);
        }
    }
}

// ---------------------------------------------------------------------------
// weight relayout via smem transpose: pc_w [oc][ic][81] -> g_wr [oc][tap][ic]
// ---------------------------------------------------------------------------
__global__ __launch_bounds__(256) void wrelayout_kernel(const float* __restrict__ w)
{
    extern __shared__ char wsm[];
    __half* sh = (__half*)wsm;
    int oc = blockIdx.x;
    int tid = threadIdx.x;
    const float* src = w + (size_t)oc * 20736;

    for (int j = tid; j < 20736; j += 256) {
        int ic = j / 81;
        int e = j - ic * 81;
        sh[e * 256 + ic] = __float2half(src[j]);
    }
    __syncthreads();

    uint4* dh = (uint4*)(g_wr + (size_t)oc * 20736);
    const uint4* s4 = (const uint4*)sh;
    for (int j = tid; j < 2592; j += 256) dh[j] = s4[j];
}

// ---------------------------------------------------------------------------
// pcconv: fp16 implicit GEMM, cp.async 3-stage, M=128 x N=256 per CTA.
// grid 144, block 256 (8 warps 4(M)x2(N)). K = 81 taps x 4 ic-chunks of 64.
// One __syncthreads per k-chunk.
// ---------------------------------------------------------------------------
#define SM_A 0
#define SM_B 16384
#define STAGE 49152
#define PCG_SMEM (3 * STAGE)

__global__ __launch_bounds__(256, 1) void pcgemm_kernel(const float* __restrict__ bias)
{
    extern __shared__ char sm[];
    __shared__ int s_rowbase[128];

    int tid = threadIdx.x;
    int wid = tid >> 5;
    int lane = tid & 31;
    int warp_m = wid & 3;
    int warp_n = wid >> 2;
    int m0 = blockIdx.x * 128;
    uint32_t smb = smem_u32(sm);

    if (tid < 128) {
        int npos = m0 + tid;
        int b = npos / 36;
        int pos = npos - b * 36;
        int y = pos / 6;
        int xq = pos - y * 6;
        s_rowbase[tid] = ((b * 20 + 2 * y) * 20 + 2 * xq) * 256;
    }
    __syncthreads();

    int r0 = tid >> 3;   // 0..31
    int c = tid & 7;
    uint32_t dbase = (uint32_t)(r0 * 128) + (uint32_t)((c * 16) ^ ((r0 & 7) << 4));
    int rb[4];
    #pragma unroll
    for (int i = 0; i < 4; i++) rb[i] = s_rowbase[r0 + 32 * i];
    int bbase0 = r0 * 20736;

#define PCG_ISSUE(K, ST) do { \
    int _kykx = (K) >> 2; \
    int _ic0 = ((K) & 3) << 6; \
    int _ky = _kykx / 9; \
    int _kx = _kykx - _ky * 9; \
    int _asrc = (_ky * 20 + _kx) * 256 + _ic0 + c * 8; \
    int _bsrc = _kykx * 256 + _ic0 + c * 8; \
    uint32_t _st = smb + (uint32_t)(ST) * STAGE; \
    _Pragma("unroll") \
    for (int _i = 0; _i < 4; _i++) \
        CP16(_st + SM_A + dbase + _i * 4096, g_cl + rb[_i] + _asrc); \
    _Pragma("unroll") \
    for (int _t = 0; _t < 8; _t++) \
        CP16(_st + SM_B + dbase + _t * 4096, g_wr + bbase0 + _t * 663552 + _bsrc); \
} while (0)

    float acc[2][16][4];
    #pragma unroll
    for (int i = 0; i < 2; i++)
        #pragma unroll
        for (int j = 0; j < 16; j++)
            #pragma unroll
            for (int k = 0; k < 4; k++) acc[i][j][k] = 0.f;

    uint32_t swz = (uint32_t)(lane & 7) << 4;
    uint32_t a_row_off = SM_A + (uint32_t)(warp_m * 32 + (lane & 15)) * 128;
    uint32_t akb = (uint32_t)(lane >> 4) << 4;
    uint32_t b_row_off = SM_B +
        (uint32_t)(warp_n * 128 + (lane & 7) + ((lane >> 4) & 1) * 8) * 128;
    uint32_t bkb = (uint32_t)((lane >> 3) & 1) << 4;

    PCG_ISSUE(0, 0);
    CP_COMMIT();
    PCG_ISSUE(1, 1);
    CP_COMMIT();

    int stage = 0;    // kc % 3
    int stage2 = 2;   // (kc+2) % 3
    for (int kc = 0; kc < 324; kc++) {
        if (kc < 323) CP_WAIT1(); else CP_WAIT0();
        __syncthreads();
        if (kc < 322) {
            PCG_ISSUE(kc + 2, stage2);
            CP_COMMIT();
        }

        uint32_t st = smb + (uint32_t)stage * STAGE;
        uint32_t a_row = st + a_row_off;
        uint32_t b_row = st + b_row_off;
        #pragma unroll
        for (int j = 0; j < 4; j++) {
            uint32_t ka = ((uint32_t)(j * 32) + akb) ^ swz;
            uint32_t ah[8];
            ldsm_x4(ah[0], ah[1], ah[2], ah[3], a_row + ka);
            ldsm_x4(ah[4], ah[5], ah[6], ah[7], a_row + 2048 + ka);
            uint32_t kb = ((uint32_t)(j * 32) + bkb) ^ swz;
            #pragma unroll
            for (int h = 0; h < 2; h++) {
                uint32_t bh[16];
                #pragma unroll
                for (int q = 0; q < 4; q++) {
                    uint32_t bt = b_row + (uint32_t)((h * 4 + q) * 2048) + kb;
                    ldsm_x4(bh[4 * q], bh[4 * q + 1], bh[4 * q + 2], bh[4 * q + 3], bt);
                }
                #pragma unroll
                for (int q = 0; q < 4; q++) {
                    #pragma unroll
                    for (int sub = 0; sub < 2; sub++) {
                        int nn = h * 8 + q * 2 + sub;
                        #pragma unroll
                        for (int tm = 0; tm < 2; tm++)
                            mma16816h(acc[tm][nn], &ah[4 * tm], &bh[4 * q + 2 * sub]);
                    }
                }
            }
        }
        stage = (stage == 2) ? 0 : stage + 1;
        stage2 = (stage2 == 2) ? 0 : stage2 + 1;
    }

    // epilogue
    int r_in8 = lane >> 2;
    int c_in8 = (lane & 3) * 2;
    #pragma unroll
    for (int tm = 0; tm < 2; tm++) {
        int row0 = m0 + warp_m * 32 + tm * 16 + r_in8;
        int b0i = row0 / 36, p0i = row0 - b0i * 36;
        int row1 = row0 + 8;
        int b1i = row1 / 36, p1i = row1 - b1i * 36;
        #pragma unroll
        for (int nn = 0; nn < 16; nn++) {
            int col = warp_n * 128 + nn * 8 + c_in8;
            float bv0 = __ldg(bias + col);
            float bv1 = __ldg(bias + col + 1);
            const float* cc2 = acc[tm][nn];
            g_pc[b0i * 9216 + col * 36 + p0i] = cc2[0] + bv0;
            g_pc[b0i * 9216 + (col + 1) * 36 + p0i] = cc2[1] + bv1;
            g_pc[b1i * 9216 + col * 36 + p1i] = cc2[2] + bv0;
            g_pc[b1i * 9216 + (col + 1) * 36 + p1i] = cc2[3] + bv1;
        }
    }
}

// ---------------------------------------------------------------------------
// squash over 1152 + transpose to hT (smem-staged, coalesced writes).
// ---------------------------------------------------------------------------
__global__ __launch_bounds__(256) void squash_h_kernel()
{
    int b = blockIdx.x;
    int tid = threadIdx.x;
    __shared__ float s_scale[8];
    __shared__ float s_val[9216];
    int g = tid >> 5;
    int lane = tid & 31;
    const float* pb = g_pc + (size_t)b * 9216;

    float ss = 0.f;
    for (int j = lane; j < 1152; j += 32) {
        float v = pb[g * 1152 + j];
        ss += v * v;
    }
    #pragma unroll
    for (int o = 16; o; o >>= 1) ss += __shfl_xor_sync(0xffffffffu, ss, o);
    if (lane == 0) s_scale[g] = sqrtf(ss) / (1.f + ss);
    __syncthreads();

    for (int idx = tid; idx < 9216; idx += 256) {
        int cch = idx / 36;
        s_val[idx] = pb[idx] * s_scale[cch >> 5];
    }
    __syncthreads();

    float* outb = g_hT + (size_t)b * 9216;
    for (int o = tid; o < 9216; o += 256) {
        int pos = o >> 3;
        int g2 = o & 7;
        int cch = g2 * 32 + pos / 36;
        int s = pos % 36;
        outb[o] = s_val[cch * 36 + s];
    }
}

// ---------------------------------------------------------------------------
// u_hat (fp16 out): grid 1152, block 256.
// ---------------------------------------------------------------------------
__global__ __launch_bounds__(256) void uhat_kernel(const float* __restrict__ W)
{
    int i = blockIdx.x;
    __shared__ float sW[1280];
    __shared__ float sh[32 * 8];
    int tid = threadIdx.x;
    for (int j = tid; j < 1280; j += 256)
        sW[(j & 7) * 160 + (j >> 3)] = W[(size_t)i * 1280 + j];

    for (int b0 = 0; b0 < BATCH; b0 += 32) {
        __syncthreads();
        sh[tid] = g_hT[((size_t)(b0 + (tid >> 3)) * 1152 + i) * 8 + (tid & 7)];
        __syncthreads();
        if (tid < 160) {
            #pragma unroll 4
            for (int bb = 0; bb < 32; bb++) {
                float u = 0.f;
                #pragma unroll
                for (int e = 0; e < 8; e++) u += sW[e * 160 + tid] * sh[bb * 8 + e];
                g_uhat[((size_t)(b0 + bb) * 1152 + i) * 160 + tid] = __float2half(u);
            }
        }
    }
}

// ---------------------------------------------------------------------------
// routing iter 0: s = 0.1*sum_i u (warp-split), v = squash; vsum = v.
// grid 512, block 256.
// ---------------------------------------------------------------------------
__global__ __launch_bounds__(256) void routing0_kernel()
{
    int b = blockIdx.x;
    int t = threadIdx.x;
    int w = t >> 5;
    int l = t & 31;
    __shared__ float spart[8][160];
    __shared__ float s_s[160];

    const __half* ub = g_uhat + (size_t)b * 184320;
    float acc[5] = {0.f, 0.f, 0.f, 0.f, 0.f};
    int i0 = w * 144;
    for (int i = i0; i < i0 + 144; i++) {
        #pragma unroll
        for (int q = 0; q < 5; q++)
            acc[q] += __half2float(__ldg(ub + i * 160 + l + 32 * q));
    }
    #pragma unroll
    for (int q = 0; q < 5; q++) spart[w][l + 32 * q] = acc[q];
    __syncthreads();

    if (t < 160) {
        float s = 0.f;
        #pragma unroll
        for (int w2 = 0; w2 < 8; w2++) s += spart[w2][t];
        s_s[t] = 0.1f * s;
    }
    __syncthreads();
    if (t < 160) {
        int k = t >> 4;
        float n2 = 0.f;
        #pragma unroll
        for (int d = 0; d < 16; d++) {
            float v = s_s[k * 16 + d];
            n2 += v * v;
        }
        float v = s_s[t] * (sqrtf(n2) / (1.f + n2));
        g_v[b * 160 + t] = v;
        g_vsum[b * 160 + t] = v;
    }
}

// ---------------------------------------------------------------------------
// routing iter (r=1,2): logits = u.vsum (additive identity, no b storage);
// c = softmax_k; s = sum_i c*u (warp-split phase B); v = squash; vsum += v.
// grid 512, block 256, dynamic smem 52480 B.
// ---------------------------------------------------------------------------
__global__ __launch_bounds__(256) void routing_iter_kernel()
{
    extern __shared__ float rsm[];
    float* c_s = rsm;              // 11520
    float* v_s = rsm + 11520;      // 160 (holds vsum)
    float* spart = rsm + 11680;    // 8*160
    float* s_s = rsm + 12960;      // 160

    int b = blockIdx.x;
    int t = threadIdx.x;
    int w = t >> 5;
    int l = t & 31;

    if (t < 160) v_s[t] = g_vsum[b * 160 + t];
    __syncthreads();

    const __half* ub = g_uhat + (size_t)b * 184320;

    // Phase A: per-row logits u.vsum + softmax -> c_s
    for (int i = t; i < 1152; i += 256) {
        const __half2* u2 = (const __half2*)(ub + i * 160);
        float bl[10];
        float mx = -1e30f;
        #pragma unroll
        for (int k = 0; k < 10; k++) {
            float dk = 0.f;
            #pragma unroll
            for (int j = 0; j < 8; j++) {
                float2 u = __half22float2(u2[k * 8 + j]);
                dk += u.x * v_s[k * 16 + 2 * j + 0];
                dk += u.y * v_s[k * 16 + 2 * j + 1];
            }
            bl[k] = dk;
            mx = fmaxf(mx, dk);
        }
        float sum = 0.f;
        #pragma unroll
        for (int k = 0; k < 10; k++) {
            float e = __expf(bl[k] - mx);
            bl[k] = e;
            sum += e;
        }
        float inv = 1.f / sum;
        #pragma unroll
        for (int k = 0; k < 10; k++) c_s[i * 10 + k] = bl[k] * inv;
    }
    __syncthreads();

    // Phase B: warp-split s accumulation. lane l covers kd = l+32q,
    // capsule k = 2q + (l>>4). c broadcast from smem.
    {
        float acc[5] = {0.f, 0.f, 0.f, 0.f, 0.f};
        int hb = l >> 4;
        int i0 = w * 144;
        for (int i = i0; i < i0 + 144; i++) {
            #pragma unroll
            for (int q = 0; q < 5; q++) {
                float u = __half2float(__ldg(ub + i * 160 + l + 32 * q));
                acc[q] += c_s[i * 10 + 2 * q + hb] * u;
            }
        }
        #pragma unroll
        for (int q = 0; q < 5; q++) spart[w * 160 + l + 32 * q] = acc[q];
    }
    __syncthreads();

    if (t < 160) {
        float s = 0.f;
        #pragma unroll
        for (int w2 = 0; w2 < 8; w2++) s += spart[w2 * 160 + t];
        s_s[t] = s;
    }
    __syncthreads();
    if (t < 160) {
        int k = t >> 4;
        float n2 = 0.f;
        #pragma unroll
        for (int d = 0; d < 16; d++) {
            float v = s_s[k * 16 + d];
            n2 += v * v;
        }
        float v = s_s[t] * (sqrtf(n2) / (1.f + n2));
        g_v[b * 160 + t] = v;
        g_vsum[b * 160 + t] = v_s[t] + v;
    }
}

// ---------------------------------------------------------------------------
__global__ void mask_kernel(const float* __restrict__ labels)
{
    int idx = blockIdx.x * 256 + threadIdx.x;
    if (idx < BATCH * 160) {
        int b = idx / 160;
        int k = (idx - b * 160) >> 4;
        g_m[idx] = g_v[idx] * labels[b * 10 + k];
    }
}

// ---------------------------------------------------------------------------
template <int ACT, int SEL>
__global__ __launch_bounds__(256) void gemm_kernel(
    const float* __restrict__ Wt, const float* __restrict__ bias,
    float* __restrict__ outp, int M, int N, int K)
{
    const float* A = (SEL == 0) ? g_m : (SEL == 1) ? g_fc1 : g_fc2;
    float* C = (SEL == 0) ? g_fc1 : (SEL == 1) ? g_fc2 : outp;

    __shared__ float As[8][64];
    __shared__ float Bs[8][64];
    int n0 = blockIdx.x * 64;
    int m0 = blockIdx.y * 64;
    int tid = threadIdx.x;
    int tx = tid & 15;
    int ty = tid >> 4;

    float acc[4][4];
    #pragma unroll
    for (int i = 0; i < 4; i++)
        #pragma unroll
        for (int j = 0; j < 4; j++) acc[i][j] = 0.f;

    for (int k0 = 0; k0 < K; k0 += 8) {
        __syncthreads();
        #pragma unroll
        for (int l = 0; l < 2; l++) {
            int e = tid + l * 256;
            int r = e >> 3;
            int kk = e & 7;
            As[kk][r] = A[(m0 + r) * K + k0 + kk];
            int n = n0 + r;
            Bs[kk][r] = (n < N) ? Wt[n * K + k0 + kk] : 0.f;
        }
        __syncthreads();
        #pragma unroll
        for (int kk = 0; kk < 8; kk++) {
            float4 a4 = *(const float4*)&As[kk][ty * 4];
            float4 b4 = *(const float4*)&Bs[kk][tx * 4];
            float a[4] = {a4.x, a4.y, a4.z, a4.w};
            float bb[4] = {b4.x, b4.y, b4.z, b4.w};
            #pragma unroll
            for (int i = 0; i < 4; i++)
                #pragma unroll
                for (int j = 0; j < 4; j++) acc[i][j] += a[i] * bb[j];
        }
    }

    #pragma unroll
    for (int i = 0; i < 4; i++) {
        int m = m0 + ty * 4 + i;
        #pragma unroll
        for (int j = 0; j < 4; j++) {
            int n = n0 + tx * 4 + j;
            if (n < N) {
                float v = acc[i][j] + bias[n];
                if (ACT == 0) v = fmaxf(v, 0.f);
                else v = 1.f / (1.f + __expf(-v));
                C[m * N + n] = v;
            }
        }
    }
}

// ---------------------------------------------------------------------------
__global__ void probs_kernel(float* __restrict__ out)
{
    int b = blockIdx.x * 128 + threadIdx.x;
    if (b < BATCH) {
        float nr[10];
        float mx = -1e30f;
        #pragma unroll
        for (int k = 0; k < 10; k++) {
            float n2 = 0.f;
            #pragma unroll
            for (int d = 0; d < 16; d++) {
                float v = g_v[b * 160 + k * 16 + d];
                n2 += v * v;
            }
            nr[k] = sqrtf(n2);
            mx = fmaxf(mx, nr[k]);
        }
        float sum = 0.f;
        #pragma unroll
        for (int k = 0; k < 10; k++) {
            nr[k] = __expf(nr[k] - mx);
            sum += nr[k];
        }
        float inv = 1.f / sum;
        #pragma unroll
        for (int k = 0; k < 10; k++) out[b * 10 + k] = nr[k] * inv;
    }
}

// ---------------------------------------------------------------------------
extern "C" void kernel_launch(void* const* d_in, const int* in_sizes, int n_in,
                              void* d_out, int out_size)
{
    const float* x       = (const float*)d_in[0];
    const float* labels  = (const float*)d_in[1];
    const float* conv1_w = (const float*)d_in[2];
    const float* conv1_b = (const float*)d_in[3];
    const float* pc_w    = (const float*)d_in[4];
    const float* pc_b    = (const float*)d_in[5];
    const float* W       = (const float*)d_in[6];
    const float* fc1_w   = (const float*)d_in[7];
    const float* fc1_b   = (const float*)d_in[8];
    const float* fc2_w   = (const float*)d_in[9];
    const float* fc2_b   = (const float*)d_in[10];
    const float* fc3_w   = (const float*)d_in[11];
    const float* fc3_b   = (const float*)d_in[12];
    float* out = (float*)d_out;

    cudaFuncSetAttribute(pcgemm_kernel,
                         cudaFuncAttributeMaxDynamicSharedMemorySize, PCG_SMEM);
    cudaFuncSetAttribute(wrelayout_kernel,
                         cudaFuncAttributeMaxDynamicSharedMemorySize, 43008);
    cudaFuncSetAttribute(routing_iter_kernel,
                         cudaFuncAttributeMaxDynamicSharedMemorySize, 53248);

    conv1_kernel<<<dim3(BATCH, 4), 128>>>(x, conv1_w, conv1_b);
    wrelayout_kernel<<<256, 256, 43008>>>(pc_w);
    pcgemm_kernel<<<144, 256, PCG_SMEM>>>(pc_b);
    squash_h_kernel<<<BATCH, 256>>>();
    uhat_kernel<<<1152, 256>>>(W);
    routing0_kernel<<<BATCH, 256>>>();
    routing_iter_kernel<<<BATCH, 256, 53248>>>();
    routing_iter_kernel<<<BATCH, 256, 53248>>>();
    mask_kernel<<<320, 256>>>(labels);
    gemm_kernel<0, 0><<<dim3(8, 8), 256>>>(fc1_w, fc1_b, out, 512, 512, 160);
    gemm_kernel<0, 1><<<dim3(16, 8), 256>>>(fc2_w, fc2_b, out, 512, 1024, 512);
    gemm_kernel<1, 2><<<dim3(13, 8), 256>>>(fc3_w, fc3_b, out + 5120, 512, 784, 1024);
    probs_kernel<<<4, 128>>>(out);
}

// round 9
// speedup vs baseline: 1.0085x; 1.0085x over previous
#include <cuda_runtime.h>
#include <cuda_bf16.h>
#include <cuda_fp16.h>
#include <cstdint>
#include <math.h>

// ---------------------------------------------------------------------------
// CapsNet forward. B=512.
//   conv1:  [512,1,28,28] -> relu -> channel-last fp16 [b,iy,ix,ic]
//   pcconv: fp16 mma.sync implicit GEMM (cp.async 2-stage, M=128 N=256 /CTA)
//   squash over 1152 -> hT; u_hat (fp16); routing x3 (no b-logit storage:
//   logits == u.vsum, vsum = running sum of v); decoder FCs; probs
// Output: [probs (512*10)] then [dec (512*784)]
// ---------------------------------------------------------------------------

#define BATCH 512

__device__ __half g_cl[BATCH * 400 * 256];        // conv1 out, channel-last fp16
__device__ __half g_wr[256 * 81 * 256];           // pc weights [oc][tap][ic] fp16
__device__ float g_pc[BATCH * 256 * 36];
__device__ float g_hT[BATCH * 1152 * 8];
__device__ __half g_uhat[BATCH * 1152 * 160];     // fp16 storage
__device__ float g_v[BATCH * 160];
__device__ float g_vsum[BATCH * 160];
__device__ float g_m[BATCH * 160];
__device__ float g_fc1[BATCH * 512];
__device__ float g_fc2[BATCH * 1024];

// ---------------- helpers ---------------------------------------------------
__device__ __forceinline__ uint32_t smem_u32(const void* p) {
    uint32_t a;
    asm("{ .reg .u64 t; cvta.to.shared.u64 t, %1; cvt.u32.u64 %0, t; }"
        : "=r"(a) : "l"(p));
    return a;
}
__device__ __forceinline__ void ldsm_x4(uint32_t& d0, uint32_t& d1,
                                        uint32_t& d2, uint32_t& d3,
                                        uint32_t addr) {
    asm volatile("ldmatrix.sync.aligned.m8n8.x4.shared.b16 {%0,%1,%2,%3}, [%4];"
                 : "=r"(d0), "=r"(d1), "=r"(d2), "=r"(d3) : "r"(addr));
}
__device__ __forceinline__ void mma16816h(float* c, const uint32_t* a,
                                          const uint32_t* b) {
    asm volatile(
        "mma.sync.aligned.m16n8k16.row.col.f32.f16.f16.f32 "
        "{%0,%1,%2,%3}, {%4,%5,%6,%7}, {%8,%9}, {%0,%1,%2,%3};"
        : "+f"(c[0]), "+f"(c[1]), "+f"(c[2]), "+f"(c[3])
        : "r"(a[0]), "r"(a[1]), "r"(a[2]), "r"(a[3]), "r"(b[0]), "r"(b[1]));
}
#define CP16(dst, src) \
    asm volatile("cp.async.cg.shared.global [%0], [%1], 16;" \
                 :: "r"(dst), "l"(src) : "memory")
#define CP_COMMIT() asm volatile("cp.async.commit_group;" ::: "memory")
#define CP_WAIT1() asm volatile("cp.async.wait_group 1;" ::: "memory")
#define CP_WAIT0() asm volatile("cp.async.wait_group 0;" ::: "memory")

// fp32x2 helpers for conv1
__device__ __forceinline__ void ffma2(unsigned long long& d,
                                      unsigned long long a,
                                      unsigned long long b) {
    asm("fma.rn.f32x2 %0, %1, %2, %0;" : "+l"(d) : "l"(a), "l"(b));
}
__device__ __forceinline__ unsigned long long pack2(float v) {
    unsigned long long r;
    asm("mov.b64 %0, {%1, %2};" : "=l"(r) : "f"(v), "f"(v));
    return r;
}
__device__ __forceinline__ void unpack2(unsigned long long p, float& lo, float& hi) {
    asm("mov.b64 {%0, %1}, %2;" : "=f"(lo), "=f"(hi) : "l"(p));
}

#define CW 68

// ---------------------------------------------------------------------------
// conv1: 1->256, 9x9, valid, relu -> channel-last fp16. grid (512,4), blk 128.
// ---------------------------------------------------------------------------
__global__ __launch_bounds__(128, 4) void conv1_kernel(
    const float* __restrict__ x, const float* __restrict__ w,
    const float* __restrict__ bias)
{
    int b = blockIdx.x;
    int ocg = blockIdx.y;
    __shared__ float s_img[784];
    __shared__ float s_w[81 * CW];
    int tid = threadIdx.x;

    for (int i = tid; i < 196; i += 128)
        *(float4*)&s_img[i * 4] = *(const float4*)&x[b * 784 + i * 4];
    for (int i = tid; i < 64 * 81; i += 128) {
        int r = i / 81;
        int e = i - r * 81;
        s_w[e * CW + r] = w[(ocg * 64 + r) * 81 + e];
    }
    __syncthreads();

    int ocp = tid & 31;
    int yg = tid >> 5;
    int oc0 = ocg * 64 + ocp * 2;
    float bv0 = bias[oc0], bv1 = bias[oc0 + 1];

    for (int yi = 0; yi < 5; yi++) {
        int y = yg * 5 + yi;
        unsigned long long acc[20];
        #pragma unroll
        for (int xx = 0; xx < 20; xx++) acc[xx] = 0ull;

        for (int ky = 0; ky < 9; ky++) {
            const float* rowp = s_img + (y + ky) * 28;
            unsigned long long rp[28];
            #pragma unroll
            for (int q = 0; q < 7; q++) {
                float4 r4 = *(const float4*)(rowp + q * 4);
                rp[q * 4 + 0] = pack2(r4.x);
                rp[q * 4 + 1] = pack2(r4.y);
                rp[q * 4 + 2] = pack2(r4.z);
                rp[q * 4 + 3] = pack2(r4.w);
            }
            #pragma unroll
            for (int kx = 0; kx < 9; kx++) {
                unsigned long long wp =
                    *(const unsigned long long*)(s_w + (ky * 9 + kx) * CW + ocp * 2);
                #pragma unroll
                for (int xx = 0; xx < 20; xx++) ffma2(acc[xx], wp, rp[xx + kx]);
            }
        }
        #pragma unroll
        for (int xx = 0; xx < 20; xx++) {
            float v0, v1;
            unpack2(acc[xx], v0, v1);
            v0 = fmaxf(v0 + bv0, 0.f);
            v1 = fmaxf(v1 + bv1, 0.f);
            int idx32 = ((b * 20 + y) * 20 + xx) * 128 + ocg * 32 + ocp;
            ((__half2*)g_cl)[idx32] = __floats2half2_rn(v0, v1);
        }
    }
}

// ---------------------------------------------------------------------------
// weight relayout via smem transpose: pc_w [oc][ic][81] -> g_wr [oc][tap][ic]
// ---------------------------------------------------------------------------
__global__ __launch_bounds__(256) void wrelayout_kernel(const float* __restrict__ w)
{
    extern __shared__ char wsm[];
    __half* sh = (__half*)wsm;
    int oc = blockIdx.x;
    int tid = threadIdx.x;
    const float* src = w + (size_t)oc * 20736;

    for (int j = tid; j < 20736; j += 256) {
        int ic = j / 81;
        int e = j - ic * 81;
        sh[e * 256 + ic] = __float2half(src[j]);
    }
    __syncthreads();

    uint4* dh = (uint4*)(g_wr + (size_t)oc * 20736);
    const uint4* s4 = (const uint4*)sh;
    for (int j = tid; j < 2592; j += 256) dh[j] = s4[j];
}

// ---------------------------------------------------------------------------
// pcconv: fp16 implicit GEMM, cp.async 2-stage (R6 configuration),
// M=128 x N=256 per CTA. grid 144, block 256 (8 warps 4(M)x2(N)).
// ---------------------------------------------------------------------------
#define SM_A 0
#define SM_B 16384
#define STAGE 49152
#define PCG_SMEM (2 * STAGE)

__global__ __launch_bounds__(256, 1) void pcgemm_kernel(const float* __restrict__ bias)
{
    extern __shared__ char sm[];
    __shared__ int s_rowbase[128];

    int tid = threadIdx.x;
    int wid = tid >> 5;
    int lane = tid & 31;
    int warp_m = wid & 3;
    int warp_n = wid >> 2;
    int m0 = blockIdx.x * 128;
    uint32_t smb = smem_u32(sm);

    if (tid < 128) {
        int npos = m0 + tid;
        int b = npos / 36;
        int pos = npos - b * 36;
        int y = pos / 6;
        int xq = pos - y * 6;
        s_rowbase[tid] = ((b * 20 + 2 * y) * 20 + 2 * xq) * 256;
    }
    __syncthreads();

    int r0 = tid >> 3;   // 0..31
    int c = tid & 7;
    uint32_t dbase = (uint32_t)(r0 * 128) + (uint32_t)((c * 16) ^ ((r0 & 7) << 4));
    int rb[4];
    #pragma unroll
    for (int i = 0; i < 4; i++) rb[i] = s_rowbase[r0 + 32 * i];
    int bbase0 = r0 * 20736;

#define PCG_ISSUE(K) do { \
    int _kykx = (K) >> 2; \
    int _ic0 = ((K) & 3) << 6; \
    int _ky = _kykx / 9; \
    int _kx = _kykx - _ky * 9; \
    int _asrc = (_ky * 20 + _kx) * 256 + _ic0 + c * 8; \
    int _bsrc = _kykx * 256 + _ic0 + c * 8; \
    uint32_t _st = smb + ((K) & 1) * STAGE; \
    _Pragma("unroll") \
    for (int _i = 0; _i < 4; _i++) \
        CP16(_st + SM_A + dbase + _i * 4096, g_cl + rb[_i] + _asrc); \
    _Pragma("unroll") \
    for (int _t = 0; _t < 8; _t++) \
        CP16(_st + SM_B + dbase + _t * 4096, g_wr + bbase0 + _t * 663552 + _bsrc); \
} while (0)

    float acc[2][16][4];
    #pragma unroll
    for (int i = 0; i < 2; i++)
        #pragma unroll
        for (int j = 0; j < 16; j++)
            #pragma unroll
            for (int k = 0; k < 4; k++) acc[i][j][k] = 0.f;

    uint32_t swz = (uint32_t)(lane & 7) << 4;
    uint32_t a_row_off = SM_A + (uint32_t)(warp_m * 32 + (lane & 15)) * 128;
    uint32_t akb = (uint32_t)(lane >> 4) << 4;
    uint32_t b_row_off = SM_B +
        (uint32_t)(warp_n * 128 + (lane & 7) + ((lane >> 4) & 1) * 8) * 128;
    uint32_t bkb = (uint32_t)((lane >> 3) & 1) << 4;

    PCG_ISSUE(0);
    CP_COMMIT();

    for (int kc = 0; kc < 324; kc++) {
        if (kc < 323) {
            PCG_ISSUE(kc + 1);
            CP_COMMIT();
            CP_WAIT1();
        } else {
            CP_WAIT0();
        }
        __syncthreads();

        uint32_t st = smb + (kc & 1) * STAGE;
        uint32_t a_row = st + a_row_off;
        uint32_t b_row = st + b_row_off;
        #pragma unroll
        for (int j = 0; j < 4; j++) {
            uint32_t ka = ((uint32_t)(j * 32) + akb) ^ swz;
            uint32_t ah[8];
            ldsm_x4(ah[0], ah[1], ah[2], ah[3], a_row + ka);
            ldsm_x4(ah[4], ah[5], ah[6], ah[7], a_row + 2048 + ka);
            uint32_t kb = ((uint32_t)(j * 32) + bkb) ^ swz;
            #pragma unroll
            for (int h = 0; h < 2; h++) {
                uint32_t bh[16];
                #pragma unroll
                for (int q = 0; q < 4; q++) {
                    uint32_t bt = b_row + (uint32_t)((h * 4 + q) * 2048) + kb;
                    ldsm_x4(bh[4 * q], bh[4 * q + 1], bh[4 * q + 2], bh[4 * q + 3], bt);
                }
                #pragma unroll
                for (int q = 0; q < 4; q++) {
                    #pragma unroll
                    for (int sub = 0; sub < 2; sub++) {
                        int nn = h * 8 + q * 2 + sub;
                        #pragma unroll
                        for (int tm = 0; tm < 2; tm++)
                            mma16816h(acc[tm][nn], &ah[4 * tm], &bh[4 * q + 2 * sub]);
                    }
                }
            }
        }
        __syncthreads();
    }

    // epilogue
    int r_in8 = lane >> 2;
    int c_in8 = (lane & 3) * 2;
    #pragma unroll
    for (int tm = 0; tm < 2; tm++) {
        int row0 = m0 + warp_m * 32 + tm * 16 + r_in8;
        int b0i = row0 / 36, p0i = row0 - b0i * 36;
        int row1 = row0 + 8;
        int b1i = row1 / 36, p1i = row1 - b1i * 36;
        #pragma unroll
        for (int nn = 0; nn < 16; nn++) {
            int col = warp_n * 128 + nn * 8 + c_in8;
            float bv0 = __ldg(bias + col);
            float bv1 = __ldg(bias + col + 1);
            const float* cc2 = acc[tm][nn];
            g_pc[b0i * 9216 + col * 36 + p0i] = cc2[0] + bv0;
            g_pc[b0i * 9216 + (col + 1) * 36 + p0i] = cc2[1] + bv1;
            g_pc[b1i * 9216 + col * 36 + p1i] = cc2[2] + bv0;
            g_pc[b1i * 9216 + (col + 1) * 36 + p1i] = cc2[3] + bv1;
        }
    }
}

// ---------------------------------------------------------------------------
// squash over 1152 + transpose to hT (smem-staged, coalesced writes).
// ---------------------------------------------------------------------------
__global__ __launch_bounds__(256) void squash_h_kernel()
{
    int b = blockIdx.x;
    int tid = threadIdx.x;
    __shared__ float s_scale[8];
    __shared__ float s_val[9216];
    int g = tid >> 5;
    int lane = tid & 31;
    const float* pb = g_pc + (size_t)b * 9216;

    float ss = 0.f;
    for (int j = lane; j < 1152; j += 32) {
        float v = pb[g * 1152 + j];
        ss += v * v;
    }
    #pragma unroll
    for (int o = 16; o; o >>= 1) ss += __shfl_xor_sync(0xffffffffu, ss, o);
    if (lane == 0) s_scale[g] = sqrtf(ss) / (1.f + ss);
    __syncthreads();

    for (int idx = tid; idx < 9216; idx += 256) {
        int cch = idx / 36;
        s_val[idx] = pb[idx] * s_scale[cch >> 5];
    }
    __syncthreads();

    float* outb = g_hT + (size_t)b * 9216;
    for (int o = tid; o < 9216; o += 256) {
        int pos = o >> 3;
        int g2 = o & 7;
        int cch = g2 * 32 + pos / 36;
        int s = pos % 36;
        outb[o] = s_val[cch * 36 + s];
    }
}

// ---------------------------------------------------------------------------
// u_hat (fp16 out): grid 1152, block 256.
// ---------------------------------------------------------------------------
__global__ __launch_bounds__(256) void uhat_kernel(const float* __restrict__ W)
{
    int i = blockIdx.x;
    __shared__ float sW[1280];
    __shared__ float sh[32 * 8];
    int tid = threadIdx.x;
    for (int j = tid; j < 1280; j += 256)
        sW[(j & 7) * 160 + (j >> 3)] = W[(size_t)i * 1280 + j];

    for (int b0 = 0; b0 < BATCH; b0 += 32) {
        __syncthreads();
        sh[tid] = g_hT[((size_t)(b0 + (tid >> 3)) * 1152 + i) * 8 + (tid & 7)];
        __syncthreads();
        if (tid < 160) {
            #pragma unroll 4
            for (int bb = 0; bb < 32; bb++) {
                float u = 0.f;
                #pragma unroll
                for (int e = 0; e < 8; e++) u += sW[e * 160 + tid] * sh[bb * 8 + e];
                g_uhat[((size_t)(b0 + bb) * 1152 + i) * 160 + tid] = __float2half(u);
            }
        }
    }
}

// ---------------------------------------------------------------------------
// routing iter 0: s = 0.1*sum_i u (warp-split), v = squash; vsum = v.
// ---------------------------------------------------------------------------
__global__ __launch_bounds__(256) void routing0_kernel()
{
    int b = blockIdx.x;
    int t = threadIdx.x;
    int w = t >> 5;
    int l = t & 31;
    __shared__ float spart[8][160];
    __shared__ float s_s[160];

    const __half* ub = g_uhat + (size_t)b * 184320;
    float acc[5] = {0.f, 0.f, 0.f, 0.f, 0.f};
    int i0 = w * 144;
    for (int i = i0; i < i0 + 144; i++) {
        #pragma unroll
        for (int q = 0; q < 5; q++)
            acc[q] += __half2float(__ldg(ub + i * 160 + l + 32 * q));
    }
    #pragma unroll
    for (int q = 0; q < 5; q++) spart[w][l + 32 * q] = acc[q];
    __syncthreads();

    if (t < 160) {
        float s = 0.f;
        #pragma unroll
        for (int w2 = 0; w2 < 8; w2++) s += spart[w2][t];
        s_s[t] = 0.1f * s;
    }
    __syncthreads();
    if (t < 160) {
        int k = t >> 4;
        float n2 = 0.f;
        #pragma unroll
        for (int d = 0; d < 16; d++) {
            float v = s_s[k * 16 + d];
            n2 += v * v;
        }
        float v = s_s[t] * (sqrtf(n2) / (1.f + n2));
        g_v[b * 160 + t] = v;
        g_vsum[b * 160 + t] = v;
    }
}

// ---------------------------------------------------------------------------
// routing iter (r=1,2): logits = u.vsum; c = softmax_k; s = sum_i c*u
// (warp-split phase B); v = squash; vsum += v.
// ---------------------------------------------------------------------------
__global__ __launch_bounds__(256) void routing_iter_kernel()
{
    extern __shared__ float rsm[];
    float* c_s = rsm;              // 11520
    float* v_s = rsm + 11520;      // 160 (holds vsum)
    float* spart = rsm + 11680;    // 8*160
    float* s_s = rsm + 12960;      // 160

    int b = blockIdx.x;
    int t = threadIdx.x;
    int w = t >> 5;
    int l = t & 31;

    if (t < 160) v_s[t] = g_vsum[b * 160 + t];
    __syncthreads();

    const __half* ub = g_uhat + (size_t)b * 184320;

    // Phase A: per-row logits u.vsum + softmax -> c_s
    for (int i = t; i < 1152; i += 256) {
        const __half2* u2 = (const __half2*)(ub + i * 160);
        float bl[10];
        float mx = -1e30f;
        #pragma unroll
        for (int k = 0; k < 10; k++) {
            float dk = 0.f;
            #pragma unroll
            for (int j = 0; j < 8; j++) {
                float2 u = __half22float2(u2[k * 8 + j]);
                dk += u.x * v_s[k * 16 + 2 * j + 0];
                dk += u.y * v_s[k * 16 + 2 * j + 1];
            }
            bl[k] = dk;
            mx = fmaxf(mx, dk);
        }
        float sum = 0.f;
        #pragma unroll
        for (int k = 0; k < 10; k++) {
            float e = __expf(bl[k] - mx);
            bl[k] = e;
            sum += e;
        }
        float inv = 1.f / sum;
        #pragma unroll
        for (int k = 0; k < 10; k++) c_s[i * 10 + k] = bl[k] * inv;
    }
    __syncthreads();

    // Phase B: warp-split s accumulation.
    {
        float acc[5] = {0.f, 0.f, 0.f, 0.f, 0.f};
        int hb = l >> 4;
        int i0 = w * 144;
        for (int i = i0; i < i0 + 144; i++) {
            #pragma unroll
            for (int q = 0; q < 5; q++) {
                float u = __half2float(__ldg(ub + i * 160 + l + 32 * q));
                acc[q] += c_s[i * 10 + 2 * q + hb] * u;
            }
        }
        #pragma unroll
        for (int q = 0; q < 5; q++) spart[w * 160 + l + 32 * q] = acc[q];
    }
    __syncthreads();

    if (t < 160) {
        float s = 0.f;
        #pragma unroll
        for (int w2 = 0; w2 < 8; w2++) s += spart[w2 * 160 + t];
        s_s[t] = s;
    }
    __syncthreads();
    if (t < 160) {
        int k = t >> 4;
        float n2 = 0.f;
        #pragma unroll
        for (int d = 0; d < 16; d++) {
            float v = s_s[k * 16 + d];
            n2 += v * v;
        }
        float v = s_s[t] * (sqrtf(n2) / (1.f + n2));
        g_v[b * 160 + t] = v;
        g_vsum[b * 160 + t] = v_s[t] + v;
    }
}

// ---------------------------------------------------------------------------
__global__ void mask_kernel(const float* __restrict__ labels)
{
    int idx = blockIdx.x * 256 + threadIdx.x;
    if (idx < BATCH * 160) {
        int b = idx / 160;
        int k = (idx - b * 160) >> 4;
        g_m[idx] = g_v[idx] * labels[b * 10 + k];
    }
}

// ---------------------------------------------------------------------------
template <int ACT, int SEL>
__global__ __launch_bounds__(256) void gemm_kernel(
    const float* __restrict__ Wt, const float* __restrict__ bias,
    float* __restrict__ outp, int M, int N, int K)
{
    const float* A = (SEL == 0) ? g_m : (SEL == 1) ? g_fc1 : g_fc2;
    float* C = (SEL == 0) ? g_fc1 : (SEL == 1) ? g_fc2 : outp;

    __shared__ float As[8][64];
    __shared__ float Bs[8][64];
    int n0 = blockIdx.x * 64;
    int m0 = blockIdx.y * 64;
    int tid = threadIdx.x;
    int tx = tid & 15;
    int ty = tid >> 4;

    float acc[4][4];
    #pragma unroll
    for (int i = 0; i < 4; i++)
        #pragma unroll
        for (int j = 0; j < 4; j++) acc[i][j] = 0.f;

    for (int k0 = 0; k0 < K; k0 += 8) {
        __syncthreads();
        #pragma unroll
        for (int l = 0; l < 2; l++) {
            int e = tid + l * 256;
            int r = e >> 3;
            int kk = e & 7;
            As[kk][r] = A[(m0 + r) * K + k0 + kk];
            int n = n0 + r;
            Bs[kk][r] = (n < N) ? Wt[n * K + k0 + kk] : 0.f;
        }
        __syncthreads();
        #pragma unroll
        for (int kk = 0; kk < 8; kk++) {
            float4 a4 = *(const float4*)&As[kk][ty * 4];
            float4 b4 = *(const float4*)&Bs[kk][tx * 4];
            float a[4] = {a4.x, a4.y, a4.z, a4.w};
            float bb[4] = {b4.x, b4.y, b4.z, b4.w};
            #pragma unroll
            for (int i = 0; i < 4; i++)
                #pragma unroll
                for (int j = 0; j < 4; j++) acc[i][j] += a[i] * bb[j];
        }
    }

    #pragma unroll
    for (int i = 0; i < 4; i++) {
        int m = m0 + ty * 4 + i;
        #pragma unroll
        for (int j = 0; j < 4; j++) {
            int n = n0 + tx * 4 + j;
            if (n < N) {
                float v = acc[i][j] + bias[n];
                if (ACT == 0) v = fmaxf(v, 0.f);
                else v = 1.f / (1.f + __expf(-v));
                C[m * N + n] = v;
            }
        }
    }
}

// ---------------------------------------------------------------------------
__global__ void probs_kernel(float* __restrict__ out)
{
    int b = blockIdx.x * 128 + threadIdx.x;
    if (b < BATCH) {
        float nr[10];
        float mx = -1e30f;
        #pragma unroll
        for (int k = 0; k < 10; k++) {
            float n2 = 0.f;
            #pragma unroll
            for (int d = 0; d < 16; d++) {
                float v = g_v[b * 160 + k * 16 + d];
                n2 += v * v;
            }
            nr[k] = sqrtf(n2);
            mx = fmaxf(mx, nr[k]);
        }
        float sum = 0.f;
        #pragma unroll
        for (int k = 0; k < 10; k++) {
            nr[k] = __expf(nr[k] - mx);
            sum += nr[k];
        }
        float inv = 1.f / sum;
        #pragma unroll
        for (int k = 0; k < 10; k++) out[b * 10 + k] = nr[k] * inv;
    }
}

// ---------------------------------------------------------------------------
extern "C" void kernel_launch(void* const* d_in, const int* in_sizes, int n_in,
                              void* d_out, int out_size)
{
    const float* x       = (const float*)d_in[0];
    const float* labels  = (const float*)d_in[1];
    const float* conv1_w = (const float*)d_in[2];
    const float* conv1_b = (const float*)d_in[3];
    const float* pc_w    = (const float*)d_in[4];
    const float* pc_b    = (const float*)d_in[5];
    const float* W       = (const float*)d_in[6];
    const float* fc1_w   = (const float*)d_in[7];
    const float* fc1_b   = (const float*)d_in[8];
    const float* fc2_w   = (const float*)d_in[9];
    const float* fc2_b   = (const float*)d_in[10];
    const float* fc3_w   = (const float*)d_in[11];
    const float* fc3_b   = (const float*)d_in[12];
    float* out = (float*)d_out;

    cudaFuncSetAttribute(pcgemm_kernel,
                         cudaFuncAttributeMaxDynamicSharedMemorySize, PCG_SMEM);
    cudaFuncSetAttribute(wrelayout_kernel,
                         cudaFuncAttributeMaxDynamicSharedMemorySize, 43008);
    cudaFuncSetAttribute(routing_iter_kernel,
                         cudaFuncAttributeMaxDynamicSharedMemorySize, 53248);

    conv1_kernel<<<dim3(BATCH, 4), 128>>>(x, conv1_w, conv1_b);
    wrelayout_kernel<<<256, 256, 43008>>>(pc_w);
    pcgemm_kernel<<<144, 256, PCG_SMEM>>>(pc_b);
    squash_h_kernel<<<BATCH, 256>>>();
    uhat_kernel<<<1152, 256>>>(W);
    routing0_kernel<<<BATCH, 256>>>();
    routing_iter_kernel<<<BATCH, 256, 53248>>>();
    routing_iter_kernel<<<BATCH, 256, 53248>>>();
    mask_kernel<<<320, 256>>>(labels);
    gemm_kernel<0, 0><<<dim3(8, 8), 256>>>(fc1_w, fc1_b, out, 512, 512, 160);
    gemm_kernel<0, 1><<<dim3(16, 8), 256>>>(fc2_w, fc2_b, out, 512, 1024, 512);
    gemm_kernel<1, 2><<<dim3(13, 8), 256>>>(fc3_w, fc3_b, out + 5120, 512, 784, 1024);
    probs_kernel<<<4, 128>>>(out);
}

// round 10
// speedup vs baseline: 1.1658x; 1.1559x over previous
#include <cuda_runtime.h>
#include <cuda_bf16.h>
#include <cuda_fp16.h>
#include <cstdint>
#include <math.h>

// ---------------------------------------------------------------------------
// CapsNet forward. B=512.
//   conv1:  [512,1,28,28] -> relu -> channel-last fp16 [b,iy,ix,ic]
//   pcconv: fp16 mma.sync implicit GEMM (cp.async 2-stage, M=64 N=256 /CTA,
//           2 CTAs/SM for cross-CTA latency hiding)
//   squash over 1152 -> hT; u_hat (fp16); routing x3 (R6 b-logit version);
//   decoder FCs; probs
// Output: [probs (512*10)] then [dec (512*784)]
// ---------------------------------------------------------------------------

#define BATCH 512

__device__ __half g_cl[BATCH * 400 * 256];        // conv1 out, channel-last fp16
__device__ __half g_wr[256 * 81 * 256];           // pc weights [oc][tap][ic] fp16
__device__ float g_pc[BATCH * 256 * 36];
__device__ float g_hT[BATCH * 1152 * 8];
__device__ __half g_uhat[BATCH * 1152 * 160];     // fp16 storage
__device__ float g_blog[BATCH * 1152 * 10];
__device__ float g_v[BATCH * 160];
__device__ float g_m[BATCH * 160];
__device__ float g_fc1[BATCH * 512];
__device__ float g_fc2[BATCH * 1024];

// ---------------- helpers ---------------------------------------------------
__device__ __forceinline__ uint32_t smem_u32(const void* p) {
    uint32_t a;
    asm("{ .reg .u64 t; cvta.to.shared.u64 t, %1; cvt.u32.u64 %0, t; }"
        : "=r"(a) : "l"(p));
    return a;
}
__device__ __forceinline__ void ldsm_x4(uint32_t& d0, uint32_t& d1,
                                        uint32_t& d2, uint32_t& d3,
                                        uint32_t addr) {
    asm volatile("ldmatrix.sync.aligned.m8n8.x4.shared.b16 {%0,%1,%2,%3}, [%4];"
                 : "=r"(d0), "=r"(d1), "=r"(d2), "=r"(d3) : "r"(addr));
}
__device__ __forceinline__ void mma16816h(float* c, const uint32_t* a,
                                          const uint32_t* b) {
    asm volatile(
        "mma.sync.aligned.m16n8k16.row.col.f32.f16.f16.f32 "
        "{%0,%1,%2,%3}, {%4,%5,%6,%7}, {%8,%9}, {%0,%1,%2,%3};"
        : "+f"(c[0]), "+f"(c[1]), "+f"(c[2]), "+f"(c[3])
        : "r"(a[0]), "r"(a[1]), "r"(a[2]), "r"(a[3]), "r"(b[0]), "r"(b[1]));
}
#define CP16(dst, src) \
    asm volatile("cp.async.cg.shared.global [%0], [%1], 16;" \
                 :: "r"(dst), "l"(src) : "memory")
#define CP_COMMIT() asm volatile("cp.async.commit_group;" ::: "memory")
#define CP_WAIT1() asm volatile("cp.async.wait_group 1;" ::: "memory")
#define CP_WAIT0() asm volatile("cp.async.wait_group 0;" ::: "memory")

// fp32x2 helpers for conv1
__device__ __forceinline__ void ffma2(unsigned long long& d,
                                      unsigned long long a,
                                      unsigned long long b) {
    asm("fma.rn.f32x2 %0, %1, %2, %0;" : "+l"(d) : "l"(a), "l"(b));
}
__device__ __forceinline__ unsigned long long pack2(float v) {
    unsigned long long r;
    asm("mov.b64 %0, {%1, %2};" : "=l"(r) : "f"(v), "f"(v));
    return r;
}
__device__ __forceinline__ void unpack2(unsigned long long p, float& lo, float& hi) {
    asm("mov.b64 {%0, %1}, %2;" : "=f"(lo), "=f"(hi) : "l"(p));
}

#define CW 68

// ---------------------------------------------------------------------------
// conv1: 1->256, 9x9, valid, relu -> channel-last fp16. grid (512,4), blk 128.
// ---------------------------------------------------------------------------
__global__ __launch_bounds__(128, 4) void conv1_kernel(
    const float* __restrict__ x, const float* __restrict__ w,
    const float* __restrict__ bias)
{
    int b = blockIdx.x;
    int ocg = blockIdx.y;
    __shared__ float s_img[784];
    __shared__ float s_w[81 * CW];
    int tid = threadIdx.x;

    for (int i = tid; i < 196; i += 128)
        *(float4*)&s_img[i * 4] = *(const float4*)&x[b * 784 + i * 4];
    for (int i = tid; i < 64 * 81; i += 128) {
        int r = i / 81;
        int e = i - r * 81;
        s_w[e * CW + r] = w[(ocg * 64 + r) * 81 + e];
    }
    __syncthreads();

    int ocp = tid & 31;
    int yg = tid >> 5;
    int oc0 = ocg * 64 + ocp * 2;
    float bv0 = bias[oc0], bv1 = bias[oc0 + 1];

    for (int yi = 0; yi < 5; yi++) {
        int y = yg * 5 + yi;
        unsigned long long acc[20];
        #pragma unroll
        for (int xx = 0; xx < 20; xx++) acc[xx] = 0ull;

        for (int ky = 0; ky < 9; ky++) {
            const float* rowp = s_img + (y + ky) * 28;
            unsigned long long rp[28];
            #pragma unroll
            for (int q = 0; q < 7; q++) {
                float4 r4 = *(const float4*)(rowp + q * 4);
                rp[q * 4 + 0] = pack2(r4.x);
                rp[q * 4 + 1] = pack2(r4.y);
                rp[q * 4 + 2] = pack2(r4.z);
                rp[q * 4 + 3] = pack2(r4.w);
            }
            #pragma unroll
            for (int kx = 0; kx < 9; kx++) {
                unsigned long long wp =
                    *(const unsigned long long*)(s_w + (ky * 9 + kx) * CW + ocp * 2);
                #pragma unroll
                for (int xx = 0; xx < 20; xx++) ffma2(acc[xx], wp, rp[xx + kx]);
            }
        }
        #pragma unroll
        for (int xx = 0; xx < 20; xx++) {
            float v0, v1;
            unpack2(acc[xx], v0, v1);
            v0 = fmaxf(v0 + bv0, 0.f);
            v1 = fmaxf(v1 + bv1, 0.f);
            int idx32 = ((b * 20 + y) * 20 + xx) * 128 + ocg * 32 + ocp;
            ((__half2*)g_cl)[idx32] = __floats2half2_rn(v0, v1);
        }
    }
}

// ---------------------------------------------------------------------------
// weight relayout via smem transpose: pc_w [oc][ic][81] -> g_wr [oc][tap][ic]
// ---------------------------------------------------------------------------
__global__ __launch_bounds__(256) void wrelayout_kernel(const float* __restrict__ w)
{
    extern __shared__ char wsm[];
    __half* sh = (__half*)wsm;
    int oc = blockIdx.x;
    int tid = threadIdx.x;
    const float* src = w + (size_t)oc * 20736;

    for (int j = tid; j < 20736; j += 256) {
        int ic = j / 81;
        int e = j - ic * 81;
        sh[e * 256 + ic] = __float2half(src[j]);
    }
    __syncthreads();

    uint4* dh = (uint4*)(g_wr + (size_t)oc * 20736);
    const uint4* s4 = (const uint4*)sh;
    for (int j = tid; j < 2592; j += 256) dh[j] = s4[j];
}

// ---------------------------------------------------------------------------
// pcconv: fp16 implicit GEMM, cp.async 2-stage, M=64 x N=256 per CTA.
// grid 288, block 256 (8 warps: 2(M) x 4(N), warp tile 32x64). 2 CTAs/SM.
// ---------------------------------------------------------------------------
#define SM_A 0
#define SM_B 8192
#define STAGE 40960
#define PCG_SMEM (2 * STAGE)

__global__ __launch_bounds__(256, 2) void pcgemm_kernel(const float* __restrict__ bias)
{
    extern __shared__ char sm[];
    __shared__ int s_rowbase[64];

    int tid = threadIdx.x;
    int wid = tid >> 5;
    int lane = tid & 31;
    int warp_m = wid & 1;
    int warp_n = wid >> 1;
    int m0 = blockIdx.x * 64;
    uint32_t smb = smem_u32(sm);

    if (tid < 64) {
        int npos = m0 + tid;
        int b = npos / 36;
        int pos = npos - b * 36;
        int y = pos / 6;
        int xq = pos - y * 6;
        s_rowbase[tid] = ((b * 20 + 2 * y) * 20 + 2 * xq) * 256;
    }
    __syncthreads();

    int r0 = tid >> 3;   // 0..31
    int c = tid & 7;
    uint32_t dbase = (uint32_t)(r0 * 128) + (uint32_t)((c * 16) ^ ((r0 & 7) << 4));
    int rb0 = s_rowbase[r0];
    int rb1 = s_rowbase[r0 + 32];
    int bbase0 = r0 * 20736;

#define PCG_ISSUE(K) do { \
    int _kykx = (K) >> 2; \
    int _ic0 = ((K) & 3) << 6; \
    int _ky = _kykx / 9; \
    int _kx = _kykx - _ky * 9; \
    int _asrc = (_ky * 20 + _kx) * 256 + _ic0 + c * 8; \
    int _bsrc = _kykx * 256 + _ic0 + c * 8; \
    uint32_t _st = smb + ((K) & 1) * STAGE; \
    CP16(_st + SM_A + dbase, g_cl + rb0 + _asrc); \
    CP16(_st + SM_A + dbase + 4096, g_cl + rb1 + _asrc); \
    _Pragma("unroll") \
    for (int _t = 0; _t < 8; _t++) \
        CP16(_st + SM_B + dbase + _t * 4096, g_wr + bbase0 + _t * 663552 + _bsrc); \
} while (0)

    float acc[2][8][4];
    #pragma unroll
    for (int i = 0; i < 2; i++)
        #pragma unroll
        for (int j = 0; j < 8; j++)
            #pragma unroll
            for (int k = 0; k < 4; k++) acc[i][j][k] = 0.f;

    uint32_t swz = (uint32_t)(lane & 7) << 4;
    uint32_t a_row_off = SM_A + (uint32_t)(warp_m * 32 + (lane & 15)) * 128;
    uint32_t akb = (uint32_t)(lane >> 4) << 4;
    uint32_t b_row_off = SM_B +
        (uint32_t)(warp_n * 64 + (lane & 7) + ((lane >> 4) & 1) * 8) * 128;
    uint32_t bkb = (uint32_t)((lane >> 3) & 1) << 4;

    PCG_ISSUE(0);
    CP_COMMIT();

    for (int kc = 0; kc < 324; kc++) {
        if (kc < 323) {
            PCG_ISSUE(kc + 1);
            CP_COMMIT();
            CP_WAIT1();
        } else {
            CP_WAIT0();
        }
        __syncthreads();

        uint32_t st = smb + (kc & 1) * STAGE;
        uint32_t a_row = st + a_row_off;
        uint32_t b_row = st + b_row_off;
        #pragma unroll
        for (int j = 0; j < 4; j++) {
            uint32_t ka = ((uint32_t)(j * 32) + akb) ^ swz;
            uint32_t ah[8];
            ldsm_x4(ah[0], ah[1], ah[2], ah[3], a_row + ka);
            ldsm_x4(ah[4], ah[5], ah[6], ah[7], a_row + 2048 + ka);
            uint32_t kb = ((uint32_t)(j * 32) + bkb) ^ swz;
            uint32_t bh[16];
            #pragma unroll
            for (int q = 0; q < 4; q++) {
                uint32_t bt = b_row + (uint32_t)(q * 2048) + kb;
                ldsm_x4(bh[4 * q], bh[4 * q + 1], bh[4 * q + 2], bh[4 * q + 3], bt);
            }
            #pragma unroll
            for (int q = 0; q < 4; q++) {
                #pragma unroll
                for (int sub = 0; sub < 2; sub++) {
                    int nn = q * 2 + sub;
                    #pragma unroll
                    for (int tm = 0; tm < 2; tm++)
                        mma16816h(acc[tm][nn], &ah[4 * tm], &bh[4 * q + 2 * sub]);
                }
            }
        }
        __syncthreads();
    }

    // epilogue
    int r_in8 = lane >> 2;
    int c_in8 = (lane & 3) * 2;
    #pragma unroll
    for (int tm = 0; tm < 2; tm++) {
        int row0 = m0 + warp_m * 32 + tm * 16 + r_in8;
        int b0i = row0 / 36, p0i = row0 - b0i * 36;
        int row1 = row0 + 8;
        int b1i = row1 / 36, p1i = row1 - b1i * 36;
        #pragma unroll
        for (int nn = 0; nn < 8; nn++) {
            int col = warp_n * 64 + nn * 8 + c_in8;
            float bv0 = __ldg(bias + col);
            float bv1 = __ldg(bias + col + 1);
            const float* cc2 = acc[tm][nn];
            g_pc[b0i * 9216 + col * 36 + p0i] = cc2[0] + bv0;
            g_pc[b0i * 9216 + (col + 1) * 36 + p0i] = cc2[1] + bv1;
            g_pc[b1i * 9216 + col * 36 + p1i] = cc2[2] + bv0;
            g_pc[b1i * 9216 + (col + 1) * 36 + p1i] = cc2[3] + bv1;
        }
    }
}

// ---------------------------------------------------------------------------
// squash over 1152 + transpose to hT (smem-staged, coalesced writes).
// ---------------------------------------------------------------------------
__global__ __launch_bounds__(256) void squash_h_kernel()
{
    int b = blockIdx.x;
    int tid = threadIdx.x;
    __shared__ float s_scale[8];
    __shared__ float s_val[9216];
    int g = tid >> 5;
    int lane = tid & 31;
    const float* pb = g_pc + (size_t)b * 9216;

    float ss = 0.f;
    for (int j = lane; j < 1152; j += 32) {
        float v = pb[g * 1152 + j];
        ss += v * v;
    }
    #pragma unroll
    for (int o = 16; o; o >>= 1) ss += __shfl_xor_sync(0xffffffffu, ss, o);
    if (lane == 0) s_scale[g] = sqrtf(ss) / (1.f + ss);
    __syncthreads();

    for (int idx = tid; idx < 9216; idx += 256) {
        int cch = idx / 36;
        s_val[idx] = pb[idx] * s_scale[cch >> 5];
    }
    __syncthreads();

    float* outb = g_hT + (size_t)b * 9216;
    for (int o = tid; o < 9216; o += 256) {
        int pos = o >> 3;
        int g2 = o & 7;
        int cch = g2 * 32 + pos / 36;
        int s = pos % 36;
        outb[o] = s_val[cch * 36 + s];
    }
}

// ---------------------------------------------------------------------------
// u_hat (fp16 out): grid 1152, block 256.
// ---------------------------------------------------------------------------
__global__ __launch_bounds__(256) void uhat_kernel(const float* __restrict__ W)
{
    int i = blockIdx.x;
    __shared__ float sW[1280];
    __shared__ float sh[32 * 8];
    int tid = threadIdx.x;
    for (int j = tid; j < 1280; j += 256)
        sW[(j & 7) * 160 + (j >> 3)] = W[(size_t)i * 1280 + j];

    for (int b0 = 0; b0 < BATCH; b0 += 32) {
        __syncthreads();
        sh[tid] = g_hT[((size_t)(b0 + (tid >> 3)) * 1152 + i) * 8 + (tid & 7)];
        __syncthreads();
        if (tid < 160) {
            #pragma unroll 4
            for (int bb = 0; bb < 32; bb++) {
                float u = 0.f;
                #pragma unroll
                for (int e = 0; e < 8; e++) u += sW[e * 160 + tid] * sh[bb * 8 + e];
                g_uhat[((size_t)(b0 + bb) * 1152 + i) * 160 + tid] = __float2half(u);
            }
        }
    }
}

// ---------------------------------------------------------------------------
// routing iter 0 (R6 version): c = 1/10 -> s = 0.1*sum_i u; v = squash;
// zero b-logits. grid 512, block 160.
// ---------------------------------------------------------------------------
__global__ __launch_bounds__(160) void routing0_kernel()
{
    int b = blockIdx.x;
    int t = threadIdx.x;
    for (int j = t; j < 11520; j += 160) g_blog[(size_t)b * 11520 + j] = 0.f;

    const __half* ub = g_uhat + (size_t)b * 184320;
    float s0 = 0.f, s1 = 0.f, s2 = 0.f, s3 = 0.f;
    for (int i = 0; i < 1152; i += 4) {
        s0 += __half2float(ub[(i + 0) * 160 + t]);
        s1 += __half2float(ub[(i + 1) * 160 + t]);
        s2 += __half2float(ub[(i + 2) * 160 + t]);
        s3 += __half2float(ub[(i + 3) * 160 + t]);
    }
    float s = 0.1f * (s0 + s1 + s2 + s3);

    __shared__ float s_s[160];
    s_s[t] = s;
    __syncthreads();
    int k = t >> 4;
    float n2 = 0.f;
    #pragma unroll
    for (int d = 0; d < 16; d++) {
        float v = s_s[k * 16 + d];
        n2 += v * v;
    }
    g_v[b * 160 + t] = s * (sqrtf(n2) / (1.f + n2));
}

// ---------------------------------------------------------------------------
// routing iter (r=1,2) (R6 version): b += u.v_prev; c = softmax_k;
// s = sum_i c*u; v = squash. grid 512, block 256.
// ---------------------------------------------------------------------------
__global__ __launch_bounds__(256) void routing_iter_kernel()
{
    int b = blockIdx.x;
    int t = threadIdx.x;
    __shared__ float v_s[160];
    __shared__ float c_s[1152 * 10];
    __shared__ float s_s[160];

    if (t < 160) v_s[t] = g_v[b * 160 + t];
    __syncthreads();

    const __half* ub = g_uhat + (size_t)b * 184320;
    float* blb = g_blog + (size_t)b * 11520;

    for (int i = t; i < 1152; i += 256) {
        const __half2* u2 = (const __half2*)(ub + i * 160);
        float bl[10];
        float mx = -1e30f;
        #pragma unroll
        for (int k = 0; k < 10; k++) {
            float dk = 0.f;
            #pragma unroll
            for (int j = 0; j < 8; j++) {
                float2 u = __half22float2(u2[k * 8 + j]);
                dk += u.x * v_s[k * 16 + 2 * j + 0];
                dk += u.y * v_s[k * 16 + 2 * j + 1];
            }
            float nb = blb[i * 10 + k] + dk;
            blb[i * 10 + k] = nb;
            bl[k] = nb;
            mx = fmaxf(mx, nb);
        }
        float sum = 0.f;
        #pragma unroll
        for (int k = 0; k < 10; k++) {
            float e = __expf(bl[k] - mx);
            bl[k] = e;
            sum += e;
        }
        float inv = 1.f / sum;
        #pragma unroll
        for (int k = 0; k < 10; k++) c_s[i * 10 + k] = bl[k] * inv;
    }
    __syncthreads();

    float s = 0.f;
    if (t < 160) {
        int k = t >> 4;
        float p0 = 0.f, p1 = 0.f;
        #pragma unroll 4
        for (int i = 0; i < 1152; i += 2) {
            p0 += c_s[(i + 0) * 10 + k] * __half2float(__ldg(ub + (i + 0) * 160 + t));
            p1 += c_s[(i + 1) * 10 + k] * __half2float(__ldg(ub + (i + 1) * 160 + t));
        }
        s = p0 + p1;
    }
    __syncthreads();
    if (t < 160) s_s[t] = s;
    __syncthreads();
    if (t < 160) {
        int k = t >> 4;
        float n2 = 0.f;
        #pragma unroll
        for (int d = 0; d < 16; d++) {
            float v = s_s[k * 16 + d];
            n2 += v * v;
        }
        g_v[b * 160 + t] = s * (sqrtf(n2) / (1.f + n2));
    }
}

// ---------------------------------------------------------------------------
__global__ void mask_kernel(const float* __restrict__ labels)
{
    int idx = blockIdx.x * 256 + threadIdx.x;
    if (idx < BATCH * 160) {
        int b = idx / 160;
        int k = (idx - b * 160) >> 4;
        g_m[idx] = g_v[idx] * labels[b * 10 + k];
    }
}

// ---------------------------------------------------------------------------
template <int ACT, int SEL>
__global__ __launch_bounds__(256) void gemm_kernel(
    const float* __restrict__ Wt, const float* __restrict__ bias,
    float* __restrict__ outp, int M, int N, int K)
{
    const float* A = (SEL == 0) ? g_m : (SEL == 1) ? g_fc1 : g_fc2;
    float* C = (SEL == 0) ? g_fc1 : (SEL == 1) ? g_fc2 : outp;

    __shared__ float As[8][64];
    __shared__ float Bs[8][64];
    int n0 = blockIdx.x * 64;
    int m0 = blockIdx.y * 64;
    int tid = threadIdx.x;
    int tx = tid & 15;
    int ty = tid >> 4;

    float acc[4][4];
    #pragma unroll
    for (int i = 0; i < 4; i++)
        #pragma unroll
        for (int j = 0; j < 4; j++) acc[i][j] = 0.f;

    for (int k0 = 0; k0 < K; k0 += 8) {
        __syncthreads();
        #pragma unroll
        for (int l = 0; l < 2; l++) {
            int e = tid + l * 256;
            int r = e >> 3;
            int kk = e & 7;
            As[kk][r] = A[(m0 + r) * K + k0 + kk];
            int n = n0 + r;
            Bs[kk][r] = (n < N) ? Wt[n * K + k0 + kk] : 0.f;
        }
        __syncthreads();
        #pragma unroll
        for (int kk = 0; kk < 8; kk++) {
            float4 a4 = *(const float4*)&As[kk][ty * 4];
            float4 b4 = *(const float4*)&Bs[kk][tx * 4];
            float a[4] = {a4.x, a4.y, a4.z, a4.w};
            float bb[4] = {b4.x, b4.y, b4.z, b4.w};
            #pragma unroll
            for (int i = 0; i < 4; i++)
                #pragma unroll
                for (int j = 0; j < 4; j++) acc[i][j] += a[i] * bb[j];
        }
    }

    #pragma unroll
    for (int i = 0; i < 4; i++) {
        int m = m0 + ty * 4 + i;
        #pragma unroll
        for (int j = 0; j < 4; j++) {
            int n = n0 + tx * 4 + j;
            if (n < N) {
                float v = acc[i][j] + bias[n];
                if (ACT == 0) v = fmaxf(v, 0.f);
                else v = 1.f / (1.f + __expf(-v));
                C[m * N + n] = v;
            }
        }
    }
}

// ---------------------------------------------------------------------------
__global__ void probs_kernel(float* __restrict__ out)
{
    int b = blockIdx.x * 128 + threadIdx.x;
    if (b < BATCH) {
        float nr[10];
        float mx = -1e30f;
        #pragma unroll
        for (int k = 0; k < 10; k++) {
            float n2 = 0.f;
            #pragma unroll
            for (int d = 0; d < 16; d++) {
                float v = g_v[b * 160 + k * 16 + d];
                n2 += v * v;
            }
            nr[k] = sqrtf(n2);
            mx = fmaxf(mx, nr[k]);
        }
        float sum = 0.f;
        #pragma unroll
        for (int k = 0; k < 10; k++) {
            nr[k] = __expf(nr[k] - mx);
            sum += nr[k];
        }
        float inv = 1.f / sum;
        #pragma unroll
        for (int k = 0; k < 10; k++) out[b * 10 + k] = nr[k] * inv;
    }
}

// ---------------------------------------------------------------------------
extern "C" void kernel_launch(void* const* d_in, const int* in_sizes, int n_in,
                              void* d_out, int out_size)
{
    const float* x       = (const float*)d_in[0];
    const float* labels  = (const float*)d_in[1];
    const float* conv1_w = (const float*)d_in[2];
    const float* conv1_b = (const float*)d_in[3];
    const float* pc_w    = (const float*)d_in[4];
    const float* pc_b    = (const float*)d_in[5];
    const float* W       = (const float*)d_in[6];
    const float* fc1_w   = (const float*)d_in[7];
    const float* fc1_b   = (const float*)d_in[8];
    const float* fc2_w   = (const float*)d_in[9];
    const float* fc2_b   = (const float*)d_in[10];
    const float* fc3_w   = (const float*)d_in[11];
    const float* fc3_b   = (const float*)d_in[12];
    float* out = (float*)d_out;

    cudaFuncSetAttribute(pcgemm_kernel,
                         cudaFuncAttributeMaxDynamicSharedMemorySize, PCG_SMEM);
    cudaFuncSetAttribute(wrelayout_kernel,
                         cudaFuncAttributeMaxDynamicSharedMemorySize, 43008);

    conv1_kernel<<<dim3(BATCH, 4), 128>>>(x, conv1_w, conv1_b);
    wrelayout_kernel<<<256, 256, 43008>>>(pc_w);
    pcgemm_kernel<<<288, 256, PCG_SMEM>>>(pc_b);
    squash_h_kernel<<<BATCH, 256>>>();
    uhat_kernel<<<1152, 256>>>(W);
    routing0_kernel<<<BATCH, 160>>>();
    routing_iter_kernel<<<BATCH, 256>>>();
    routing_iter_kernel<<<BATCH, 256>>>();
    mask_kernel<<<320, 256>>>(labels);
    gemm_kernel<0, 0><<<dim3(8, 8), 256>>>(fc1_w, fc1_b, out, 512, 512, 160);
    gemm_kernel<0, 1><<<dim3(16, 8), 256>>>(fc2_w, fc2_b, out, 512, 1024, 512);
    gemm_kernel<1, 2><<<dim3(13, 8), 256>>>(fc3_w, fc3_b, out + 5120, 512, 784, 1024);
    probs_kernel<<<4, 128>>>(out);
}

// round 11
// speedup vs baseline: 1.2350x; 1.0594x over previous
#include <cuda_runtime.h>
#include <cuda_bf16.h>
#include <cuda_fp16.h>
#include <cstdint>
#include <math.h>

// ---------------------------------------------------------------------------
// CapsNet forward. B=512.
//   x -> fp16; conv1 as fp16 mma.sync GEMM (im2col K=81 pad 128) -> g_cl
//   pcconv: fp16 mma.sync implicit GEMM (cp.async 2-stage, M=64 N=256, 2 CTA/SM)
//   squash -> hT; u_hat (fp16); routing x3 (blog: iter1 write-only, iter2
//   read-only, no zeroing); decoder FCs; probs
// Output: [probs (512*10)] then [dec (512*784)]
// ---------------------------------------------------------------------------

#define BATCH 512

__device__ __half g_x16[BATCH * 784];             // input fp16
__device__ __half g_i2c[BATCH * 400 * 128];       // conv1 im2col [npos][128]
__device__ __half g_wr1[256 * 128];               // conv1 w [oc][tap pad 128]
__device__ __half g_cl[BATCH * 400 * 256];        // conv1 out, channel-last fp16
__device__ __half g_wr[256 * 81 * 256];           // pc weights [oc][tap][ic] fp16
__device__ float g_pc[BATCH * 256 * 36];
__device__ float g_hT[BATCH * 1152 * 8];
__device__ __half g_uhat[BATCH * 1152 * 160];     // fp16 storage
__device__ float g_blog[BATCH * 1152 * 10];
__device__ float g_v[BATCH * 160];
__device__ float g_m[BATCH * 160];
__device__ float g_fc1[BATCH * 512];
__device__ float g_fc2[BATCH * 1024];

// ---------------- helpers ---------------------------------------------------
__device__ __forceinline__ uint32_t smem_u32(const void* p) {
    uint32_t a;
    asm("{ .reg .u64 t; cvta.to.shared.u64 t, %1; cvt.u32.u64 %0, t; }"
        : "=r"(a) : "l"(p));
    return a;
}
__device__ __forceinline__ void ldsm_x4(uint32_t& d0, uint32_t& d1,
                                        uint32_t& d2, uint32_t& d3,
                                        uint32_t addr) {
    asm volatile("ldmatrix.sync.aligned.m8n8.x4.shared.b16 {%0,%1,%2,%3}, [%4];"
                 : "=r"(d0), "=r"(d1), "=r"(d2), "=r"(d3) : "r"(addr));
}
__device__ __forceinline__ void mma16816h(float* c, const uint32_t* a,
                                          const uint32_t* b) {
    asm volatile(
        "mma.sync.aligned.m16n8k16.row.col.f32.f16.f16.f32 "
        "{%0,%1,%2,%3}, {%4,%5,%6,%7}, {%8,%9}, {%0,%1,%2,%3};"
        : "+f"(c[0]), "+f"(c[1]), "+f"(c[2]), "+f"(c[3])
        : "r"(a[0]), "r"(a[1]), "r"(a[2]), "r"(a[3]), "r"(b[0]), "r"(b[1]));
}
#define CP16(dst, src) \
    asm volatile("cp.async.cg.shared.global [%0], [%1], 16;" \
                 :: "r"(dst), "l"(src) : "memory")
#define CP_COMMIT() asm volatile("cp.async.commit_group;" ::: "memory")
#define CP_WAIT1() asm volatile("cp.async.wait_group 1;" ::: "memory")
#define CP_WAIT0() asm volatile("cp.async.wait_group 0;" ::: "memory")

// ---------------------------------------------------------------------------
// x -> fp16. grid 392, block 256 (4 elems/thread; 392*1024 = 512*784).
// ---------------------------------------------------------------------------
__global__ void xcvt_kernel(const float* __restrict__ x)
{
    int i = blockIdx.x * 1024 + threadIdx.x * 4;
    float4 v = *(const float4*)(x + i);
    *(__half2*)(g_x16 + i) = __floats2half2_rn(v.x, v.y);
    *(__half2*)(g_x16 + i + 2) = __floats2half2_rn(v.z, v.w);
}

// ---------------------------------------------------------------------------
// conv1 weights -> fp16 [oc][tap] padded to 128. grid 256, block 128.
// ---------------------------------------------------------------------------
__global__ void wr1_kernel(const float* __restrict__ w)
{
    int oc = blockIdx.x;
    int t = threadIdx.x;
    g_wr1[oc * 128 + t] = (t < 81) ? __float2half(w[oc * 81 + t])
                                   : __float2half(0.f);
}

// ---------------------------------------------------------------------------
// im2col: g_x16 -> g_i2c [npos=b*400+oy*20+ox][tap pad 128]. grid 512, blk 256.
// ---------------------------------------------------------------------------
__global__ __launch_bounds__(256) void im2col_kernel()
{
    __shared__ __half s_img[784];
    __shared__ int s_off[128];
    int b = blockIdx.x;
    int tid = threadIdx.x;

    if (tid < 98)
        ((uint4*)s_img)[tid] = ((const uint4*)(g_x16 + b * 784))[tid];
    if (tid < 128)
        s_off[tid] = (tid < 81) ? (tid / 9) * 28 + (tid % 9) : -1;
    __syncthreads();

    for (int it = tid; it < 6400; it += 256) {
        int row = it >> 4;
        int q = it & 15;
        int oy = row / 20;
        int ox = row - oy * 20;
        int base = oy * 28 + ox;
        union { __half h[8]; uint4 u; } val;
        #pragma unroll
        for (int j = 0; j < 8; j++) {
            int off = s_off[q * 8 + j];
            val.h[j] = (off >= 0) ? s_img[base + off] : __float2half(0.f);
        }
        *(uint4*)(g_i2c + (size_t)b * 51200 + row * 128 + q * 8) = val.u;
    }
}

// ---------------------------------------------------------------------------
// conv1 GEMM: C[204800, 256] = relu(A_i2c[., 128] @ W1[256, 128]^T + bias),
// fp16 out channel-last (== g_cl layout). grid 1600, block 256 (4Mx2N warps).
// Both K-chunks loaded once (no pipeline; K=128 only).
// ---------------------------------------------------------------------------
#define C1_A0 0
#define C1_A1 16384
#define C1_B0 32768
#define C1_B1 65536
#define C1_SMEM 98304

__global__ __launch_bounds__(256, 1) void conv1gemm_kernel(
    const float* __restrict__ bias)
{
    extern __shared__ char sm[];
    int tid = threadIdx.x;
    int wid = tid >> 5;
    int lane = tid & 31;
    int warp_m = wid & 3;
    int warp_n = wid >> 2;
    int m0 = blockIdx.x * 128;
    uint32_t smb = smem_u32(sm);

    int r0 = tid >> 3;
    int c = tid & 7;
    uint32_t dbase = (uint32_t)(r0 * 128) + (uint32_t)((c * 16) ^ ((r0 & 7) << 4));

    #pragma unroll
    for (int kc2 = 0; kc2 < 2; kc2++) {
        uint32_t abase = smb + (kc2 ? C1_A1 : C1_A0);
        uint32_t bbase = smb + (kc2 ? C1_B1 : C1_B0);
        #pragma unroll
        for (int i = 0; i < 4; i++)
            CP16(abase + dbase + i * 4096,
                 g_i2c + (size_t)(m0 + r0 + 32 * i) * 128 + kc2 * 64 + c * 8);
        #pragma unroll
        for (int t = 0; t < 8; t++)
            CP16(bbase + dbase + t * 4096,
                 g_wr1 + (r0 + 32 * t) * 128 + kc2 * 64 + c * 8);
    }
    CP_COMMIT();
    CP_WAIT0();
    __syncthreads();

    float acc[2][16][4];
    #pragma unroll
    for (int i = 0; i < 2; i++)
        #pragma unroll
        for (int j = 0; j < 16; j++)
            #pragma unroll
            for (int k = 0; k < 4; k++) acc[i][j][k] = 0.f;

    uint32_t swz = (uint32_t)(lane & 7) << 4;
    uint32_t a_row_off = (uint32_t)(warp_m * 32 + (lane & 15)) * 128;
    uint32_t akb = (uint32_t)(lane >> 4) << 4;
    uint32_t b_row_off =
        (uint32_t)(warp_n * 128 + (lane & 7) + ((lane >> 4) & 1) * 8) * 128;
    uint32_t bkb = (uint32_t)((lane >> 3) & 1) << 4;

    #pragma unroll
    for (int kc2 = 0; kc2 < 2; kc2++) {
        uint32_t a_row = smb + (kc2 ? C1_A1 : C1_A0) + a_row_off;
        uint32_t b_row = smb + (kc2 ? C1_B1 : C1_B0) + b_row_off;
        #pragma unroll
        for (int j = 0; j < 4; j++) {
            uint32_t ka = ((uint32_t)(j * 32) + akb) ^ swz;
            uint32_t ah[8];
            ldsm_x4(ah[0], ah[1], ah[2], ah[3], a_row + ka);
            ldsm_x4(ah[4], ah[5], ah[6], ah[7], a_row + 2048 + ka);
            uint32_t kb = ((uint32_t)(j * 32) + bkb) ^ swz;
            #pragma unroll
            for (int h = 0; h < 2; h++) {
                uint32_t bh[16];
                #pragma unroll
                for (int q = 0; q < 4; q++) {
                    uint32_t bt = b_row + (uint32_t)((h * 4 + q) * 2048) + kb;
                    ldsm_x4(bh[4 * q], bh[4 * q + 1], bh[4 * q + 2], bh[4 * q + 3], bt);
                }
                #pragma unroll
                for (int q = 0; q < 4; q++) {
                    #pragma unroll
                    for (int sub = 0; sub < 2; sub++) {
                        int nn = h * 8 + q * 2 + sub;
                        #pragma unroll
                        for (int tm = 0; tm < 2; tm++)
                            mma16816h(acc[tm][nn], &ah[4 * tm], &bh[4 * q + 2 * sub]);
                    }
                }
            }
        }
    }

    // epilogue: relu(acc+bias) -> g_cl[npos*256 + oc] fp16 (half2 stores)
    int r_in8 = lane >> 2;
    int c_in8 = (lane & 3) * 2;
    #pragma unroll
    for (int tm = 0; tm < 2; tm++) {
        size_t row0 = (size_t)(m0 + warp_m * 32 + tm * 16 + r_in8);
        size_t row1 = row0 + 8;
        #pragma unroll
        for (int nn = 0; nn < 16; nn++) {
            int col = warp_n * 128 + nn * 8 + c_in8;
            float bv0 = __ldg(bias + col);
            float bv1 = __ldg(bias + col + 1);
            const float* cc2 = acc[tm][nn];
            ((__half2*)g_cl)[(row0 * 256 + col) >> 1] =
                __floats2half2_rn(fmaxf(cc2[0] + bv0, 0.f), fmaxf(cc2[1] + bv1, 0.f));
            ((__half2*)g_cl)[(row1 * 256 + col) >> 1] =
                __floats2half2_rn(fmaxf(cc2[2] + bv0, 0.f), fmaxf(cc2[3] + bv1, 0.f));
        }
    }
}

// ---------------------------------------------------------------------------
// weight relayout via smem transpose: pc_w [oc][ic][81] -> g_wr [oc][tap][ic]
// ---------------------------------------------------------------------------
__global__ __launch_bounds__(256) void wrelayout_kernel(const float* __restrict__ w)
{
    extern __shared__ char wsm[];
    __half* sh = (__half*)wsm;
    int oc = blockIdx.x;
    int tid = threadIdx.x;
    const float* src = w + (size_t)oc * 20736;

    for (int j = tid; j < 20736; j += 256) {
        int ic = j / 81;
        int e = j - ic * 81;
        sh[e * 256 + ic] = __float2half(src[j]);
    }
    __syncthreads();

    uint4* dh = (uint4*)(g_wr + (size_t)oc * 20736);
    const uint4* s4 = (const uint4*)sh;
    for (int j = tid; j < 2592; j += 256) dh[j] = s4[j];
}

// ---------------------------------------------------------------------------
// pcconv: fp16 implicit GEMM, cp.async 2-stage, M=64 x N=256 per CTA.
// grid 288, block 256 (8 warps: 2(M) x 4(N)). 2 CTAs/SM. (R10 best config.)
// ---------------------------------------------------------------------------
#define SM_A 0
#define SM_B 8192
#define STAGE 40960
#define PCG_SMEM (2 * STAGE)

__global__ __launch_bounds__(256, 2) void pcgemm_kernel(const float* __restrict__ bias)
{
    extern __shared__ char sm[];
    __shared__ int s_rowbase[64];

    int tid = threadIdx.x;
    int wid = tid >> 5;
    int lane = tid & 31;
    int warp_m = wid & 1;
    int warp_n = wid >> 1;
    int m0 = blockIdx.x * 64;
    uint32_t smb = smem_u32(sm);

    if (tid < 64) {
        int npos = m0 + tid;
        int b = npos / 36;
        int pos = npos - b * 36;
        int y = pos / 6;
        int xq = pos - y * 6;
        s_rowbase[tid] = ((b * 20 + 2 * y) * 20 + 2 * xq) * 256;
    }
    __syncthreads();

    int r0 = tid >> 3;
    int c = tid & 7;
    uint32_t dbase = (uint32_t)(r0 * 128) + (uint32_t)((c * 16) ^ ((r0 & 7) << 4));
    int rb0 = s_rowbase[r0];
    int rb1 = s_rowbase[r0 + 32];
    int bbase0 = r0 * 20736;

#define PCG_ISSUE(K) do { \
    int _kykx = (K) >> 2; \
    int _ic0 = ((K) & 3) << 6; \
    int _ky = _kykx / 9; \
    int _kx = _kykx - _ky * 9; \
    int _asrc = (_ky * 20 + _kx) * 256 + _ic0 + c * 8; \
    int _bsrc = _kykx * 256 + _ic0 + c * 8; \
    uint32_t _st = smb + ((K) & 1) * STAGE; \
    CP16(_st + SM_A + dbase, g_cl + rb0 + _asrc); \
    CP16(_st + SM_A + dbase + 4096, g_cl + rb1 + _asrc); \
    _Pragma("unroll") \
    for (int _t = 0; _t < 8; _t++) \
        CP16(_st + SM_B + dbase + _t * 4096, g_wr + bbase0 + _t * 663552 + _bsrc); \
} while (0)

    float acc[2][8][4];
    #pragma unroll
    for (int i = 0; i < 2; i++)
        #pragma unroll
        for (int j = 0; j < 8; j++)
            #pragma unroll
            for (int k = 0; k < 4; k++) acc[i][j][k] = 0.f;

    uint32_t swz = (uint32_t)(lane & 7) << 4;
    uint32_t a_row_off = SM_A + (uint32_t)(warp_m * 32 + (lane & 15)) * 128;
    uint32_t akb = (uint32_t)(lane >> 4) << 4;
    uint32_t b_row_off = SM_B +
        (uint32_t)(warp_n * 64 + (lane & 7) + ((lane >> 4) & 1) * 8) * 128;
    uint32_t bkb = (uint32_t)((lane >> 3) & 1) << 4;

    PCG_ISSUE(0);
    CP_COMMIT();

    for (int kc = 0; kc < 324; kc++) {
        if (kc < 323) {
            PCG_ISSUE(kc + 1);
            CP_COMMIT();
            CP_WAIT1();
        } else {
            CP_WAIT0();
        }
        __syncthreads();

        uint32_t st = smb + (kc & 1) * STAGE;
        uint32_t a_row = st + a_row_off;
        uint32_t b_row = st + b_row_off;
        #pragma unroll
        for (int j = 0; j < 4; j++) {
            uint32_t ka = ((uint32_t)(j * 32) + akb) ^ swz;
            uint32_t ah[8];
            ldsm_x4(ah[0], ah[1], ah[2], ah[3], a_row + ka);
            ldsm_x4(ah[4], ah[5], ah[6], ah[7], a_row + 2048 + ka);
            uint32_t kb = ((uint32_t)(j * 32) + bkb) ^ swz;
            uint32_t bh[16];
            #pragma unroll
            for (int q = 0; q < 4; q++) {
                uint32_t bt = b_row + (uint32_t)(q * 2048) + kb;
                ldsm_x4(bh[4 * q], bh[4 * q + 1], bh[4 * q + 2], bh[4 * q + 3], bt);
            }
            #pragma unroll
            for (int q = 0; q < 4; q++) {
                #pragma unroll
                for (int sub = 0; sub < 2; sub++) {
                    int nn = q * 2 + sub;
                    #pragma unroll
                    for (int tm = 0; tm < 2; tm++)
                        mma16816h(acc[tm][nn], &ah[4 * tm], &bh[4 * q + 2 * sub]);
                }
            }
        }
        __syncthreads();
    }

    // epilogue
    int r_in8 = lane >> 2;
    int c_in8 = (lane & 3) * 2;
    #pragma unroll
    for (int tm = 0; tm < 2; tm++) {
        int row0 = m0 + warp_m * 32 + tm * 16 + r_in8;
        int b0i = row0 / 36, p0i = row0 - b0i * 36;
        int row1 = row0 + 8;
        int b1i = row1 / 36, p1i = row1 - b1i * 36;
        #pragma unroll
        for (int nn = 0; nn < 8; nn++) {
            int col = warp_n * 64 + nn * 8 + c_in8;
            float bv0 = __ldg(bias + col);
            float bv1 = __ldg(bias + col + 1);
            const float* cc2 = acc[tm][nn];
            g_pc[b0i * 9216 + col * 36 + p0i] = cc2[0] + bv0;
            g_pc[b0i * 9216 + (col + 1) * 36 + p0i] = cc2[1] + bv1;
            g_pc[b1i * 9216 + col * 36 + p1i] = cc2[2] + bv0;
            g_pc[b1i * 9216 + (col + 1) * 36 + p1i] = cc2[3] + bv1;
        }
    }
}

// ---------------------------------------------------------------------------
// squash over 1152 + transpose to hT (smem-staged, coalesced writes).
// ---------------------------------------------------------------------------
__global__ __launch_bounds__(256) void squash_h_kernel()
{
    int b = blockIdx.x;
    int tid = threadIdx.x;
    __shared__ float s_scale[8];
    __shared__ float s_val[9216];
    int g = tid >> 5;
    int lane = tid & 31;
    const float* pb = g_pc + (size_t)b * 9216;

    float ss = 0.f;
    for (int j = lane; j < 1152; j += 32) {
        float v = pb[g * 1152 + j];
        ss += v * v;
    }
    #pragma unroll
    for (int o = 16; o; o >>= 1) ss += __shfl_xor_sync(0xffffffffu, ss, o);
    if (lane == 0) s_scale[g] = sqrtf(ss) / (1.f + ss);
    __syncthreads();

    for (int idx = tid; idx < 9216; idx += 256) {
        int cch = idx / 36;
        s_val[idx] = pb[idx] * s_scale[cch >> 5];
    }
    __syncthreads();

    float* outb = g_hT + (size_t)b * 9216;
    for (int o = tid; o < 9216; o += 256) {
        int pos = o >> 3;
        int g2 = o & 7;
        int cch = g2 * 32 + pos / 36;
        int s = pos % 36;
        outb[o] = s_val[cch * 36 + s];
    }
}

// ---------------------------------------------------------------------------
// u_hat (fp16 out): grid 1152, block 256.
// ---------------------------------------------------------------------------
__global__ __launch_bounds__(256) void uhat_kernel(const float* __restrict__ W)
{
    int i = blockIdx.x;
    __shared__ float sW[1280];
    __shared__ float sh[32 * 8];
    int tid = threadIdx.x;
    for (int j = tid; j < 1280; j += 256)
        sW[(j & 7) * 160 + (j >> 3)] = W[(size_t)i * 1280 + j];

    for (int b0 = 0; b0 < BATCH; b0 += 32) {
        __syncthreads();
        sh[tid] = g_hT[((size_t)(b0 + (tid >> 3)) * 1152 + i) * 8 + (tid & 7)];
        __syncthreads();
        if (tid < 160) {
            #pragma unroll 4
            for (int bb = 0; bb < 32; bb++) {
                float u = 0.f;
                #pragma unroll
                for (int e = 0; e < 8; e++) u += sW[e * 160 + tid] * sh[bb * 8 + e];
                g_uhat[((size_t)(b0 + bb) * 1152 + i) * 160 + tid] = __float2half(u);
            }
        }
    }
}

// ---------------------------------------------------------------------------
// routing iter 0: c = 1/10 -> s = 0.1*sum_i u; v = squash. No blog zeroing
// (iter1 treats blog as 0 and writes it). grid 512, block 160.
// ---------------------------------------------------------------------------
__global__ __launch_bounds__(160) void routing0_kernel()
{
    int b = blockIdx.x;
    int t = threadIdx.x;

    const __half* ub = g_uhat + (size_t)b * 184320;
    float s0 = 0.f, s1 = 0.f, s2 = 0.f, s3 = 0.f;
    for (int i = 0; i < 1152; i += 4) {
        s0 += __half2float(ub[(i + 0) * 160 + t]);
        s1 += __half2float(ub[(i + 1) * 160 + t]);
        s2 += __half2float(ub[(i + 2) * 160 + t]);
        s3 += __half2float(ub[(i + 3) * 160 + t]);
    }
    float s = 0.1f * (s0 + s1 + s2 + s3);

    __shared__ float s_s[160];
    s_s[t] = s;
    __syncthreads();
    int k = t >> 4;
    float n2 = 0.f;
    #pragma unroll
    for (int d = 0; d < 16; d++) {
        float v = s_s[k * 16 + d];
        n2 += v * v;
    }
    g_v[b * 160 + t] = s * (sqrtf(n2) / (1.f + n2));
}

// ---------------------------------------------------------------------------
// routing iter: FIRST=1: b = u.v (no blog read, write blog);
// FIRST=0,LAST=1: b = blog + u.v (read, no write). grid 512, block 256.
// ---------------------------------------------------------------------------
template <int FIRST, int LAST>
__global__ __launch_bounds__(256) void routing_iter_kernel()
{
    int b = blockIdx.x;
    int t = threadIdx.x;
    __shared__ float v_s[160];
    __shared__ float c_s[1152 * 10];
    __shared__ float s_s[160];

    if (t < 160) v_s[t] = g_v[b * 160 + t];
    __syncthreads();

    const __half* ub = g_uhat + (size_t)b * 184320;
    float* blb = g_blog + (size_t)b * 11520;

    for (int i = t; i < 1152; i += 256) {
        const __half2* u2 = (const __half2*)(ub + i * 160);
        float bl[10];
        float mx = -1e30f;
        #pragma unroll
        for (int k = 0; k < 10; k++) {
            float dk = 0.f;
            #pragma unroll
            for (int j = 0; j < 8; j++) {
                float2 u = __half22float2(u2[k * 8 + j]);
                dk += u.x * v_s[k * 16 + 2 * j + 0];
                dk += u.y * v_s[k * 16 + 2 * j + 1];
            }
            float nb = FIRST ? dk : (blb[i * 10 + k] + dk);
            if (!LAST) blb[i * 10 + k] = nb;
            bl[k] = nb;
            mx = fmaxf(mx, nb);
        }
        float sum = 0.f;
        #pragma unroll
        for (int k = 0; k < 10; k++) {
            float e = __expf(bl[k] - mx);
            bl[k] = e;
            sum += e;
        }
        float inv = 1.f / sum;
        #pragma unroll
        for (int k = 0; k < 10; k++) c_s[i * 10 + k] = bl[k] * inv;
    }
    __syncthreads();

    float s = 0.f;
    if (t < 160) {
        int k = t >> 4;
        float p0 = 0.f, p1 = 0.f;
        #pragma unroll 4
        for (int i = 0; i < 1152; i += 2) {
            p0 += c_s[(i + 0) * 10 + k] * __half2float(__ldg(ub + (i + 0) * 160 + t));
            p1 += c_s[(i + 1) * 10 + k] * __half2float(__ldg(ub + (i + 1) * 160 + t));
        }
        s = p0 + p1;
    }
    __syncthreads();
    if (t < 160) s_s[t] = s;
    __syncthreads();
    if (t < 160) {
        int k = t >> 4;
        float n2 = 0.f;
        #pragma unroll
        for (int d = 0; d < 16; d++) {
            float v = s_s[k * 16 + d];
            n2 += v * v;
        }
        g_v[b * 160 + t] = s * (sqrtf(n2) / (1.f + n2));
    }
}

// ---------------------------------------------------------------------------
__global__ void mask_kernel(const float* __restrict__ labels)
{
    int idx = blockIdx.x * 256 + threadIdx.x;
    if (idx < BATCH * 160) {
        int b = idx / 160;
        int k = (idx - b * 160) >> 4;
        g_m[idx] = g_v[idx] * labels[b * 10 + k];
    }
}

// ---------------------------------------------------------------------------
template <int ACT, int SEL>
__global__ __launch_bounds__(256) void gemm_kernel(
    const float* __restrict__ Wt, const float* __restrict__ bias,
    float* __restrict__ outp, int M, int N, int K)
{
    const float* A = (SEL == 0) ? g_m : (SEL == 1) ? g_fc1 : g_fc2;
    float* C = (SEL == 0) ? g_fc1 : (SEL == 1) ? g_fc2 : outp;

    __shared__ float As[8][64];
    __shared__ float Bs[8][64];
    int n0 = blockIdx.x * 64;
    int m0 = blockIdx.y * 64;
    int tid = threadIdx.x;
    int tx = tid & 15;
    int ty = tid >> 4;

    float acc[4][4];
    #pragma unroll
    for (int i = 0; i < 4; i++)
        #pragma unroll
        for (int j = 0; j < 4; j++) acc[i][j] = 0.f;

    for (int k0 = 0; k0 < K; k0 += 8) {
        __syncthreads();
        #pragma unroll
        for (int l = 0; l < 2; l++) {
            int e = tid + l * 256;
            int r = e >> 3;
            int kk = e & 7;
            As[kk][r] = A[(m0 + r) * K + k0 + kk];
            int n = n0 + r;
            Bs[kk][r] = (n < N) ? Wt[n * K + k0 + kk] : 0.f;
        }
        __syncthreads();
        #pragma unroll
        for (int kk = 0; kk < 8; kk++) {
            float4 a4 = *(const float4*)&As[kk][ty * 4];
            float4 b4 = *(const float4*)&Bs[kk][tx * 4];
            float a[4] = {a4.x, a4.y, a4.z, a4.w};
            float bb[4] = {b4.x, b4.y, b4.z, b4.w};
            #pragma unroll
            for (int i = 0; i < 4; i++)
                #pragma unroll
                for (int j = 0; j < 4; j++) acc[i][j] += a[i] * bb[j];
        }
    }

    #pragma unroll
    for (int i = 0; i < 4; i++) {
        int m = m0 + ty * 4 + i;
        #pragma unroll
        for (int j = 0; j < 4; j++) {
            int n = n0 + tx * 4 + j;
            if (n < N) {
                float v = acc[i][j] + bias[n];
                if (ACT == 0) v = fmaxf(v, 0.f);
                else v = 1.f / (1.f + __expf(-v));
                C[m * N + n] = v;
            }
        }
    }
}

// ---------------------------------------------------------------------------
__global__ void probs_kernel(float* __restrict__ out)
{
    int b = blockIdx.x * 128 + threadIdx.x;
    if (b < BATCH) {
        float nr[10];
        float mx = -1e30f;
        #pragma unroll
        for (int k = 0; k < 10; k++) {
            float n2 = 0.f;
            #pragma unroll
            for (int d = 0; d < 16; d++) {
                float v = g_v[b * 160 + k * 16 + d];
                n2 += v * v;
            }
            nr[k] = sqrtf(n2);
            mx = fmaxf(mx, nr[k]);
        }
        float sum = 0.f;
        #pragma unroll
        for (int k = 0; k < 10; k++) {
            nr[k] = __expf(nr[k] - mx);
            sum += nr[k];
        }
        float inv = 1.f / sum;
        #pragma unroll
        for (int k = 0; k < 10; k++) out[b * 10 + k] = nr[k] * inv;
    }
}

// ---------------------------------------------------------------------------
extern "C" void kernel_launch(void* const* d_in, const int* in_sizes, int n_in,
                              void* d_out, int out_size)
{
    const float* x       = (const float*)d_in[0];
    const float* labels  = (const float*)d_in[1];
    const float* conv1_w = (const float*)d_in[2];
    const float* conv1_b = (const float*)d_in[3];
    const float* pc_w    = (const float*)d_in[4];
    const float* pc_b    = (const float*)d_in[5];
    const float* W       = (const float*)d_in[6];
    const float* fc1_w   = (const float*)d_in[7];
    const float* fc1_b   = (const float*)d_in[8];
    const float* fc2_w   = (const float*)d_in[9];
    const float* fc2_b   = (const float*)d_in[10];
    const float* fc3_w   = (const float*)d_in[11];
    const float* fc3_b   = (const float*)d_in[12];
    float* out = (float*)d_out;

    cudaFuncSetAttribute(pcgemm_kernel,
                         cudaFuncAttributeMaxDynamicSharedMemorySize, PCG_SMEM);
    cudaFuncSetAttribute(conv1gemm_kernel,
                         cudaFuncAttributeMaxDynamicSharedMemorySize, C1_SMEM);
    cudaFuncSetAttribute(wrelayout_kernel,
                         cudaFuncAttributeMaxDynamicSharedMemorySize, 43008);

    xcvt_kernel<<<392, 256>>>(x);
    wr1_kernel<<<256, 128>>>(conv1_w);
    wrelayout_kernel<<<256, 256, 43008>>>(pc_w);
    im2col_kernel<<<BATCH, 256>>>();
    conv1gemm_kernel<<<1600, 256, C1_SMEM>>>(conv1_b);
    pcgemm_kernel<<<288, 256, PCG_SMEM>>>(pc_b);
    squash_h_kernel<<<BATCH, 256>>>();
    uhat_kernel<<<1152, 256>>>(W);
    routing0_kernel<<<BATCH, 160>>>();
    routing_iter_kernel<1, 0><<<BATCH, 256>>>();
    routing_iter_kernel<0, 1><<<BATCH, 256>>>();
    mask_kernel<<<320, 256>>>(labels);
    gemm_kernel<0, 0><<<dim3(8, 8), 256>>>(fc1_w, fc1_b, out, 512, 512, 160);
    gemm_kernel<0, 1><<<dim3(16, 8), 256>>>(fc2_w, fc2_b, out, 512, 1024, 512);
    gemm_kernel<1, 2><<<dim3(13, 8), 256>>>(fc3_w, fc3_b, out + 5120, 512, 784, 1024);
    probs_kernel<<<4, 128>>>(out);
}

// round 12
// speedup vs baseline: 1.3457x; 1.0897x over previous
#include <cuda_runtime.h>
#include <cuda_bf16.h>
#include <cuda_fp16.h>
#include <cstdint>
#include <math.h>

// ---------------------------------------------------------------------------
// CapsNet forward. B=512.
//   x -> fp16; conv1 as fp16 mma.sync GEMM (im2col K=81 pad 128) -> g_cl
//   pcconv: fp16 mma.sync implicit GEMM (cp.async 2-stage, M=64 N=256, 2 CTA/SM)
//   squash -> hT; u_hat (fp16, grid split); routing x3 (blog edge-elided,
//   uint4 phase-A loads); decoder FCs (mask fused into fc1); probs
// Output: [probs (512*10)] then [dec (512*784)]
// ---------------------------------------------------------------------------

#define BATCH 512

__device__ __half g_x16[BATCH * 784];             // input fp16
__device__ __half g_i2c[BATCH * 400 * 128];       // conv1 im2col [npos][128]
__device__ __half g_wr1[256 * 128];               // conv1 w [oc][tap pad 128]
__device__ __half g_cl[BATCH * 400 * 256];        // conv1 out, channel-last fp16
__device__ __half g_wr[256 * 81 * 256];           // pc weights [oc][tap][ic] fp16
__device__ float g_pc[BATCH * 256 * 36];
__device__ float g_hT[BATCH * 1152 * 8];
__device__ __half g_uhat[BATCH * 1152 * 160];     // fp16 storage
__device__ float g_blog[BATCH * 1152 * 10];
__device__ float g_v[BATCH * 160];
__device__ float g_fc1[BATCH * 512];
__device__ float g_fc2[BATCH * 1024];

// ---------------- helpers ---------------------------------------------------
__device__ __forceinline__ uint32_t smem_u32(const void* p) {
    uint32_t a;
    asm("{ .reg .u64 t; cvta.to.shared.u64 t, %1; cvt.u32.u64 %0, t; }"
        : "=r"(a) : "l"(p));
    return a;
}
__device__ __forceinline__ void ldsm_x4(uint32_t& d0, uint32_t& d1,
                                        uint32_t& d2, uint32_t& d3,
                                        uint32_t addr) {
    asm volatile("ldmatrix.sync.aligned.m8n8.x4.shared.b16 {%0,%1,%2,%3}, [%4];"
                 : "=r"(d0), "=r"(d1), "=r"(d2), "=r"(d3) : "r"(addr));
}
__device__ __forceinline__ void mma16816h(float* c, const uint32_t* a,
                                          const uint32_t* b) {
    asm volatile(
        "mma.sync.aligned.m16n8k16.row.col.f32.f16.f16.f32 "
        "{%0,%1,%2,%3}, {%4,%5,%6,%7}, {%8,%9}, {%0,%1,%2,%3};"
        : "+f"(c[0]), "+f"(c[1]), "+f"(c[2]), "+f"(c[3])
        : "r"(a[0]), "r"(a[1]), "r"(a[2]), "r"(a[3]), "r"(b[0]), "r"(b[1]));
}
#define CP16(dst, src) \
    asm volatile("cp.async.cg.shared.global [%0], [%1], 16;" \
                 :: "r"(dst), "l"(src) : "memory")
#define CP_COMMIT() asm volatile("cp.async.commit_group;" ::: "memory")
#define CP_WAIT1() asm volatile("cp.async.wait_group 1;" ::: "memory")
#define CP_WAIT0() asm volatile("cp.async.wait_group 0;" ::: "memory")

// ---------------------------------------------------------------------------
// x -> fp16. grid 392, block 256.
// ---------------------------------------------------------------------------
__global__ void xcvt_kernel(const float* __restrict__ x)
{
    int i = blockIdx.x * 1024 + threadIdx.x * 4;
    float4 v = *(const float4*)(x + i);
    *(__half2*)(g_x16 + i) = __floats2half2_rn(v.x, v.y);
    *(__half2*)(g_x16 + i + 2) = __floats2half2_rn(v.z, v.w);
}

// ---------------------------------------------------------------------------
// conv1 weights -> fp16 [oc][tap pad 128]. grid 256, block 128.
// ---------------------------------------------------------------------------
__global__ void wr1_kernel(const float* __restrict__ w)
{
    int oc = blockIdx.x;
    int t = threadIdx.x;
    g_wr1[oc * 128 + t] = (t < 81) ? __float2half(w[oc * 81 + t])
                                   : __float2half(0.f);
}

// ---------------------------------------------------------------------------
// im2col: g_x16 -> g_i2c [npos][tap pad 128]. grid 512, block 256.
// ---------------------------------------------------------------------------
__global__ __launch_bounds__(256) void im2col_kernel()
{
    __shared__ __half s_img[784];
    __shared__ int s_off[128];
    int b = blockIdx.x;
    int tid = threadIdx.x;

    if (tid < 98)
        ((uint4*)s_img)[tid] = ((const uint4*)(g_x16 + b * 784))[tid];
    if (tid < 128)
        s_off[tid] = (tid < 81) ? (tid / 9) * 28 + (tid % 9) : -1;
    __syncthreads();

    for (int it = tid; it < 6400; it += 256) {
        int row = it >> 4;
        int q = it & 15;
        int oy = row / 20;
        int ox = row - oy * 20;
        int base = oy * 28 + ox;
        union { __half h[8]; uint4 u; } val;
        #pragma unroll
        for (int j = 0; j < 8; j++) {
            int off = s_off[q * 8 + j];
            val.h[j] = (off >= 0) ? s_img[base + off] : __float2half(0.f);
        }
        *(uint4*)(g_i2c + (size_t)b * 51200 + row * 128 + q * 8) = val.u;
    }
}

// ---------------------------------------------------------------------------
// conv1 GEMM: C[204800,256] = relu(i2c @ W1^T + bias) -> g_cl fp16.
// grid 1600, block 256.
// ---------------------------------------------------------------------------
#define C1_A0 0
#define C1_A1 16384
#define C1_B0 32768
#define C1_B1 65536
#define C1_SMEM 98304

__global__ __launch_bounds__(256, 1) void conv1gemm_kernel(
    const float* __restrict__ bias)
{
    extern __shared__ char sm[];
    int tid = threadIdx.x;
    int wid = tid >> 5;
    int lane = tid & 31;
    int warp_m = wid & 3;
    int warp_n = wid >> 2;
    int m0 = blockIdx.x * 128;
    uint32_t smb = smem_u32(sm);

    int r0 = tid >> 3;
    int c = tid & 7;
    uint32_t dbase = (uint32_t)(r0 * 128) + (uint32_t)((c * 16) ^ ((r0 & 7) << 4));

    #pragma unroll
    for (int kc2 = 0; kc2 < 2; kc2++) {
        uint32_t abase = smb + (kc2 ? C1_A1 : C1_A0);
        uint32_t bbase = smb + (kc2 ? C1_B1 : C1_B0);
        #pragma unroll
        for (int i = 0; i < 4; i++)
            CP16(abase + dbase + i * 4096,
                 g_i2c + (size_t)(m0 + r0 + 32 * i) * 128 + kc2 * 64 + c * 8);
        #pragma unroll
        for (int t = 0; t < 8; t++)
            CP16(bbase + dbase + t * 4096,
                 g_wr1 + (r0 + 32 * t) * 128 + kc2 * 64 + c * 8);
    }
    CP_COMMIT();
    CP_WAIT0();
    __syncthreads();

    float acc[2][16][4];
    #pragma unroll
    for (int i = 0; i < 2; i++)
        #pragma unroll
        for (int j = 0; j < 16; j++)
            #pragma unroll
            for (int k = 0; k < 4; k++) acc[i][j][k] = 0.f;

    uint32_t swz = (uint32_t)(lane & 7) << 4;
    uint32_t a_row_off = (uint32_t)(warp_m * 32 + (lane & 15)) * 128;
    uint32_t akb = (uint32_t)(lane >> 4) << 4;
    uint32_t b_row_off =
        (uint32_t)(warp_n * 128 + (lane & 7) + ((lane >> 4) & 1) * 8) * 128;
    uint32_t bkb = (uint32_t)((lane >> 3) & 1) << 4;

    #pragma unroll
    for (int kc2 = 0; kc2 < 2; kc2++) {
        uint32_t a_row = smb + (kc2 ? C1_A1 : C1_A0) + a_row_off;
        uint32_t b_row = smb + (kc2 ? C1_B1 : C1_B0) + b_row_off;
        #pragma unroll
        for (int j = 0; j < 4; j++) {
            uint32_t ka = ((uint32_t)(j * 32) + akb) ^ swz;
            uint32_t ah[8];
            ldsm_x4(ah[0], ah[1], ah[2], ah[3], a_row + ka);
            ldsm_x4(ah[4], ah[5], ah[6], ah[7], a_row + 2048 + ka);
            uint32_t kb = ((uint32_t)(j * 32) + bkb) ^ swz;
            #pragma unroll
            for (int h = 0; h < 2; h++) {
                uint32_t bh[16];
                #pragma unroll
                for (int q = 0; q < 4; q++) {
                    uint32_t bt = b_row + (uint32_t)((h * 4 + q) * 2048) + kb;
                    ldsm_x4(bh[4 * q], bh[4 * q + 1], bh[4 * q + 2], bh[4 * q + 3], bt);
                }
                #pragma unroll
                for (int q = 0; q < 4; q++) {
                    #pragma unroll
                    for (int sub = 0; sub < 2; sub++) {
                        int nn = h * 8 + q * 2 + sub;
                        #pragma unroll
                        for (int tm = 0; tm < 2; tm++)
                            mma16816h(acc[tm][nn], &ah[4 * tm], &bh[4 * q + 2 * sub]);
                    }
                }
            }
        }
    }

    int r_in8 = lane >> 2;
    int c_in8 = (lane & 3) * 2;
    #pragma unroll
    for (int tm = 0; tm < 2; tm++) {
        size_t row0 = (size_t)(m0 + warp_m * 32 + tm * 16 + r_in8);
        size_t row1 = row0 + 8;
        #pragma unroll
        for (int nn = 0; nn < 16; nn++) {
            int col = warp_n * 128 + nn * 8 + c_in8;
            float bv0 = __ldg(bias + col);
            float bv1 = __ldg(bias + col + 1);
            const float* cc2 = acc[tm][nn];
            ((__half2*)g_cl)[(row0 * 256 + col) >> 1] =
                __floats2half2_rn(fmaxf(cc2[0] + bv0, 0.f), fmaxf(cc2[1] + bv1, 0.f));
            ((__half2*)g_cl)[(row1 * 256 + col) >> 1] =
                __floats2half2_rn(fmaxf(cc2[2] + bv0, 0.f), fmaxf(cc2[3] + bv1, 0.f));
        }
    }
}

// ---------------------------------------------------------------------------
// weight relayout: pc_w [oc][ic][81] -> g_wr [oc][tap][ic] fp16.
// ---------------------------------------------------------------------------
__global__ __launch_bounds__(256) void wrelayout_kernel(const float* __restrict__ w)
{
    extern __shared__ char wsm[];
    __half* sh = (__half*)wsm;
    int oc = blockIdx.x;
    int tid = threadIdx.x;
    const float* src = w + (size_t)oc * 20736;

    for (int j = tid; j < 20736; j += 256) {
        int ic = j / 81;
        int e = j - ic * 81;
        sh[e * 256 + ic] = __float2half(src[j]);
    }
    __syncthreads();

    uint4* dh = (uint4*)(g_wr + (size_t)oc * 20736);
    const uint4* s4 = (const uint4*)sh;
    for (int j = tid; j < 2592; j += 256) dh[j] = s4[j];
}

// ---------------------------------------------------------------------------
// pcconv: fp16 implicit GEMM, cp.async 2-stage, M=64 x N=256, 2 CTAs/SM.
// grid 288, block 256. (R10/R11 best config, unchanged.)
// ---------------------------------------------------------------------------
#define SM_A 0
#define SM_B 8192
#define STAGE 40960
#define PCG_SMEM (2 * STAGE)

__global__ __launch_bounds__(256, 2) void pcgemm_kernel(const float* __restrict__ bias)
{
    extern __shared__ char sm[];
    __shared__ int s_rowbase[64];

    int tid = threadIdx.x;
    int wid = tid >> 5;
    int lane = tid & 31;
    int warp_m = wid & 1;
    int warp_n = wid >> 1;
    int m0 = blockIdx.x * 64;
    uint32_t smb = smem_u32(sm);

    if (tid < 64) {
        int npos = m0 + tid;
        int b = npos / 36;
        int pos = npos - b * 36;
        int y = pos / 6;
        int xq = pos - y * 6;
        s_rowbase[tid] = ((b * 20 + 2 * y) * 20 + 2 * xq) * 256;
    }
    __syncthreads();

    int r0 = tid >> 3;
    int c = tid & 7;
    uint32_t dbase = (uint32_t)(r0 * 128) + (uint32_t)((c * 16) ^ ((r0 & 7) << 4));
    int rb0 = s_rowbase[r0];
    int rb1 = s_rowbase[r0 + 32];
    int bbase0 = r0 * 20736;

#define PCG_ISSUE(K) do { \
    int _kykx = (K) >> 2; \
    int _ic0 = ((K) & 3) << 6; \
    int _ky = _kykx / 9; \
    int _kx = _kykx - _ky * 9; \
    int _asrc = (_ky * 20 + _kx) * 256 + _ic0 + c * 8; \
    int _bsrc = _kykx * 256 + _ic0 + c * 8; \
    uint32_t _st = smb + ((K) & 1) * STAGE; \
    CP16(_st + SM_A + dbase, g_cl + rb0 + _asrc); \
    CP16(_st + SM_A + dbase + 4096, g_cl + rb1 + _asrc); \
    _Pragma("unroll") \
    for (int _t = 0; _t < 8; _t++) \
        CP16(_st + SM_B + dbase + _t * 4096, g_wr + bbase0 + _t * 663552 + _bsrc); \
} while (0)

    float acc[2][8][4];
    #pragma unroll
    for (int i = 0; i < 2; i++)
        #pragma unroll
        for (int j = 0; j < 8; j++)
            #pragma unroll
            for (int k = 0; k < 4; k++) acc[i][j][k] = 0.f;

    uint32_t swz = (uint32_t)(lane & 7) << 4;
    uint32_t a_row_off = SM_A + (uint32_t)(warp_m * 32 + (lane & 15)) * 128;
    uint32_t akb = (uint32_t)(lane >> 4) << 4;
    uint32_t b_row_off = SM_B +
        (uint32_t)(warp_n * 64 + (lane & 7) + ((lane >> 4) & 1) * 8) * 128;
    uint32_t bkb = (uint32_t)((lane >> 3) & 1) << 4;

    PCG_ISSUE(0);
    CP_COMMIT();

    for (int kc = 0; kc < 324; kc++) {
        if (kc < 323) {
            PCG_ISSUE(kc + 1);
            CP_COMMIT();
            CP_WAIT1();
        } else {
            CP_WAIT0();
        }
        __syncthreads();

        uint32_t st = smb + (kc & 1) * STAGE;
        uint32_t a_row = st + a_row_off;
        uint32_t b_row = st + b_row_off;
        #pragma unroll
        for (int j = 0; j < 4; j++) {
            uint32_t ka = ((uint32_t)(j * 32) + akb) ^ swz;
            uint32_t ah[8];
            ldsm_x4(ah[0], ah[1], ah[2], ah[3], a_row + ka);
            ldsm_x4(ah[4], ah[5], ah[6], ah[7], a_row + 2048 + ka);
            uint32_t kb = ((uint32_t)(j * 32) + bkb) ^ swz;
            uint32_t bh[16];
            #pragma unroll
            for (int q = 0; q < 4; q++) {
                uint32_t bt = b_row + (uint32_t)(q * 2048) + kb;
                ldsm_x4(bh[4 * q], bh[4 * q + 1], bh[4 * q + 2], bh[4 * q + 3], bt);
            }
            #pragma unroll
            for (int q = 0; q < 4; q++) {
                #pragma unroll
                for (int sub = 0; sub < 2; sub++) {
                    int nn = q * 2 + sub;
                    #pragma unroll
                    for (int tm = 0; tm < 2; tm++)
                        mma16816h(acc[tm][nn], &ah[4 * tm], &bh[4 * q + 2 * sub]);
                }
            }
        }
        __syncthreads();
    }

    int r_in8 = lane >> 2;
    int c_in8 = (lane & 3) * 2;
    #pragma unroll
    for (int tm = 0; tm < 2; tm++) {
        int row0 = m0 + warp_m * 32 + tm * 16 + r_in8;
        int b0i = row0 / 36, p0i = row0 - b0i * 36;
        int row1 = row0 + 8;
        int b1i = row1 / 36, p1i = row1 - b1i * 36;
        #pragma unroll
        for (int nn = 0; nn < 8; nn++) {
            int col = warp_n * 64 + nn * 8 + c_in8;
            float bv0 = __ldg(bias + col);
            float bv1 = __ldg(bias + col + 1);
            const float* cc2 = acc[tm][nn];
            g_pc[b0i * 9216 + col * 36 + p0i] = cc2[0] + bv0;
            g_pc[b0i * 9216 + (col + 1) * 36 + p0i] = cc2[1] + bv1;
            g_pc[b1i * 9216 + col * 36 + p1i] = cc2[2] + bv0;
            g_pc[b1i * 9216 + (col + 1) * 36 + p1i] = cc2[3] + bv1;
        }
    }
}

// ---------------------------------------------------------------------------
// squash + transpose to hT. grid 512, block 256.
// ---------------------------------------------------------------------------
__global__ __launch_bounds__(256) void squash_h_kernel()
{
    int b = blockIdx.x;
    int tid = threadIdx.x;
    __shared__ float s_scale[8];
    __shared__ float s_val[9216];
    int g = tid >> 5;
    int lane = tid & 31;
    const float* pb = g_pc + (size_t)b * 9216;

    float ss = 0.f;
    for (int j = lane; j < 1152; j += 32) {
        float v = pb[g * 1152 + j];
        ss += v * v;
    }
    #pragma unroll
    for (int o = 16; o; o >>= 1) ss += __shfl_xor_sync(0xffffffffu, ss, o);
    if (lane == 0) s_scale[g] = sqrtf(ss) / (1.f + ss);
    __syncthreads();

    for (int idx = tid; idx < 9216; idx += 256) {
        int cch = idx / 36;
        s_val[idx] = pb[idx] * s_scale[cch >> 5];
    }
    __syncthreads();

    float* outb = g_hT + (size_t)b * 9216;
    for (int o = tid; o < 9216; o += 256) {
        int pos = o >> 3;
        int g2 = o & 7;
        int cch = g2 * 32 + pos / 36;
        int s = pos % 36;
        outb[o] = s_val[cch * 36 + s];
    }
}

// ---------------------------------------------------------------------------
// u_hat (fp16 out): grid (1152, 2), block 256; each block does 256 images.
// ---------------------------------------------------------------------------
__global__ __launch_bounds__(256) void uhat_kernel(const float* __restrict__ W)
{
    int i = blockIdx.x;
    int bh = blockIdx.y * 256;
    __shared__ float sW[1280];
    __shared__ float sh[32 * 8];
    int tid = threadIdx.x;
    for (int j = tid; j < 1280; j += 256)
        sW[(j & 7) * 160 + (j >> 3)] = W[(size_t)i * 1280 + j];

    for (int b0 = bh; b0 < bh + 256; b0 += 32) {
        __syncthreads();
        sh[tid] = g_hT[((size_t)(b0 + (tid >> 3)) * 1152 + i) * 8 + (tid & 7)];
        __syncthreads();
        if (tid < 160) {
            #pragma unroll 4
            for (int bb = 0; bb < 32; bb++) {
                float u = 0.f;
                #pragma unroll
                for (int e = 0; e < 8; e++) u += sW[e * 160 + tid] * sh[bb * 8 + e];
                g_uhat[((size_t)(b0 + bb) * 1152 + i) * 160 + tid] = __float2half(u);
            }
        }
    }
}

// ---------------------------------------------------------------------------
// routing iter 0: s = 0.1*sum_i u; v = squash. grid 512, block 160.
// ---------------------------------------------------------------------------
__global__ __launch_bounds__(160) void routing0_kernel()
{
    int b = blockIdx.x;
    int t = threadIdx.x;

    const __half* ub = g_uhat + (size_t)b * 184320;
    float s0 = 0.f, s1 = 0.f, s2 = 0.f, s3 = 0.f;
    for (int i = 0; i < 1152; i += 4) {
        s0 += __half2float(ub[(i + 0) * 160 + t]);
        s1 += __half2float(ub[(i + 1) * 160 + t]);
        s2 += __half2float(ub[(i + 2) * 160 + t]);
        s3 += __half2float(ub[(i + 3) * 160 + t]);
    }
    float s = 0.1f * (s0 + s1 + s2 + s3);

    __shared__ float s_s[160];
    s_s[t] = s;
    __syncthreads();
    int k = t >> 4;
    float n2 = 0.f;
    #pragma unroll
    for (int d = 0; d < 16; d++) {
        float v = s_s[k * 16 + d];
        n2 += v * v;
    }
    g_v[b * 160 + t] = s * (sqrtf(n2) / (1.f + n2));
}

// ---------------------------------------------------------------------------
// routing iter: FIRST=1: b = u.v (write blog); LAST=1: b = blog + u.v (no
// write). Phase A with uint4 loads. grid 512, block 256.
// ---------------------------------------------------------------------------
template <int FIRST, int LAST>
__global__ __launch_bounds__(256) void routing_iter_kernel()
{
    int b = blockIdx.x;
    int t = threadIdx.x;
    __shared__ float v_s[160];
    __shared__ float c_s[1152 * 10];
    __shared__ float s_s[160];

    if (t < 160) v_s[t] = g_v[b * 160 + t];
    __syncthreads();

    const __half* ub = g_uhat + (size_t)b * 184320;
    float* blb = g_blog + (size_t)b * 11520;

    for (int i = t; i < 1152; i += 256) {
        const uint4* u4 = (const uint4*)(ub + i * 160);   // 20 x uint4
        float bl[10];
        float mx = -1e30f;
        #pragma unroll
        for (int k = 0; k < 10; k++) {
            uint4 ua = u4[2 * k];
            uint4 ubv = u4[2 * k + 1];
            const __half2* ha = (const __half2*)&ua;
            const __half2* hb = (const __half2*)&ubv;
            float dk = 0.f;
            #pragma unroll
            for (int j = 0; j < 4; j++) {
                float2 f = __half22float2(ha[j]);
                dk += f.x * v_s[k * 16 + 2 * j + 0];
                dk += f.y * v_s[k * 16 + 2 * j + 1];
            }
            #pragma unroll
            for (int j = 0; j < 4; j++) {
                float2 f = __half22float2(hb[j]);
                dk += f.x * v_s[k * 16 + 8 + 2 * j + 0];
                dk += f.y * v_s[k * 16 + 8 + 2 * j + 1];
            }
            float nb = FIRST ? dk : (blb[i * 10 + k] + dk);
            if (!LAST) blb[i * 10 + k] = nb;
            bl[k] = nb;
            mx = fmaxf(mx, nb);
        }
        float sum = 0.f;
        #pragma unroll
        for (int k = 0; k < 10; k++) {
            float e = __expf(bl[k] - mx);
            bl[k] = e;
            sum += e;
        }
        float inv = 1.f / sum;
        #pragma unroll
        for (int k = 0; k < 10; k++) c_s[i * 10 + k] = bl[k] * inv;
    }
    __syncthreads();

    float s = 0.f;
    if (t < 160) {
        int k = t >> 4;
        float p0 = 0.f, p1 = 0.f, p2 = 0.f, p3 = 0.f;
        #pragma unroll 2
        for (int i = 0; i < 1152; i += 4) {
            p0 += c_s[(i + 0) * 10 + k] * __half2float(__ldg(ub + (i + 0) * 160 + t));
            p1 += c_s[(i + 1) * 10 + k] * __half2float(__ldg(ub + (i + 1) * 160 + t));
            p2 += c_s[(i + 2) * 10 + k] * __half2float(__ldg(ub + (i + 2) * 160 + t));
            p3 += c_s[(i + 3) * 10 + k] * __half2float(__ldg(ub + (i + 3) * 160 + t));
        }
        s = (p0 + p1) + (p2 + p3);
    }
    __syncthreads();
    if (t < 160) s_s[t] = s;
    __syncthreads();
    if (t < 160) {
        int k = t >> 4;
        float n2 = 0.f;
        #pragma unroll
        for (int d = 0; d < 16; d++) {
            float v = s_s[k * 16 + d];
            n2 += v * v;
        }
        g_v[b * 160 + t] = s * (sqrtf(n2) / (1.f + n2));
    }
}

// ---------------------------------------------------------------------------
// GEMM: C[M,N] = act(A @ Wt^T + bias). SEL0 fuses mask (A = v * label).
// ---------------------------------------------------------------------------
template <int ACT, int SEL>
__global__ __launch_bounds__(256) void gemm_kernel(
    const float* __restrict__ Wt, const float* __restrict__ bias,
    const float* __restrict__ labels,
    float* __restrict__ outp, int M, int N, int K)
{
    const float* A = (SEL == 0) ? g_v : (SEL == 1) ? g_fc1 : g_fc2;
    float* C = (SEL == 0) ? g_fc1 : (SEL == 1) ? g_fc2 : outp;

    __shared__ float As[8][64];
    __shared__ float Bs[8][64];
    int n0 = blockIdx.x * 64;
    int m0 = blockIdx.y * 64;
    int tid = threadIdx.x;
    int tx = tid & 15;
    int ty = tid >> 4;

    float acc[4][4];
    #pragma unroll
    for (int i = 0; i < 4; i++)
        #pragma unroll
        for (int j = 0; j < 4; j++) acc[i][j] = 0.f;

    for (int k0 = 0; k0 < K; k0 += 8) {
        __syncthreads();
        #pragma unroll
        for (int l = 0; l < 2; l++) {
            int e = tid + l * 256;
            int r = e >> 3;
            int kk = e & 7;
            float a = A[(m0 + r) * K + k0 + kk];
            if (SEL == 0)
                a *= __ldg(labels + (m0 + r) * 10 + ((k0 + kk) >> 4));
            As[kk][r] = a;
            int n = n0 + r;
            Bs[kk][r] = (n < N) ? Wt[n * K + k0 + kk] : 0.f;
        }
        __syncthreads();
        #pragma unroll
        for (int kk = 0; kk < 8; kk++) {
            float4 a4 = *(const float4*)&As[kk][ty * 4];
            float4 b4 = *(const float4*)&Bs[kk][tx * 4];
            float a[4] = {a4.x, a4.y, a4.z, a4.w};
            float bb[4] = {b4.x, b4.y, b4.z, b4.w};
            #pragma unroll
            for (int i = 0; i < 4; i++)
                #pragma unroll
                for (int j = 0; j < 4; j++) acc[i][j] += a[i] * bb[j];
        }
    }

    #pragma unroll
    for (int i = 0; i < 4; i++) {
        int m = m0 + ty * 4 + i;
        #pragma unroll
        for (int j = 0; j < 4; j++) {
            int n = n0 + tx * 4 + j;
            if (n < N) {
                float v = acc[i][j] + bias[n];
                if (ACT == 0) v = fmaxf(v, 0.f);
                else v = 1.f / (1.f + __expf(-v));
                C[m * N + n] = v;
            }
        }
    }
}

// ---------------------------------------------------------------------------
__global__ void probs_kernel(float* __restrict__ out)
{
    int b = blockIdx.x * 128 + threadIdx.x;
    if (b < BATCH) {
        float nr[10];
        float mx = -1e30f;
        #pragma unroll
        for (int k = 0; k < 10; k++) {
            float n2 = 0.f;
            #pragma unroll
            for (int d = 0; d < 16; d++) {
                float v = g_v[b * 160 + k * 16 + d];
                n2 += v * v;
            }
            nr[k] = sqrtf(n2);
            mx = fmaxf(mx, nr[k]);
        }
        float sum = 0.f;
        #pragma unroll
        for (int k = 0; k < 10; k++) {
            nr[k] = __expf(nr[k] - mx);
            sum += nr[k];
        }
        float inv = 1.f / sum;
        #pragma unroll
        for (int k = 0; k < 10; k++) out[b * 10 + k] = nr[k] * inv;
    }
}

// ---------------------------------------------------------------------------
extern "C" void kernel_launch(void* const* d_in, const int* in_sizes, int n_in,
                              void* d_out, int out_size)
{
    const float* x       = (const float*)d_in[0];
    const float* labels  = (const float*)d_in[1];
    const float* conv1_w = (const float*)d_in[2];
    const float* conv1_b = (const float*)d_in[3];
    const float* pc_w    = (const float*)d_in[4];
    const float* pc_b    = (const float*)d_in[5];
    const float* W       = (const float*)d_in[6];
    const float* fc1_w   = (const float*)d_in[7];
    const float* fc1_b   = (const float*)d_in[8];
    const float* fc2_w   = (const float*)d_in[9];
    const float* fc2_b   = (const float*)d_in[10];
    const float* fc3_w   = (const float*)d_in[11];
    const float* fc3_b   = (const float*)d_in[12];
    float* out = (float*)d_out;

    cudaFuncSetAttribute(pcgemm_kernel,
                         cudaFuncAttributeMaxDynamicSharedMemorySize, PCG_SMEM);
    cudaFuncSetAttribute(conv1gemm_kernel,
                         cudaFuncAttributeMaxDynamicSharedMemorySize, C1_SMEM);
    cudaFuncSetAttribute(wrelayout_kernel,
                         cudaFuncAttributeMaxDynamicSharedMemorySize, 43008);

    xcvt_kernel<<<392, 256>>>(x);
    wr1_kernel<<<256, 128>>>(conv1_w);
    wrelayout_kernel<<<256, 256, 43008>>>(pc_w);
    im2col_kernel<<<BATCH, 256>>>();
    conv1gemm_kernel<<<1600, 256, C1_SMEM>>>(conv1_b);
    pcgemm_kernel<<<288, 256, PCG_SMEM>>>(pc_b);
    squash_h_kernel<<<BATCH, 256>>>();
    uhat_kernel<<<dim3(1152, 2), 256>>>(W);
    routing0_kernel<<<BATCH, 160>>>();
    routing_iter_kernel<1, 0><<<BATCH, 256>>>();
    routing_iter_kernel<0, 1><<<BATCH, 256>>>();
    gemm_kernel<0, 0><<<dim3(8, 8), 256>>>(fc1_w, fc1_b, labels, out, 512, 512, 160);
    gemm_kernel<0, 1><<<dim3(16, 8), 256>>>(fc2_w, fc2_b, nullptr, out, 512, 1024, 512);
    gemm_kernel<1, 2><<<dim3(13, 8), 256>>>(fc3_w, fc3_b, nullptr, out + 5120, 512, 784, 1024);
    probs_kernel<<<4, 128>>>(out);
}

// round 13
// speedup vs baseline: 1.4422x; 1.0717x over previous
#include <cuda_runtime.h>
#include <cuda_bf16.h>
#include <cuda_fp16.h>
#include <cstdint>
#include <math.h>

// ---------------------------------------------------------------------------
// CapsNet forward. B=512.
//   x -> fp16; conv1 as fp16 mma.sync GEMM (im2col K=81 pad 128) -> g_cl
//   pcconv: fp16 mma.sync implicit GEMM (cp.async 2-stage, M=64 N=256, 2 CTA/SM)
//   squash -> hT; u_hat (fp16, grid split); routing FUSED (one block/image,
//   vsum identity, u_hat L2-resident across the 5 passes); decoder FCs
//   (mask fused into fc1); probs
// Output: [probs (512*10)] then [dec (512*784)]
// ---------------------------------------------------------------------------

#define BATCH 512

__device__ __half g_x16[BATCH * 784];             // input fp16
__device__ __half g_i2c[BATCH * 400 * 128];       // conv1 im2col [npos][128]
__device__ __half g_wr1[256 * 128];               // conv1 w [oc][tap pad 128]
__device__ __half g_cl[BATCH * 400 * 256];        // conv1 out, channel-last fp16
__device__ __half g_wr[256 * 81 * 256];           // pc weights [oc][tap][ic] fp16
__device__ float g_pc[BATCH * 256 * 36];
__device__ float g_hT[BATCH * 1152 * 8];
__device__ __half g_uhat[BATCH * 1152 * 160];     // fp16 storage
__device__ float g_v[BATCH * 160];
__device__ float g_fc1[BATCH * 512];
__device__ float g_fc2[BATCH * 1024];

// ---------------- helpers ---------------------------------------------------
__device__ __forceinline__ uint32_t smem_u32(const void* p) {
    uint32_t a;
    asm("{ .reg .u64 t; cvta.to.shared.u64 t, %1; cvt.u32.u64 %0, t; }"
        : "=r"(a) : "l"(p));
    return a;
}
__device__ __forceinline__ void ldsm_x4(uint32_t& d0, uint32_t& d1,
                                        uint32_t& d2, uint32_t& d3,
                                        uint32_t addr) {
    asm volatile("ldmatrix.sync.aligned.m8n8.x4.shared.b16 {%0,%1,%2,%3}, [%4];"
                 : "=r"(d0), "=r"(d1), "=r"(d2), "=r"(d3) : "r"(addr));
}
__device__ __forceinline__ void mma16816h(float* c, const uint32_t* a,
                                          const uint32_t* b) {
    asm volatile(
        "mma.sync.aligned.m16n8k16.row.col.f32.f16.f16.f32 "
        "{%0,%1,%2,%3}, {%4,%5,%6,%7}, {%8,%9}, {%0,%1,%2,%3};"
        : "+f"(c[0]), "+f"(c[1]), "+f"(c[2]), "+f"(c[3])
        : "r"(a[0]), "r"(a[1]), "r"(a[2]), "r"(a[3]), "r"(b[0]), "r"(b[1]));
}
#define CP16(dst, src) \
    asm volatile("cp.async.cg.shared.global [%0], [%1], 16;" \
                 :: "r"(dst), "l"(src) : "memory")
#define CP_COMMIT() asm volatile("cp.async.commit_group;" ::: "memory")
#define CP_WAIT1() asm volatile("cp.async.wait_group 1;" ::: "memory")
#define CP_WAIT0() asm volatile("cp.async.wait_group 0;" ::: "memory")

// ---------------------------------------------------------------------------
// x -> fp16. grid 392, block 256.
// ---------------------------------------------------------------------------
__global__ void xcvt_kernel(const float* __restrict__ x)
{
    int i = blockIdx.x * 1024 + threadIdx.x * 4;
    float4 v = *(const float4*)(x + i);
    *(__half2*)(g_x16 + i) = __floats2half2_rn(v.x, v.y);
    *(__half2*)(g_x16 + i + 2) = __floats2half2_rn(v.z, v.w);
}

// ---------------------------------------------------------------------------
// conv1 weights -> fp16 [oc][tap pad 128]. grid 256, block 128.
// ---------------------------------------------------------------------------
__global__ void wr1_kernel(const float* __restrict__ w)
{
    int oc = blockIdx.x;
    int t = threadIdx.x;
    g_wr1[oc * 128 + t] = (t < 81) ? __float2half(w[oc * 81 + t])
                                   : __float2half(0.f);
}

// ---------------------------------------------------------------------------
// im2col: g_x16 -> g_i2c [npos][tap pad 128]. grid 512, block 256.
// ---------------------------------------------------------------------------
__global__ __launch_bounds__(256) void im2col_kernel()
{
    __shared__ __half s_img[784];
    __shared__ int s_off[128];
    int b = blockIdx.x;
    int tid = threadIdx.x;

    if (tid < 98)
        ((uint4*)s_img)[tid] = ((const uint4*)(g_x16 + b * 784))[tid];
    if (tid < 128)
        s_off[tid] = (tid < 81) ? (tid / 9) * 28 + (tid % 9) : -1;
    __syncthreads();

    for (int it = tid; it < 6400; it += 256) {
        int row = it >> 4;
        int q = it & 15;
        int oy = row / 20;
        int ox = row - oy * 20;
        int base = oy * 28 + ox;
        union { __half h[8]; uint4 u; } val;
        #pragma unroll
        for (int j = 0; j < 8; j++) {
            int off = s_off[q * 8 + j];
            val.h[j] = (off >= 0) ? s_img[base + off] : __float2half(0.f);
        }
        *(uint4*)(g_i2c + (size_t)b * 51200 + row * 128 + q * 8) = val.u;
    }
}

// ---------------------------------------------------------------------------
// conv1 GEMM: C[204800,256] = relu(i2c @ W1^T + bias) -> g_cl fp16.
// grid 1600, block 256.
// ---------------------------------------------------------------------------
#define C1_A0 0
#define C1_A1 16384
#define C1_B0 32768
#define C1_B1 65536
#define C1_SMEM 98304

__global__ __launch_bounds__(256, 1) void conv1gemm_kernel(
    const float* __restrict__ bias)
{
    extern __shared__ char sm[];
    int tid = threadIdx.x;
    int wid = tid >> 5;
    int lane = tid & 31;
    int warp_m = wid & 3;
    int warp_n = wid >> 2;
    int m0 = blockIdx.x * 128;
    uint32_t smb = smem_u32(sm);

    int r0 = tid >> 3;
    int c = tid & 7;
    uint32_t dbase = (uint32_t)(r0 * 128) + (uint32_t)((c * 16) ^ ((r0 & 7) << 4));

    #pragma unroll
    for (int kc2 = 0; kc2 < 2; kc2++) {
        uint32_t abase = smb + (kc2 ? C1_A1 : C1_A0);
        uint32_t bbase = smb + (kc2 ? C1_B1 : C1_B0);
        #pragma unroll
        for (int i = 0; i < 4; i++)
            CP16(abase + dbase + i * 4096,
                 g_i2c + (size_t)(m0 + r0 + 32 * i) * 128 + kc2 * 64 + c * 8);
        #pragma unroll
        for (int t = 0; t < 8; t++)
            CP16(bbase + dbase + t * 4096,
                 g_wr1 + (r0 + 32 * t) * 128 + kc2 * 64 + c * 8);
    }
    CP_COMMIT();
    CP_WAIT0();
    __syncthreads();

    float acc[2][16][4];
    #pragma unroll
    for (int i = 0; i < 2; i++)
        #pragma unroll
        for (int j = 0; j < 16; j++)
            #pragma unroll
            for (int k = 0; k < 4; k++) acc[i][j][k] = 0.f;

    uint32_t swz = (uint32_t)(lane & 7) << 4;
    uint32_t a_row_off = (uint32_t)(warp_m * 32 + (lane & 15)) * 128;
    uint32_t akb = (uint32_t)(lane >> 4) << 4;
    uint32_t b_row_off =
        (uint32_t)(warp_n * 128 + (lane & 7) + ((lane >> 4) & 1) * 8) * 128;
    uint32_t bkb = (uint32_t)((lane >> 3) & 1) << 4;

    #pragma unroll
    for (int kc2 = 0; kc2 < 2; kc2++) {
        uint32_t a_row = smb + (kc2 ? C1_A1 : C1_A0) + a_row_off;
        uint32_t b_row = smb + (kc2 ? C1_B1 : C1_B0) + b_row_off;
        #pragma unroll
        for (int j = 0; j < 4; j++) {
            uint32_t ka = ((uint32_t)(j * 32) + akb) ^ swz;
            uint32_t ah[8];
            ldsm_x4(ah[0], ah[1], ah[2], ah[3], a_row + ka);
            ldsm_x4(ah[4], ah[5], ah[6], ah[7], a_row + 2048 + ka);
            uint32_t kb = ((uint32_t)(j * 32) + bkb) ^ swz;
            #pragma unroll
            for (int h = 0; h < 2; h++) {
                uint32_t bh[16];
                #pragma unroll
                for (int q = 0; q < 4; q++) {
                    uint32_t bt = b_row + (uint32_t)((h * 4 + q) * 2048) + kb;
                    ldsm_x4(bh[4 * q], bh[4 * q + 1], bh[4 * q + 2], bh[4 * q + 3], bt);
                }
                #pragma unroll
                for (int q = 0; q < 4; q++) {
                    #pragma unroll
                    for (int sub = 0; sub < 2; sub++) {
                        int nn = h * 8 + q * 2 + sub;
                        #pragma unroll
                        for (int tm = 0; tm < 2; tm++)
                            mma16816h(acc[tm][nn], &ah[4 * tm], &bh[4 * q + 2 * sub]);
                    }
                }
            }
        }
    }

    int r_in8 = lane >> 2;
    int c_in8 = (lane & 3) * 2;
    #pragma unroll
    for (int tm = 0; tm < 2; tm++) {
        size_t row0 = (size_t)(m0 + warp_m * 32 + tm * 16 + r_in8);
        size_t row1 = row0 + 8;
        #pragma unroll
        for (int nn = 0; nn < 16; nn++) {
            int col = warp_n * 128 + nn * 8 + c_in8;
            float bv0 = __ldg(bias + col);
            float bv1 = __ldg(bias + col + 1);
            const float* cc2 = acc[tm][nn];
            ((__half2*)g_cl)[(row0 * 256 + col) >> 1] =
                __floats2half2_rn(fmaxf(cc2[0] + bv0, 0.f), fmaxf(cc2[1] + bv1, 0.f));
            ((__half2*)g_cl)[(row1 * 256 + col) >> 1] =
                __floats2half2_rn(fmaxf(cc2[2] + bv0, 0.f), fmaxf(cc2[3] + bv1, 0.f));
        }
    }
}

// ---------------------------------------------------------------------------
// weight relayout: pc_w [oc][ic][81] -> g_wr [oc][tap][ic] fp16.
// ---------------------------------------------------------------------------
__global__ __launch_bounds__(256) void wrelayout_kernel(const float* __restrict__ w)
{
    extern __shared__ char wsm[];
    __half* sh = (__half*)wsm;
    int oc = blockIdx.x;
    int tid = threadIdx.x;
    const float* src = w + (size_t)oc * 20736;

    for (int j = tid; j < 20736; j += 256) {
        int ic = j / 81;
        int e = j - ic * 81;
        sh[e * 256 + ic] = __float2half(src[j]);
    }
    __syncthreads();

    uint4* dh = (uint4*)(g_wr + (size_t)oc * 20736);
    const uint4* s4 = (const uint4*)sh;
    for (int j = tid; j < 2592; j += 256) dh[j] = s4[j];
}

// ---------------------------------------------------------------------------
// pcconv: fp16 implicit GEMM, cp.async 2-stage, M=64 x N=256, 2 CTAs/SM.
// grid 288, block 256. (best measured config, unchanged.)
// ---------------------------------------------------------------------------
#define SM_A 0
#define SM_B 8192
#define STAGE 40960
#define PCG_SMEM (2 * STAGE)

__global__ __launch_bounds__(256, 2) void pcgemm_kernel(const float* __restrict__ bias)
{
    extern __shared__ char sm[];
    __shared__ int s_rowbase[64];

    int tid = threadIdx.x;
    int wid = tid >> 5;
    int lane = tid & 31;
    int warp_m = wid & 1;
    int warp_n = wid >> 1;
    int m0 = blockIdx.x * 64;
    uint32_t smb = smem_u32(sm);

    if (tid < 64) {
        int npos = m0 + tid;
        int b = npos / 36;
        int pos = npos - b * 36;
        int y = pos / 6;
        int xq = pos - y * 6;
        s_rowbase[tid] = ((b * 20 + 2 * y) * 20 + 2 * xq) * 256;
    }
    __syncthreads();

    int r0 = tid >> 3;
    int c = tid & 7;
    uint32_t dbase = (uint32_t)(r0 * 128) + (uint32_t)((c * 16) ^ ((r0 & 7) << 4));
    int rb0 = s_rowbase[r0];
    int rb1 = s_rowbase[r0 + 32];
    int bbase0 = r0 * 20736;

#define PCG_ISSUE(K) do { \
    int _kykx = (K) >> 2; \
    int _ic0 = ((K) & 3) << 6; \
    int _ky = _kykx / 9; \
    int _kx = _kykx - _ky * 9; \
    int _asrc = (_ky * 20 + _kx) * 256 + _ic0 + c * 8; \
    int _bsrc = _kykx * 256 + _ic0 + c * 8; \
    uint32_t _st = smb + ((K) & 1) * STAGE; \
    CP16(_st + SM_A + dbase, g_cl + rb0 + _asrc); \
    CP16(_st + SM_A + dbase + 4096, g_cl + rb1 + _asrc); \
    _Pragma("unroll") \
    for (int _t = 0; _t < 8; _t++) \
        CP16(_st + SM_B + dbase + _t * 4096, g_wr + bbase0 + _t * 663552 + _bsrc); \
} while (0)

    float acc[2][8][4];
    #pragma unroll
    for (int i = 0; i < 2; i++)
        #pragma unroll
        for (int j = 0; j < 8; j++)
            #pragma unroll
            for (int k = 0; k < 4; k++) acc[i][j][k] = 0.f;

    uint32_t swz = (uint32_t)(lane & 7) << 4;
    uint32_t a_row_off = SM_A + (uint32_t)(warp_m * 32 + (lane & 15)) * 128;
    uint32_t akb = (uint32_t)(lane >> 4) << 4;
    uint32_t b_row_off = SM_B +
        (uint32_t)(warp_n * 64 + (lane & 7) + ((lane >> 4) & 1) * 8) * 128;
    uint32_t bkb = (uint32_t)((lane >> 3) & 1) << 4;

    PCG_ISSUE(0);
    CP_COMMIT();

    for (int kc = 0; kc < 324; kc++) {
        if (kc < 323) {
            PCG_ISSUE(kc + 1);
            CP_COMMIT();
            CP_WAIT1();
        } else {
            CP_WAIT0();
        }
        __syncthreads();

        uint32_t st = smb + (kc & 1) * STAGE;
        uint32_t a_row = st + a_row_off;
        uint32_t b_row = st + b_row_off;
        #pragma unroll
        for (int j = 0; j < 4; j++) {
            uint32_t ka = ((uint32_t)(j * 32) + akb) ^ swz;
            uint32_t ah[8];
            ldsm_x4(ah[0], ah[1], ah[2], ah[3], a_row + ka);
            ldsm_x4(ah[4], ah[5], ah[6], ah[7], a_row + 2048 + ka);
            uint32_t kb = ((uint32_t)(j * 32) + bkb) ^ swz;
            uint32_t bh[16];
            #pragma unroll
            for (int q = 0; q < 4; q++) {
                uint32_t bt = b_row + (uint32_t)(q * 2048) + kb;
                ldsm_x4(bh[4 * q], bh[4 * q + 1], bh[4 * q + 2], bh[4 * q + 3], bt);
            }
            #pragma unroll
            for (int q = 0; q < 4; q++) {
                #pragma unroll
                for (int sub = 0; sub < 2; sub++) {
                    int nn = q * 2 + sub;
                    #pragma unroll
                    for (int tm = 0; tm < 2; tm++)
                        mma16816h(acc[tm][nn], &ah[4 * tm], &bh[4 * q + 2 * sub]);
                }
            }
        }
        __syncthreads();
    }

    int r_in8 = lane >> 2;
    int c_in8 = (lane & 3) * 2;
    #pragma unroll
    for (int tm = 0; tm < 2; tm++) {
        int row0 = m0 + warp_m * 32 + tm * 16 + r_in8;
        int b0i = row0 / 36, p0i = row0 - b0i * 36;
        int row1 = row0 + 8;
        int b1i = row1 / 36, p1i = row1 - b1i * 36;
        #pragma unroll
        for (int nn = 0; nn < 8; nn++) {
            int col = warp_n * 64 + nn * 8 + c_in8;
            float bv0 = __ldg(bias + col);
            float bv1 = __ldg(bias + col + 1);
            const float* cc2 = acc[tm][nn];
            g_pc[b0i * 9216 + col * 36 + p0i] = cc2[0] + bv0;
            g_pc[b0i * 9216 + (col + 1) * 36 + p0i] = cc2[1] + bv1;
            g_pc[b1i * 9216 + col * 36 + p1i] = cc2[2] + bv0;
            g_pc[b1i * 9216 + (col + 1) * 36 + p1i] = cc2[3] + bv1;
        }
    }
}

// ---------------------------------------------------------------------------
// squash + transpose to hT. grid 512, block 256.
// ---------------------------------------------------------------------------
__global__ __launch_bounds__(256) void squash_h_kernel()
{
    int b = blockIdx.x;
    int tid = threadIdx.x;
    __shared__ float s_scale[8];
    __shared__ float s_val[9216];
    int g = tid >> 5;
    int lane = tid & 31;
    const float* pb = g_pc + (size_t)b * 9216;

    float ss = 0.f;
    for (int j = lane; j < 1152; j += 32) {
        float v = pb[g * 1152 + j];
        ss += v * v;
    }
    #pragma unroll
    for (int o = 16; o; o >>= 1) ss += __shfl_xor_sync(0xffffffffu, ss, o);
    if (lane == 0) s_scale[g] = sqrtf(ss) / (1.f + ss);
    __syncthreads();

    for (int idx = tid; idx < 9216; idx += 256) {
        int cch = idx / 36;
        s_val[idx] = pb[idx] * s_scale[cch >> 5];
    }
    __syncthreads();

    float* outb = g_hT + (size_t)b * 9216;
    for (int o = tid; o < 9216; o += 256) {
        int pos = o >> 3;
        int g2 = o & 7;
        int cch = g2 * 32 + pos / 36;
        int s = pos % 36;
        outb[o] = s_val[cch * 36 + s];
    }
}

// ---------------------------------------------------------------------------
// u_hat (fp16 out): grid (1152, 2), block 256; each block does 256 images.
// ---------------------------------------------------------------------------
__global__ __launch_bounds__(256) void uhat_kernel(const float* __restrict__ W)
{
    int i = blockIdx.x;
    int bh = blockIdx.y * 256;
    __shared__ float sW[1280];
    __shared__ float sh[32 * 8];
    int tid = threadIdx.x;
    for (int j = tid; j < 1280; j += 256)
        sW[(j & 7) * 160 + (j >> 3)] = W[(size_t)i * 1280 + j];

    for (int b0 = bh; b0 < bh + 256; b0 += 32) {
        __syncthreads();
        sh[tid] = g_hT[((size_t)(b0 + (tid >> 3)) * 1152 + i) * 8 + (tid & 7)];
        __syncthreads();
        if (tid < 160) {
            #pragma unroll 4
            for (int bb = 0; bb < 32; bb++) {
                float u = 0.f;
                #pragma unroll
                for (int e = 0; e < 8; e++) u += sW[e * 160 + tid] * sh[bb * 8 + e];
                g_uhat[((size_t)(b0 + bb) * 1152 + i) * 160 + tid] = __float2half(u);
            }
        }
    }
}

// ---------------------------------------------------------------------------
// FUSED routing: one block per image; r0 + iter1 + iter2 in one kernel.
// vsum identity: logits_r = u . (v0 + ... + v_{r-1}); no blog storage.
// u_b (368 KB) is re-read 4x after the cold pass -> L2 hits at <=2 blocks/SM.
// smem: c_s 46080B + v/vsum/s 1920B = 48000B -> 2 blocks/SM.
// ---------------------------------------------------------------------------
__global__ __launch_bounds__(256, 2) void routing_fused_kernel()
{
    __shared__ float c_s[11520];
    __shared__ float vsum_s[160];
    __shared__ float s_s[160];

    int b = blockIdx.x;
    int t = threadIdx.x;
    const __half* ub = g_uhat + (size_t)b * 184320;

    // ---- r0: s = 0.1 * sum_i u ; v0 = squash(s); vsum = v0
    if (t < 160) {
        float s0 = 0.f, s1 = 0.f, s2 = 0.f, s3 = 0.f;
        for (int i = 0; i < 1152; i += 4) {
            s0 += __half2float(__ldg(ub + (i + 0) * 160 + t));
            s1 += __half2float(__ldg(ub + (i + 1) * 160 + t));
            s2 += __half2float(__ldg(ub + (i + 2) * 160 + t));
            s3 += __half2float(__ldg(ub + (i + 3) * 160 + t));
        }
        s_s[t] = 0.1f * ((s0 + s1) + (s2 + s3));
    }
    __syncthreads();
    if (t < 160) {
        int k = t >> 4;
        float n2 = 0.f;
        #pragma unroll
        for (int d = 0; d < 16; d++) {
            float v = s_s[k * 16 + d];
            n2 += v * v;
        }
        vsum_s[t] = s_s[t] * (sqrtf(n2) / (1.f + n2));
    }
    __syncthreads();

    // ---- iters r = 1, 2
    #pragma unroll 1
    for (int r = 0; r < 2; r++) {
        // Phase A: logits = u . vsum (uint4 loads), softmax -> c_s
        for (int i = t; i < 1152; i += 256) {
            const uint4* u4 = (const uint4*)(ub + i * 160);
            float bl[10];
            float mx = -1e30f;
            #pragma unroll
            for (int k = 0; k < 10; k++) {
                uint4 ua = u4[2 * k];
                uint4 ubv = u4[2 * k + 1];
                const __half2* ha = (const __half2*)&ua;
                const __half2* hb = (const __half2*)&ubv;
                float dk = 0.f;
                #pragma unroll
                for (int j = 0; j < 4; j++) {
                    float2 f = __half22float2(ha[j]);
                    dk += f.x * vsum_s[k * 16 + 2 * j + 0];
                    dk += f.y * vsum_s[k * 16 + 2 * j + 1];
                }
                #pragma unroll
                for (int j = 0; j < 4; j++) {
                    float2 f = __half22float2(hb[j]);
                    dk += f.x * vsum_s[k * 16 + 8 + 2 * j + 0];
                    dk += f.y * vsum_s[k * 16 + 8 + 2 * j + 1];
                }
                bl[k] = dk;
                mx = fmaxf(mx, dk);
            }
            float sum = 0.f;
            #pragma unroll
            for (int k = 0; k < 10; k++) {
                float e = __expf(bl[k] - mx);
                bl[k] = e;
                sum += e;
            }
            float inv = 1.f / sum;
            #pragma unroll
            for (int k = 0; k < 10; k++) c_s[i * 10 + k] = bl[k] * inv;
        }
        __syncthreads();

        // Phase B: s = sum_i c*u ; v = squash(s); vsum += v
        float s = 0.f;
        if (t < 160) {
            int k = t >> 4;
            float p0 = 0.f, p1 = 0.f, p2 = 0.f, p3 = 0.f;
            #pragma unroll 2
            for (int i = 0; i < 1152; i += 4) {
                p0 += c_s[(i + 0) * 10 + k] * __half2float(__ldg(ub + (i + 0) * 160 + t));
                p1 += c_s[(i + 1) * 10 + k] * __half2float(__ldg(ub + (i + 1) * 160 + t));
                p2 += c_s[(i + 2) * 10 + k] * __half2float(__ldg(ub + (i + 2) * 160 + t));
                p3 += c_s[(i + 3) * 10 + k] * __half2float(__ldg(ub + (i + 3) * 160 + t));
            }
            s = (p0 + p1) + (p2 + p3);
        }
        __syncthreads();
        if (t < 160) s_s[t] = s;
        __syncthreads();
        if (t < 160) {
            int k = t >> 4;
            float n2 = 0.f;
            #pragma unroll
            for (int d = 0; d < 16; d++) {
                float v = s_s[k * 16 + d];
                n2 += v * v;
            }
            float v = s_s[t] * (sqrtf(n2) / (1.f + n2));
            if (r == 1) g_v[b * 160 + t] = v;       // final v
            else vsum_s[t] += v;                    // accumulate for iter2
        }
        __syncthreads();
    }
}

// ---------------------------------------------------------------------------
// GEMM: C[M,N] = act(A @ Wt^T + bias). SEL0 fuses mask (A = v * label).
// ---------------------------------------------------------------------------
template <int ACT, int SEL>
__global__ __launch_bounds__(256) void gemm_kernel(
    const float* __restrict__ Wt, const float* __restrict__ bias,
    const float* __restrict__ labels,
    float* __restrict__ outp, int M, int N, int K)
{
    const float* A = (SEL == 0) ? g_v : (SEL == 1) ? g_fc1 : g_fc2;
    float* C = (SEL == 0) ? g_fc1 : (SEL == 1) ? g_fc2 : outp;

    __shared__ float As[8][64];
    __shared__ float Bs[8][64];
    int n0 = blockIdx.x * 64;
    int m0 = blockIdx.y * 64;
    int tid = threadIdx.x;
    int tx = tid & 15;
    int ty = tid >> 4;

    float acc[4][4];
    #pragma unroll
    for (int i = 0; i < 4; i++)
        #pragma unroll
        for (int j = 0; j < 4; j++) acc[i][j] = 0.f;

    for (int k0 = 0; k0 < K; k0 += 8) {
        __syncthreads();
        #pragma unroll
        for (int l = 0; l < 2; l++) {
            int e = tid + l * 256;
            int r = e >> 3;
            int kk = e & 7;
            float a = A[(m0 + r) * K + k0 + kk];
            if (SEL == 0)
                a *= __ldg(labels + (m0 + r) * 10 + ((k0 + kk) >> 4));
            As[kk][r] = a;
            int n = n0 + r;
            Bs[kk][r] = (n < N) ? Wt[n * K + k0 + kk] : 0.f;
        }
        __syncthreads();
        #pragma unroll
        for (int kk = 0; kk < 8; kk++) {
            float4 a4 = *(const float4*)&As[kk][ty * 4];
            float4 b4 = *(const float4*)&Bs[kk][tx * 4];
            float a[4] = {a4.x, a4.y, a4.z, a4.w};
            float bb[4] = {b4.x, b4.y, b4.z, b4.w};
            #pragma unroll
            for (int i = 0; i < 4; i++)
                #pragma unroll
                for (int j = 0; j < 4; j++) acc[i][j] += a[i] * bb[j];
        }
    }

    #pragma unroll
    for (int i = 0; i < 4; i++) {
        int m = m0 + ty * 4 + i;
        #pragma unroll
        for (int j = 0; j < 4; j++) {
            int n = n0 + tx * 4 + j;
            if (n < N) {
                float v = acc[i][j] + bias[n];
                if (ACT == 0) v = fmaxf(v, 0.f);
                else v = 1.f / (1.f + __expf(-v));
                C[m * N + n] = v;
            }
        }
    }
}

// ---------------------------------------------------------------------------
__global__ void probs_kernel(float* __restrict__ out)
{
    int b = blockIdx.x * 128 + threadIdx.x;
    if (b < BATCH) {
        float nr[10];
        float mx = -1e30f;
        #pragma unroll
        for (int k = 0; k < 10; k++) {
            float n2 = 0.f;
            #pragma unroll
            for (int d = 0; d < 16; d++) {
                float v = g_v[b * 160 + k * 16 + d];
                n2 += v * v;
            }
            nr[k] = sqrtf(n2);
            mx = fmaxf(mx, nr[k]);
        }
        float sum = 0.f;
        #pragma unroll
        for (int k = 0; k < 10; k++) {
            nr[k] = __expf(nr[k] - mx);
            sum += nr[k];
        }
        float inv = 1.f / sum;
        #pragma unroll
        for (int k = 0; k < 10; k++) out[b * 10 + k] = nr[k] * inv;
    }
}

// ---------------------------------------------------------------------------
extern "C" void kernel_launch(void* const* d_in, const int* in_sizes, int n_in,
                              void* d_out, int out_size)
{
    const float* x       = (const float*)d_in[0];
    const float* labels  = (const float*)d_in[1];
    const float* conv1_w = (const float*)d_in[2];
    const float* conv1_b = (const float*)d_in[3];
    const float* pc_w    = (const float*)d_in[4];
    const float* pc_b    = (const float*)d_in[5];
    const float* W       = (const float*)d_in[6];
    const float* fc1_w   = (const float*)d_in[7];
    const float* fc1_b   = (const float*)d_in[8];
    const float* fc2_w   = (const float*)d_in[9];
    const float* fc2_b   = (const float*)d_in[10];
    const float* fc3_w   = (const float*)d_in[11];
    const float* fc3_b   = (const float*)d_in[12];
    float* out = (float*)d_out;

    cudaFuncSetAttribute(pcgemm_kernel,
                         cudaFuncAttributeMaxDynamicSharedMemorySize, PCG_SMEM);
    cudaFuncSetAttribute(conv1gemm_kernel,
                         cudaFuncAttributeMaxDynamicSharedMemorySize, C1_SMEM);
    cudaFuncSetAttribute(wrelayout_kernel,
                         cudaFuncAttributeMaxDynamicSharedMemorySize, 43008);

    xcvt_kernel<<<392, 256>>>(x);
    wr1_kernel<<<256, 128>>>(conv1_w);
    wrelayout_kernel<<<256, 256, 43008>>>(pc_w);
    im2col_kernel<<<BATCH, 256>>>();
    conv1gemm_kernel<<<1600, 256, C1_SMEM>>>(conv1_b);
    pcgemm_kernel<<<288, 256, PCG_SMEM>>>(pc_b);
    squash_h_kernel<<<BATCH, 256>>>();
    uhat_kernel<<<dim3(1152, 2), 256>>>(W);
    routing_fused_kernel<<<BATCH, 256>>>();
    gemm_kernel<0, 0><<<dim3(8, 8), 256>>>(fc1_w, fc1_b, labels, out, 512, 512, 160);
    gemm_kernel<0, 1><<<dim3(16, 8), 256>>>(fc2_w, fc2_b, nullptr, out, 512, 1024, 512);
    gemm_kernel<1, 2><<<dim3(13, 8), 256>>>(fc3_w, fc3_b, nullptr, out + 5120, 512, 784, 1024);
    probs_kernel<<<4, 128>>>(out);
}

// round 14
// speedup vs baseline: 1.4450x; 1.0019x over previous
#include <cuda_runtime.h>
#include <cuda_bf16.h>
#include <cuda_fp16.h>
#include <cstdint>
#include <math.h>

// ---------------------------------------------------------------------------
// CapsNet forward. B=512.
//   conv1 as fp16 mma.sync GEMM (im2col converts x inline) -> g_cl
//   pcconv: fp16 mma.sync implicit GEMM (cp.async 2-stage, M=64 N=256, 2 CTA/SM)
//           -> g_pc [b][pos][oc] (coalesced float2 epilogue)
//   squash -> hT; u_hat (fp16, 320-thread blocks); routing FUSED (1 blk/image,
//   vsum identity, L2-resident u_hat); decoder FCs (mask fused); probs
// Output: [probs (512*10)] then [dec (512*784)]
// ---------------------------------------------------------------------------

#define BATCH 512

__device__ __half g_i2c[BATCH * 400 * 128];       // conv1 im2col [npos][128]
__device__ __half g_wr1[256 * 128];               // conv1 w [oc][tap pad 128]
__device__ __half g_cl[BATCH * 400 * 256];        // conv1 out, channel-last fp16
__device__ __half g_wr[256 * 81 * 256];           // pc weights [oc][tap][ic] fp16
__device__ float g_pc[BATCH * 36 * 256];          // [b][pos][oc]
__device__ float g_hT[BATCH * 1152 * 8];
__device__ __half g_uhat[BATCH * 1152 * 160];     // fp16 storage
__device__ float g_v[BATCH * 160];
__device__ float g_fc1[BATCH * 512];
__device__ float g_fc2[BATCH * 1024];

// ---------------- helpers ---------------------------------------------------
__device__ __forceinline__ uint32_t smem_u32(const void* p) {
    uint32_t a;
    asm("{ .reg .u64 t; cvta.to.shared.u64 t, %1; cvt.u32.u64 %0, t; }"
        : "=r"(a) : "l"(p));
    return a;
}
__device__ __forceinline__ void ldsm_x4(uint32_t& d0, uint32_t& d1,
                                        uint32_t& d2, uint32_t& d3,
                                        uint32_t addr) {
    asm volatile("ldmatrix.sync.aligned.m8n8.x4.shared.b16 {%0,%1,%2,%3}, [%4];"
                 : "=r"(d0), "=r"(d1), "=r"(d2), "=r"(d3) : "r"(addr));
}
__device__ __forceinline__ void mma16816h(float* c, const uint32_t* a,
                                          const uint32_t* b) {
    asm volatile(
        "mma.sync.aligned.m16n8k16.row.col.f32.f16.f16.f32 "
        "{%0,%1,%2,%3}, {%4,%5,%6,%7}, {%8,%9}, {%0,%1,%2,%3};"
        : "+f"(c[0]), "+f"(c[1]), "+f"(c[2]), "+f"(c[3])
        : "r"(a[0]), "r"(a[1]), "r"(a[2]), "r"(a[3]), "r"(b[0]), "r"(b[1]));
}
#define CP16(dst, src) \
    asm volatile("cp.async.cg.shared.global [%0], [%1], 16;" \
                 :: "r"(dst), "l"(src) : "memory")
#define CP_COMMIT() asm volatile("cp.async.commit_group;" ::: "memory")
#define CP_WAIT1() asm volatile("cp.async.wait_group 1;" ::: "memory")
#define CP_WAIT0() asm volatile("cp.async.wait_group 0;" ::: "memory")

// ---------------------------------------------------------------------------
// conv1 weights -> fp16 [oc][tap pad 128]. grid 256, block 128.
// ---------------------------------------------------------------------------
__global__ void wr1_kernel(const float* __restrict__ w)
{
    int oc = blockIdx.x;
    int t = threadIdx.x;
    g_wr1[oc * 128 + t] = (t < 81) ? __float2half(w[oc * 81 + t])
                                   : __float2half(0.f);
}

// ---------------------------------------------------------------------------
// im2col (x fp32 read + convert inline): -> g_i2c [npos][tap pad 128].
// grid 512, block 256.
// ---------------------------------------------------------------------------
__global__ __launch_bounds__(256) void im2col_kernel(const float* __restrict__ x)
{
    __shared__ __half s_img[784];
    __shared__ int s_off[128];
    int b = blockIdx.x;
    int tid = threadIdx.x;

    for (int i = tid; i < 784; i += 256)
        s_img[i] = __float2half(x[b * 784 + i]);
    if (tid < 128)
        s_off[tid] = (tid < 81) ? (tid / 9) * 28 + (tid % 9) : -1;
    __syncthreads();

    for (int it = tid; it < 6400; it += 256) {
        int row = it >> 4;
        int q = it & 15;
        int oy = row / 20;
        int ox = row - oy * 20;
        int base = oy * 28 + ox;
        union { __half h[8]; uint4 u; } val;
        #pragma unroll
        for (int j = 0; j < 8; j++) {
            int off = s_off[q * 8 + j];
            val.h[j] = (off >= 0) ? s_img[base + off] : __float2half(0.f);
        }
        *(uint4*)(g_i2c + (size_t)b * 51200 + row * 128 + q * 8) = val.u;
    }
}

// ---------------------------------------------------------------------------
// conv1 GEMM: C[204800,256] = relu(i2c @ W1^T + bias) -> g_cl fp16.
// grid 1600, block 256.
// ---------------------------------------------------------------------------
#define C1_A0 0
#define C1_A1 16384
#define C1_B0 32768
#define C1_B1 65536
#define C1_SMEM 98304

__global__ __launch_bounds__(256, 1) void conv1gemm_kernel(
    const float* __restrict__ bias)
{
    extern __shared__ char sm[];
    int tid = threadIdx.x;
    int wid = tid >> 5;
    int lane = tid & 31;
    int warp_m = wid & 3;
    int warp_n = wid >> 2;
    int m0 = blockIdx.x * 128;
    uint32_t smb = smem_u32(sm);

    int r0 = tid >> 3;
    int c = tid & 7;
    uint32_t dbase = (uint32_t)(r0 * 128) + (uint32_t)((c * 16) ^ ((r0 & 7) << 4));

    #pragma unroll
    for (int kc2 = 0; kc2 < 2; kc2++) {
        uint32_t abase = smb + (kc2 ? C1_A1 : C1_A0);
        uint32_t bbase = smb + (kc2 ? C1_B1 : C1_B0);
        #pragma unroll
        for (int i = 0; i < 4; i++)
            CP16(abase + dbase + i * 4096,
                 g_i2c + (size_t)(m0 + r0 + 32 * i) * 128 + kc2 * 64 + c * 8);
        #pragma unroll
        for (int t = 0; t < 8; t++)
            CP16(bbase + dbase + t * 4096,
                 g_wr1 + (r0 + 32 * t) * 128 + kc2 * 64 + c * 8);
    }
    CP_COMMIT();
    CP_WAIT0();
    __syncthreads();

    float acc[2][16][4];
    #pragma unroll
    for (int i = 0; i < 2; i++)
        #pragma unroll
        for (int j = 0; j < 16; j++)
            #pragma unroll
            for (int k = 0; k < 4; k++) acc[i][j][k] = 0.f;

    uint32_t swz = (uint32_t)(lane & 7) << 4;
    uint32_t a_row_off = (uint32_t)(warp_m * 32 + (lane & 15)) * 128;
    uint32_t akb = (uint32_t)(lane >> 4) << 4;
    uint32_t b_row_off =
        (uint32_t)(warp_n * 128 + (lane & 7) + ((lane >> 4) & 1) * 8) * 128;
    uint32_t bkb = (uint32_t)((lane >> 3) & 1) << 4;

    #pragma unroll
    for (int kc2 = 0; kc2 < 2; kc2++) {
        uint32_t a_row = smb + (kc2 ? C1_A1 : C1_A0) + a_row_off;
        uint32_t b_row = smb + (kc2 ? C1_B1 : C1_B0) + b_row_off;
        #pragma unroll
        for (int j = 0; j < 4; j++) {
            uint32_t ka = ((uint32_t)(j * 32) + akb) ^ swz;
            uint32_t ah[8];
            ldsm_x4(ah[0], ah[1], ah[2], ah[3], a_row + ka);
            ldsm_x4(ah[4], ah[5], ah[6], ah[7], a_row + 2048 + ka);
            uint32_t kb = ((uint32_t)(j * 32) + bkb) ^ swz;
            #pragma unroll
            for (int h = 0; h < 2; h++) {
                uint32_t bh[16];
                #pragma unroll
                for (int q = 0; q < 4; q++) {
                    uint32_t bt = b_row + (uint32_t)((h * 4 + q) * 2048) + kb;
                    ldsm_x4(bh[4 * q], bh[4 * q + 1], bh[4 * q + 2], bh[4 * q + 3], bt);
                }
                #pragma unroll
                for (int q = 0; q < 4; q++) {
                    #pragma unroll
                    for (int sub = 0; sub < 2; sub++) {
                        int nn = h * 8 + q * 2 + sub;
                        #pragma unroll
                        for (int tm = 0; tm < 2; tm++)
                            mma16816h(acc[tm][nn], &ah[4 * tm], &bh[4 * q + 2 * sub]);
                    }
                }
            }
        }
    }

    int r_in8 = lane >> 2;
    int c_in8 = (lane & 3) * 2;
    #pragma unroll
    for (int tm = 0; tm < 2; tm++) {
        size_t row0 = (size_t)(m0 + warp_m * 32 + tm * 16 + r_in8);
        size_t row1 = row0 + 8;
        #pragma unroll
        for (int nn = 0; nn < 16; nn++) {
            int col = warp_n * 128 + nn * 8 + c_in8;
            float bv0 = __ldg(bias + col);
            float bv1 = __ldg(bias + col + 1);
            const float* cc2 = acc[tm][nn];
            ((__half2*)g_cl)[(row0 * 256 + col) >> 1] =
                __floats2half2_rn(fmaxf(cc2[0] + bv0, 0.f), fmaxf(cc2[1] + bv1, 0.f));
            ((__half2*)g_cl)[(row1 * 256 + col) >> 1] =
                __floats2half2_rn(fmaxf(cc2[2] + bv0, 0.f), fmaxf(cc2[3] + bv1, 0.f));
        }
    }
}

// ---------------------------------------------------------------------------
// weight relayout: pc_w [oc][ic][81] -> g_wr [oc][tap][ic] fp16.
// ---------------------------------------------------------------------------
__global__ __launch_bounds__(256) void wrelayout_kernel(const float* __restrict__ w)
{
    extern __shared__ char wsm[];
    __half* sh = (__half*)wsm;
    int oc = blockIdx.x;
    int tid = threadIdx.x;
    const float* src = w + (size_t)oc * 20736;

    for (int j = tid; j < 20736; j += 256) {
        int ic = j / 81;
        int e = j - ic * 81;
        sh[e * 256 + ic] = __float2half(src[j]);
    }
    __syncthreads();

    uint4* dh = (uint4*)(g_wr + (size_t)oc * 20736);
    const uint4* s4 = (const uint4*)sh;
    for (int j = tid; j < 2592; j += 256) dh[j] = s4[j];
}

// ---------------------------------------------------------------------------
// pcconv: fp16 implicit GEMM, cp.async 2-stage, M=64 x N=256, 2 CTAs/SM.
// grid 288, block 256. Epilogue -> g_pc [b][pos][oc] with float2 stores.
// ---------------------------------------------------------------------------
#define SM_A 0
#define SM_B 8192
#define STAGE 40960
#define PCG_SMEM (2 * STAGE)

__global__ __launch_bounds__(256, 2) void pcgemm_kernel(const float* __restrict__ bias)
{
    extern __shared__ char sm[];
    __shared__ int s_rowbase[64];

    int tid = threadIdx.x;
    int wid = tid >> 5;
    int lane = tid & 31;
    int warp_m = wid & 1;
    int warp_n = wid >> 1;
    int m0 = blockIdx.x * 64;
    uint32_t smb = smem_u32(sm);

    if (tid < 64) {
        int npos = m0 + tid;
        int b = npos / 36;
        int pos = npos - b * 36;
        int y = pos / 6;
        int xq = pos - y * 6;
        s_rowbase[tid] = ((b * 20 + 2 * y) * 20 + 2 * xq) * 256;
    }
    __syncthreads();

    int r0 = tid >> 3;
    int c = tid & 7;
    uint32_t dbase = (uint32_t)(r0 * 128) + (uint32_t)((c * 16) ^ ((r0 & 7) << 4));
    int rb0 = s_rowbase[r0];
    int rb1 = s_rowbase[r0 + 32];
    int bbase0 = r0 * 20736;

#define PCG_ISSUE(K) do { \
    int _kykx = (K) >> 2; \
    int _ic0 = ((K) & 3) << 6; \
    int _ky = _kykx / 9; \
    int _kx = _kykx - _ky * 9; \
    int _asrc = (_ky * 20 + _kx) * 256 + _ic0 + c * 8; \
    int _bsrc = _kykx * 256 + _ic0 + c * 8; \
    uint32_t _st = smb + ((K) & 1) * STAGE; \
    CP16(_st + SM_A + dbase, g_cl + rb0 + _asrc); \
    CP16(_st + SM_A + dbase + 4096, g_cl + rb1 + _asrc); \
    _Pragma("unroll") \
    for (int _t = 0; _t < 8; _t++) \
        CP16(_st + SM_B + dbase + _t * 4096, g_wr + bbase0 + _t * 663552 + _bsrc); \
} while (0)

    float acc[2][8][4];
    #pragma unroll
    for (int i = 0; i < 2; i++)
        #pragma unroll
        for (int j = 0; j < 8; j++)
            #pragma unroll
            for (int k = 0; k < 4; k++) acc[i][j][k] = 0.f;

    uint32_t swz = (uint32_t)(lane & 7) << 4;
    uint32_t a_row_off = SM_A + (uint32_t)(warp_m * 32 + (lane & 15)) * 128;
    uint32_t akb = (uint32_t)(lane >> 4) << 4;
    uint32_t b_row_off = SM_B +
        (uint32_t)(warp_n * 64 + (lane & 7) + ((lane >> 4) & 1) * 8) * 128;
    uint32_t bkb = (uint32_t)((lane >> 3) & 1) << 4;

    PCG_ISSUE(0);
    CP_COMMIT();

    for (int kc = 0; kc < 324; kc++) {
        if (kc < 323) {
            PCG_ISSUE(kc + 1);
            CP_COMMIT();
            CP_WAIT1();
        } else {
            CP_WAIT0();
        }
        __syncthreads();

        uint32_t st = smb + (kc & 1) * STAGE;
        uint32_t a_row = st + a_row_off;
        uint32_t b_row = st + b_row_off;
        #pragma unroll
        for (int j = 0; j < 4; j++) {
            uint32_t ka = ((uint32_t)(j * 32) + akb) ^ swz;
            uint32_t ah[8];
            ldsm_x4(ah[0], ah[1], ah[2], ah[3], a_row + ka);
            ldsm_x4(ah[4], ah[5], ah[6], ah[7], a_row + 2048 + ka);
            uint32_t kb = ((uint32_t)(j * 32) + bkb) ^ swz;
            uint32_t bh[16];
            #pragma unroll
            for (int q = 0; q < 4; q++) {
                uint32_t bt = b_row + (uint32_t)(q * 2048) + kb;
                ldsm_x4(bh[4 * q], bh[4 * q + 1], bh[4 * q + 2], bh[4 * q + 3], bt);
            }
            #pragma unroll
            for (int q = 0; q < 4; q++) {
                #pragma unroll
                for (int sub = 0; sub < 2; sub++) {
                    int nn = q * 2 + sub;
                    #pragma unroll
                    for (int tm = 0; tm < 2; tm++)
                        mma16816h(acc[tm][nn], &ah[4 * tm], &bh[4 * q + 2 * sub]);
                }
            }
        }
        __syncthreads();
    }

    // epilogue -> g_pc [b][pos][oc], float2 coalesced
    int r_in8 = lane >> 2;
    int c_in8 = (lane & 3) * 2;
    #pragma unroll
    for (int tm = 0; tm < 2; tm++) {
        int row0 = m0 + warp_m * 32 + tm * 16 + r_in8;
        int b0i = row0 / 36, p0i = row0 - b0i * 36;
        int row1 = row0 + 8;
        int b1i = row1 / 36, p1i = row1 - b1i * 36;
        #pragma unroll
        for (int nn = 0; nn < 8; nn++) {
            int col = warp_n * 64 + nn * 8 + c_in8;
            float bv0 = __ldg(bias + col);
            float bv1 = __ldg(bias + col + 1);
            const float* cc2 = acc[tm][nn];
            float2 st0;
            st0.x = cc2[0] + bv0;
            st0.y = cc2[1] + bv1;
            *(float2*)(g_pc + (size_t)b0i * 9216 + p0i * 256 + col) = st0;
            float2 st1;
            st1.x = cc2[2] + bv0;
            st1.y = cc2[3] + bv1;
            *(float2*)(g_pc + (size_t)b1i * 9216 + p1i * 256 + col) = st1;
        }
    }
}

// ---------------------------------------------------------------------------
// squash + transpose to hT. g_pc is [b][pos=36][oc=256]. grid 512, block 256.
// ---------------------------------------------------------------------------
__global__ __launch_bounds__(256) void squash_h_kernel()
{
    int b = blockIdx.x;
    int tid = threadIdx.x;
    __shared__ float s_scale[8];
    __shared__ float s_val[9216];   // old layout [c*36+s] for hT phase
    int g = tid >> 5;
    int lane = tid & 31;
    const float* pb = g_pc + (size_t)b * 9216;

    // group-g sum of squares: c = g*32+lane, over all 36 pos (coalesced)
    float ss = 0.f;
    int cbase = g * 32 + lane;
    for (int s = 0; s < 36; s++) {
        float v = pb[s * 256 + cbase];
        ss += v * v;
    }
    #pragma unroll
    for (int o = 16; o; o >>= 1) ss += __shfl_xor_sync(0xffffffffu, ss, o);
    if (lane == 0) s_scale[g] = sqrtf(ss) / (1.f + ss);
    __syncthreads();

    // fill s_val (old layout) from coalesced new-layout reads
    for (int idx2 = tid; idx2 < 9216; idx2 += 256) {
        int s = idx2 >> 8;
        int cch = idx2 & 255;
        s_val[cch * 36 + s] = pb[idx2] * s_scale[cch >> 5];
    }
    __syncthreads();

    float* outb = g_hT + (size_t)b * 9216;
    for (int o = tid; o < 9216; o += 256) {
        int pos = o >> 3;
        int g2 = o & 7;
        int cch = g2 * 32 + pos / 36;
        int s = pos % 36;
        outb[o] = s_val[cch * 36 + s];
    }
}

// ---------------------------------------------------------------------------
// u_hat (fp16 out): grid (1152, 2), block 320. Threads split (kd, bb-half):
// half = tid/160 (warp-aligned), 16 images each.
// ---------------------------------------------------------------------------
__global__ __launch_bounds__(320) void uhat_kernel(const float* __restrict__ W)
{
    int i = blockIdx.x;
    int bh = blockIdx.y * 256;
    __shared__ float sW[1280];
    __shared__ float sh[32 * 8];
    int tid = threadIdx.x;
    for (int j = tid; j < 1280; j += 320)
        sW[(j & 7) * 160 + (j >> 3)] = W[(size_t)i * 1280 + j];

    int half = tid / 160;          // 0 or 1 (warp-aligned: 160 = 5*32)
    int kd = tid - half * 160;

    for (int b0 = bh; b0 < bh + 256; b0 += 32) {
        __syncthreads();
        if (tid < 256)
            sh[tid] = g_hT[((size_t)(b0 + (tid >> 3)) * 1152 + i) * 8 + (tid & 7)];
        __syncthreads();
        int bb0 = half * 16;
        #pragma unroll 4
        for (int bb = bb0; bb < bb0 + 16; bb++) {
            float u = 0.f;
            #pragma unroll
            for (int e = 0; e < 8; e++) u += sW[e * 160 + kd] * sh[bb * 8 + e];
            g_uhat[((size_t)(b0 + bb) * 1152 + i) * 160 + kd] = __float2half(u);
        }
    }
}

// ---------------------------------------------------------------------------
// FUSED routing: one block per image; r0 + iter1 + iter2, vsum identity.
// ---------------------------------------------------------------------------
__global__ __launch_bounds__(256, 2) void routing_fused_kernel()
{
    __shared__ float c_s[11520];
    __shared__ float vsum_s[160];
    __shared__ float s_s[160];

    int b = blockIdx.x;
    int t = threadIdx.x;
    const __half* ub = g_uhat + (size_t)b * 184320;

    if (t < 160) {
        float s0 = 0.f, s1 = 0.f, s2 = 0.f, s3 = 0.f;
        for (int i = 0; i < 1152; i += 4) {
            s0 += __half2float(__ldg(ub + (i + 0) * 160 + t));
            s1 += __half2float(__ldg(ub + (i + 1) * 160 + t));
            s2 += __half2float(__ldg(ub + (i + 2) * 160 + t));
            s3 += __half2float(__ldg(ub + (i + 3) * 160 + t));
        }
        s_s[t] = 0.1f * ((s0 + s1) + (s2 + s3));
    }
    __syncthreads();
    if (t < 160) {
        int k = t >> 4;
        float n2 = 0.f;
        #pragma unroll
        for (int d = 0; d < 16; d++) {
            float v = s_s[k * 16 + d];
            n2 += v * v;
        }
        vsum_s[t] = s_s[t] * (sqrtf(n2) / (1.f + n2));
    }
    __syncthreads();

    #pragma unroll 1
    for (int r = 0; r < 2; r++) {
        for (int i = t; i < 1152; i += 256) {
            const uint4* u4 = (const uint4*)(ub + i * 160);
            float bl[10];
            float mx = -1e30f;
            #pragma unroll
            for (int k = 0; k < 10; k++) {
                uint4 ua = u4[2 * k];
                uint4 ubv = u4[2 * k + 1];
                const __half2* ha = (const __half2*)&ua;
                const __half2* hb = (const __half2*)&ubv;
                float dk = 0.f;
                #pragma unroll
                for (int j = 0; j < 4; j++) {
                    float2 f = __half22float2(ha[j]);
                    dk += f.x * vsum_s[k * 16 + 2 * j + 0];
                    dk += f.y * vsum_s[k * 16 + 2 * j + 1];
                }
                #pragma unroll
                for (int j = 0; j < 4; j++) {
                    float2 f = __half22float2(hb[j]);
                    dk += f.x * vsum_s[k * 16 + 8 + 2 * j + 0];
                    dk += f.y * vsum_s[k * 16 + 8 + 2 * j + 1];
                }
                bl[k] = dk;
                mx = fmaxf(mx, dk);
            }
            float sum = 0.f;
            #pragma unroll
            for (int k = 0; k < 10; k++) {
                float e = __expf(bl[k] - mx);
                bl[k] = e;
                sum += e;
            }
            float inv = 1.f / sum;
            #pragma unroll
            for (int k = 0; k < 10; k++) c_s[i * 10 + k] = bl[k] * inv;
        }
        __syncthreads();

        float s = 0.f;
        if (t < 160) {
            int k = t >> 4;
            float p0 = 0.f, p1 = 0.f, p2 = 0.f, p3 = 0.f;
            #pragma unroll 2
            for (int i = 0; i < 1152; i += 4) {
                p0 += c_s[(i + 0) * 10 + k] * __half2float(__ldg(ub + (i + 0) * 160 + t));
                p1 += c_s[(i + 1) * 10 + k] * __half2float(__ldg(ub + (i + 1) * 160 + t));
                p2 += c_s[(i + 2) * 10 + k] * __half2float(__ldg(ub + (i + 2) * 160 + t));
                p3 += c_s[(i + 3) * 10 + k] * __half2float(__ldg(ub + (i + 3) * 160 + t));
            }
            s = (p0 + p1) + (p2 + p3);
        }
        __syncthreads();
        if (t < 160) s_s[t] = s;
        __syncthreads();
        if (t < 160) {
            int k = t >> 4;
            float n2 = 0.f;
            #pragma unroll
            for (int d = 0; d < 16; d++) {
                float v = s_s[k * 16 + d];
                n2 += v * v;
            }
            float v = s_s[t] * (sqrtf(n2) / (1.f + n2));
            if (r == 1) g_v[b * 160 + t] = v;
            else vsum_s[t] += v;
        }
        __syncthreads();
    }
}

// ---------------------------------------------------------------------------
// GEMM: C[M,N] = act(A @ Wt^T + bias). SEL0 fuses mask (A = v * label).
// ---------------------------------------------------------------------------
template <int ACT, int SEL>
__global__ __launch_bounds__(256) void gemm_kernel(
    const float* __restrict__ Wt, const float* __restrict__ bias,
    const float* __restrict__ labels,
    float* __restrict__ outp, int M, int N, int K)
{
    const float* A = (SEL == 0) ? g_v : (SEL == 1) ? g_fc1 : g_fc2;
    float* C = (SEL == 0) ? g_fc1 : (SEL == 1) ? g_fc2 : outp;

    __shared__ float As[8][64];
    __shared__ float Bs[8][64];
    int n0 = blockIdx.x * 64;
    int m0 = blockIdx.y * 64;
    int tid = threadIdx.x;
    int tx = tid & 15;
    int ty = tid >> 4;

    float acc[4][4];
    #pragma unroll
    for (int i = 0; i < 4; i++)
        #pragma unroll
        for (int j = 0; j < 4; j++) acc[i][j] = 0.f;

    for (int k0 = 0; k0 < K; k0 += 8) {
        __syncthreads();
        #pragma unroll
        for (int l = 0; l < 2; l++) {
            int e = tid + l * 256;
            int r = e >> 3;
            int kk = e & 7;
            float a = A[(m0 + r) * K + k0 + kk];
            if (SEL == 0)
                a *= __ldg(labels + (m0 + r) * 10 + ((k0 + kk) >> 4));
            As[kk][r] = a;
            int n = n0 + r;
            Bs[kk][r] = (n < N) ? Wt[n * K + k0 + kk] : 0.f;
        }
        __syncthreads();
        #pragma unroll
        for (int kk = 0; kk < 8; kk++) {
            float4 a4 = *(const float4*)&As[kk][ty * 4];
            float4 b4 = *(const float4*)&Bs[kk][tx * 4];
            float a[4] = {a4.x, a4.y, a4.z, a4.w};
            float bb[4] = {b4.x, b4.y, b4.z, b4.w};
            #pragma unroll
            for (int i = 0; i < 4; i++)
                #pragma unroll
                for (int j = 0; j < 4; j++) acc[i][j] += a[i] * bb[j];
        }
    }

    #pragma unroll
    for (int i = 0; i < 4; i++) {
        int m = m0 + ty * 4 + i;
        #pragma unroll
        for (int j = 0; j < 4; j++) {
            int n = n0 + tx * 4 + j;
            if (n < N) {
                float v = acc[i][j] + bias[n];
                if (ACT == 0) v = fmaxf(v, 0.f);
                else v = 1.f / (1.f + __expf(-v));
                C[m * N + n] = v;
            }
        }
    }
}

// ---------------------------------------------------------------------------
__global__ void probs_kernel(float* __restrict__ out)
{
    int b = blockIdx.x * 128 + threadIdx.x;
    if (b < BATCH) {
        float nr[10];
        float mx = -1e30f;
        #pragma unroll
        for (int k = 0; k < 10; k++) {
            float n2 = 0.f;
            #pragma unroll
            for (int d = 0; d < 16; d++) {
                float v = g_v[b * 160 + k * 16 + d];
                n2 += v * v;
            }
            nr[k] = sqrtf(n2);
            mx = fmaxf(mx, nr[k]);
        }
        float sum = 0.f;
        #pragma unroll
        for (int k = 0; k < 10; k++) {
            nr[k] = __expf(nr[k] - mx);
            sum += nr[k];
        }
        float inv = 1.f / sum;
        #pragma unroll
        for (int k = 0; k < 10; k++) out[b * 10 + k] = nr[k] * inv;
    }
}

// ---------------------------------------------------------------------------
extern "C" void kernel_launch(void* const* d_in, const int* in_sizes, int n_in,
                              void* d_out, int out_size)
{
    const float* x       = (const float*)d_in[0];
    const float* labels  = (const float*)d_in[1];
    const float* conv1_w = (const float*)d_in[2];
    const float* conv1_b = (const float*)d_in[3];
    const float* pc_w    = (const float*)d_in[4];
    const float* pc_b    = (const float*)d_in[5];
    const float* W       = (const float*)d_in[6];
    const float* fc1_w   = (const float*)d_in[7];
    const float* fc1_b   = (const float*)d_in[8];
    const float* fc2_w   = (const float*)d_in[9];
    const float* fc2_b   = (const float*)d_in[10];
    const float* fc3_w   = (const float*)d_in[11];
    const float* fc3_b   = (const float*)d_in[12];
    float* out = (float*)d_out;

    cudaFuncSetAttribute(pcgemm_kernel,
                         cudaFuncAttributeMaxDynamicSharedMemorySize, PCG_SMEM);
    cudaFuncSetAttribute(conv1gemm_kernel,
                         cudaFuncAttributeMaxDynamicSharedMemorySize, C1_SMEM);
    cudaFuncSetAttribute(wrelayout_kernel,
                         cudaFuncAttributeMaxDynamicSharedMemorySize, 43008);

    wr1_kernel<<<256, 128>>>(conv1_w);
    wrelayout_kernel<<<256, 256, 43008>>>(pc_w);
    im2col_kernel<<<BATCH, 256>>>(x);
    conv1gemm_kernel<<<1600, 256, C1_SMEM>>>(conv1_b);
    pcgemm_kernel<<<288, 256, PCG_SMEM>>>(pc_b);
    squash_h_kernel<<<BATCH, 256>>>();
    uhat_kernel<<<dim3(1152, 2), 320>>>(W);
    routing_fused_kernel<<<BATCH, 256>>>();
    gemm_kernel<0, 0><<<dim3(8, 8), 256>>>(fc1_w, fc1_b, labels, out, 512, 512, 160);
    gemm_kernel<0, 1><<<dim3(16, 8), 256>>>(fc2_w, fc2_b, nullptr, out, 512, 1024, 512);
    gemm_kernel<1, 2><<<dim3(13, 8), 256>>>(fc3_w, fc3_b, nullptr, out + 5120, 512, 784, 1024);
    probs_kernel<<<4, 128>>>(out);
}

// round 16
// speedup vs baseline: 1.4550x; 1.0069x over previous
#include <cuda_runtime.h>
#include <cuda_bf16.h>
#include <cuda_fp16.h>
#include <cstdint>
#include <math.h>

// ---------------------------------------------------------------------------
// CapsNet forward. B=512.
//   conv1 as fp16 mma.sync GEMM (im2col; M=64 N=256 tiles, 2 CTA/SM) -> g_cl
//   pcconv: fp16 mma.sync implicit GEMM (cp.async 2-stage, M=64 N=256, 2 CTA/SM)
//           -> g_pc [b][pos][oc]
//   squash -> hT; u_hat (fp16, 320-thr); routing FUSED (vsum identity,
//   L2-resident u_hat); decoder FCs (mask fused); probs
// Output: [probs (512*10)] then [dec (512*784)]
// ---------------------------------------------------------------------------

#define BATCH 512

__device__ __half g_i2c[BATCH * 400 * 128];       // conv1 im2col [npos][128]
__device__ __half g_wr1[256 * 128];               // conv1 w [oc][tap pad 128]
__device__ __half g_cl[BATCH * 400 * 256];        // conv1 out, channel-last fp16
__device__ __half g_wr[256 * 81 * 256];           // pc weights [oc][tap][ic] fp16
__device__ float g_pc[BATCH * 36 * 256];          // [b][pos][oc]
__device__ float g_hT[BATCH * 1152 * 8];
__device__ __half g_uhat[BATCH * 1152 * 160];     // fp16 storage
__device__ float g_v[BATCH * 160];
__device__ float g_fc1[BATCH * 512];
__device__ float g_fc2[BATCH * 1024];

// ---------------- helpers ---------------------------------------------------
__device__ __forceinline__ uint32_t smem_u32(const void* p) {
    uint32_t a;
    asm("{ .reg .u64 t; cvta.to.shared.u64 t, %1; cvt.u32.u64 %0, t; }"
        : "=r"(a) : "l"(p));
    return a;
}
__device__ __forceinline__ void ldsm_x4(uint32_t& d0, uint32_t& d1,
                                        uint32_t& d2, uint32_t& d3,
                                        uint32_t addr) {
    asm volatile("ldmatrix.sync.aligned.m8n8.x4.shared.b16 {%0,%1,%2,%3}, [%4];"
                 : "=r"(d0), "=r"(d1), "=r"(d2), "=r"(d3) : "r"(addr));
}
__device__ __forceinline__ void mma16816h(float* c, const uint32_t* a,
                                          const uint32_t* b) {
    asm volatile(
        "mma.sync.aligned.m16n8k16.row.col.f32.f16.f16.f32 "
        "{%0,%1,%2,%3}, {%4,%5,%6,%7}, {%8,%9}, {%0,%1,%2,%3};"
        : "+f"(c[0]), "+f"(c[1]), "+f"(c[2]), "+f"(c[3])
        : "r"(a[0]), "r"(a[1]), "r"(a[2]), "r"(a[3]), "r"(b[0]), "r"(b[1]));
}
#define CP16(dst, src) \
    asm volatile("cp.async.cg.shared.global [%0], [%1], 16;" \
                 :: "r"(dst), "l"(src) : "memory")
#define CP_COMMIT() asm volatile("cp.async.commit_group;" ::: "memory")
#define CP_WAIT1() asm volatile("cp.async.wait_group 1;" ::: "memory")
#define CP_WAIT0() asm volatile("cp.async.wait_group 0;" ::: "memory")

// ---------------------------------------------------------------------------
// conv1 weights -> fp16 [oc][tap pad 128]. grid 256, block 128.
// ---------------------------------------------------------------------------
__global__ void wr1_kernel(const float* __restrict__ w)
{
    int oc = blockIdx.x;
    int t = threadIdx.x;
    g_wr1[oc * 128 + t] = (t < 81) ? __float2half(w[oc * 81 + t])
                                   : __float2half(0.f);
}

// ---------------------------------------------------------------------------
// im2col (x fp32 read + convert inline): -> g_i2c [npos][tap pad 128].
// grid 512, block 256.
// ---------------------------------------------------------------------------
__global__ __launch_bounds__(256) void im2col_kernel(const float* __restrict__ x)
{
    __shared__ __half s_img[784];
    __shared__ int s_off[128];
    int b = blockIdx.x;
    int tid = threadIdx.x;

    for (int i = tid; i < 784; i += 256)
        s_img[i] = __float2half(x[b * 784 + i]);
    if (tid < 128)
        s_off[tid] = (tid < 81) ? (tid / 9) * 28 + (tid % 9) : -1;
    __syncthreads();

    for (int it = tid; it < 6400; it += 256) {
        int row = it >> 4;
        int q = it & 15;
        int oy = row / 20;
        int ox = row - oy * 20;
        int base = oy * 28 + ox;
        union { __half h[8]; uint4 u; } val;
        #pragma unroll
        for (int j = 0; j < 8; j++) {
            int off = s_off[q * 8 + j];
            val.h[j] = (off >= 0) ? s_img[base + off] : __float2half(0.f);
        }
        *(uint4*)(g_i2c + (size_t)b * 51200 + row * 128 + q * 8) = val.u;
    }
}

// ---------------------------------------------------------------------------
// conv1 GEMM: C[204800,256] = relu(i2c @ W1^T + bias) -> g_cl fp16.
// M=64 x N=256 per CTA, 2 CTAs/SM, grid 3200. Warps 2(M) x 4(N).
// ---------------------------------------------------------------------------
#define C1_A0 0
#define C1_A1 8192
#define C1_B0 16384
#define C1_B1 49152
#define C1_SMEM 81920

__global__ __launch_bounds__(256, 2) void conv1gemm_kernel(
    const float* __restrict__ bias)
{
    extern __shared__ char sm[];
    int tid = threadIdx.x;
    int wid = tid >> 5;
    int lane = tid & 31;
    int warp_m = wid & 1;
    int warp_n = wid >> 1;
    int m0 = blockIdx.x * 64;
    uint32_t smb = smem_u32(sm);

    int r0 = tid >> 3;
    int c = tid & 7;
    uint32_t dbase = (uint32_t)(r0 * 128) + (uint32_t)((c * 16) ^ ((r0 & 7) << 4));

    #pragma unroll
    for (int kc2 = 0; kc2 < 2; kc2++) {
        uint32_t abase = smb + (kc2 ? C1_A1 : C1_A0);
        uint32_t bbase = smb + (kc2 ? C1_B1 : C1_B0);
        CP16(abase + dbase,
             g_i2c + (size_t)(m0 + r0) * 128 + kc2 * 64 + c * 8);
        CP16(abase + dbase + 4096,
             g_i2c + (size_t)(m0 + r0 + 32) * 128 + kc2 * 64 + c * 8);
        #pragma unroll
        for (int t = 0; t < 8; t++)
            CP16(bbase + dbase + t * 4096,
                 g_wr1 + (r0 + 32 * t) * 128 + kc2 * 64 + c * 8);
    }
    CP_COMMIT();
    CP_WAIT0();
    __syncthreads();

    float acc[2][8][4];
    #pragma unroll
    for (int i = 0; i < 2; i++)
        #pragma unroll
        for (int j = 0; j < 8; j++)
            #pragma unroll
            for (int k = 0; k < 4; k++) acc[i][j][k] = 0.f;

    uint32_t swz = (uint32_t)(lane & 7) << 4;
    uint32_t a_row_off = (uint32_t)(warp_m * 32 + (lane & 15)) * 128;
    uint32_t akb = (uint32_t)(lane >> 4) << 4;
    uint32_t b_row_off =
        (uint32_t)(warp_n * 64 + (lane & 7) + ((lane >> 4) & 1) * 8) * 128;
    uint32_t bkb = (uint32_t)((lane >> 3) & 1) << 4;

    #pragma unroll
    for (int kc2 = 0; kc2 < 2; kc2++) {
        uint32_t a_row = smb + (kc2 ? C1_A1 : C1_A0) + a_row_off;
        uint32_t b_row = smb + (kc2 ? C1_B1 : C1_B0) + b_row_off;
        #pragma unroll
        for (int j = 0; j < 4; j++) {
            uint32_t ka = ((uint32_t)(j * 32) + akb) ^ swz;
            uint32_t ah[8];
            ldsm_x4(ah[0], ah[1], ah[2], ah[3], a_row + ka);
            ldsm_x4(ah[4], ah[5], ah[6], ah[7], a_row + 2048 + ka);
            uint32_t kb = ((uint32_t)(j * 32) + bkb) ^ swz;
            uint32_t bh[16];
            #pragma unroll
            for (int q = 0; q < 4; q++) {
                uint32_t bt = b_row + (uint32_t)(q * 2048) + kb;
                ldsm_x4(bh[4 * q], bh[4 * q + 1], bh[4 * q + 2], bh[4 * q + 3], bt);
            }
            #pragma unroll
            for (int q = 0; q < 4; q++) {
                #pragma unroll
                for (int sub = 0; sub < 2; sub++) {
                    int nn = q * 2 + sub;
                    #pragma unroll
                    for (int tm = 0; tm < 2; tm++)
                        mma16816h(acc[tm][nn], &ah[4 * tm], &bh[4 * q + 2 * sub]);
                }
            }
        }
    }

    int r_in8 = lane >> 2;
    int c_in8 = (lane & 3) * 2;
    #pragma unroll
    for (int tm = 0; tm < 2; tm++) {
        size_t row0 = (size_t)(m0 + warp_m * 32 + tm * 16 + r_in8);
        size_t row1 = row0 + 8;
        #pragma unroll
        for (int nn = 0; nn < 8; nn++) {
            int col = warp_n * 64 + nn * 8 + c_in8;
            float bv0 = __ldg(bias + col);
            float bv1 = __ldg(bias + col + 1);
            const float* cc2 = acc[tm][nn];
            ((__half2*)g_cl)[(row0 * 256 + col) >> 1] =
                __floats2half2_rn(fmaxf(cc2[0] + bv0, 0.f), fmaxf(cc2[1] + bv1, 0.f));
            ((__half2*)g_cl)[(row1 * 256 + col) >> 1] =
                __floats2half2_rn(fmaxf(cc2[2] + bv0, 0.f), fmaxf(cc2[3] + bv1, 0.f));
        }
    }
}

// ---------------------------------------------------------------------------
// weight relayout: pc_w [oc][ic][81] -> g_wr [oc][tap][ic] fp16.
// ---------------------------------------------------------------------------
__global__ __launch_bounds__(256) void wrelayout_kernel(const float* __restrict__ w)
{
    extern __shared__ char wsm[];
    __half* sh = (__half*)wsm;
    int oc = blockIdx.x;
    int tid = threadIdx.x;
    const float* src = w + (size_t)oc * 20736;

    for (int j = tid; j < 20736; j += 256) {
        int ic = j / 81;
        int e = j - ic * 81;
        sh[e * 256 + ic] = __float2half(src[j]);
    }
    __syncthreads();

    uint4* dh = (uint4*)(g_wr + (size_t)oc * 20736);
    const uint4* s4 = (const uint4*)sh;
    for (int j = tid; j < 2592; j += 256) dh[j] = s4[j];
}

// ---------------------------------------------------------------------------
// pcconv: fp16 implicit GEMM, cp.async 2-stage, M=64 x N=256, 2 CTAs/SM.
// grid 288, block 256. (best measured config, unchanged.)
// ---------------------------------------------------------------------------
#define SM_A 0
#define SM_B 8192
#define STAGE 40960
#define PCG_SMEM (2 * STAGE)

__global__ __launch_bounds__(256, 2) void pcgemm_kernel(const float* __restrict__ bias)
{
    extern __shared__ char sm[];
    __shared__ int s_rowbase[64];

    int tid = threadIdx.x;
    int wid = tid >> 5;
    int lane = tid & 31;
    int warp_m = wid & 1;
    int warp_n = wid >> 1;
    int m0 = blockIdx.x * 64;
    uint32_t smb = smem_u32(sm);

    if (tid < 64) {
        int npos = m0 + tid;
        int b = npos / 36;
        int pos = npos - b * 36;
        int y = pos / 6;
        int xq = pos - y * 6;
        s_rowbase[tid] = ((b * 20 + 2 * y) * 20 + 2 * xq) * 256;
    }
    __syncthreads();

    int r0 = tid >> 3;
    int c = tid & 7;
    uint32_t dbase = (uint32_t)(r0 * 128) + (uint32_t)((c * 16) ^ ((r0 & 7) << 4));
    int rb0 = s_rowbase[r0];
    int rb1 = s_rowbase[r0 + 32];
    int bbase0 = r0 * 20736;

#define PCG_ISSUE(K) do { \
    int _kykx = (K) >> 2; \
    int _ic0 = ((K) & 3) << 6; \
    int _ky = _kykx / 9; \
    int _kx = _kykx - _ky * 9; \
    int _asrc = (_ky * 20 + _kx) * 256 + _ic0 + c * 8; \
    int _bsrc = _kykx * 256 + _ic0 + c * 8; \
    uint32_t _st = smb + ((K) & 1) * STAGE; \
    CP16(_st + SM_A + dbase, g_cl + rb0 + _asrc); \
    CP16(_st + SM_A + dbase + 4096, g_cl + rb1 + _asrc); \
    _Pragma("unroll") \
    for (int _t = 0; _t < 8; _t++) \
        CP16(_st + SM_B + dbase + _t * 4096, g_wr + bbase0 + _t * 663552 + _bsrc); \
} while (0)

    float acc[2][8][4];
    #pragma unroll
    for (int i = 0; i < 2; i++)
        #pragma unroll
        for (int j = 0; j < 8; j++)
            #pragma unroll
            for (int k = 0; k < 4; k++) acc[i][j][k] = 0.f;

    uint32_t swz = (uint32_t)(lane & 7) << 4;
    uint32_t a_row_off = SM_A + (uint32_t)(warp_m * 32 + (lane & 15)) * 128;
    uint32_t akb = (uint32_t)(lane >> 4) << 4;
    uint32_t b_row_off = SM_B +
        (uint32_t)(warp_n * 64 + (lane & 7) + ((lane >> 4) & 1) * 8) * 128;
    uint32_t bkb = (uint32_t)((lane >> 3) & 1) << 4;

    PCG_ISSUE(0);
    CP_COMMIT();

    for (int kc = 0; kc < 324; kc++) {
        if (kc < 323) {
            PCG_ISSUE(kc + 1);
            CP_COMMIT();
            CP_WAIT1();
        } else {
            CP_WAIT0();
        }
        __syncthreads();

        uint32_t st = smb + (kc & 1) * STAGE;
        uint32_t a_row = st + a_row_off;
        uint32_t b_row = st + b_row_off;
        #pragma unroll
        for (int j = 0; j < 4; j++) {
            uint32_t ka = ((uint32_t)(j * 32) + akb) ^ swz;
            uint32_t ah[8];
            ldsm_x4(ah[0], ah[1], ah[2], ah[3], a_row + ka);
            ldsm_x4(ah[4], ah[5], ah[6], ah[7], a_row + 2048 + ka);
            uint32_t kb = ((uint32_t)(j * 32) + bkb) ^ swz;
            uint32_t bh[16];
            #pragma unroll
            for (int q = 0; q < 4; q++) {
                uint32_t bt = b_row + (uint32_t)(q * 2048) + kb;
                ldsm_x4(bh[4 * q], bh[4 * q + 1], bh[4 * q + 2], bh[4 * q + 3], bt);
            }
            #pragma unroll
            for (int q = 0; q < 4; q++) {
                #pragma unroll
                for (int sub = 0; sub < 2; sub++) {
                    int nn = q * 2 + sub;
                    #pragma unroll
                    for (int tm = 0; tm < 2; tm++)
                        mma16816h(acc[tm][nn], &ah[4 * tm], &bh[4 * q + 2 * sub]);
                }
            }
        }
        __syncthreads();
    }

    // epilogue -> g_pc [b][pos][oc], float2 coalesced
    int r_in8 = lane >> 2;
    int c_in8 = (lane & 3) * 2;
    #pragma unroll
    for (int tm = 0; tm < 2; tm++) {
        int row0 = m0 + warp_m * 32 + tm * 16 + r_in8;
        int b0i = row0 / 36, p0i = row0 - b0i * 36;
        int row1 = row0 + 8;
        int b1i = row1 / 36, p1i = row1 - b1i * 36;
        #pragma unroll
        for (int nn = 0; nn < 8; nn++) {
            int col = warp_n * 64 + nn * 8 + c_in8;
            float bv0 = __ldg(bias + col);
            float bv1 = __ldg(bias + col + 1);
            const float* cc2 = acc[tm][nn];
            float2 st0;
            st0.x = cc2[0] + bv0;
            st0.y = cc2[1] + bv1;
            *(float2*)(g_pc + (size_t)b0i * 9216 + p0i * 256 + col) = st0;
            float2 st1;
            st1.x = cc2[2] + bv0;
            st1.y = cc2[3] + bv1;
            *(float2*)(g_pc + (size_t)b1i * 9216 + p1i * 256 + col) = st1;
        }
    }
}

// ---------------------------------------------------------------------------
// squash + transpose to hT. g_pc is [b][pos=36][oc=256]. grid 512, block 256.
// ---------------------------------------------------------------------------
__global__ __launch_bounds__(256) void squash_h_kernel()
{
    int b = blockIdx.x;
    int tid = threadIdx.x;
    __shared__ float s_scale[8];
    __shared__ float s_val[9216];
    int g = tid >> 5;
    int lane = tid & 31;
    const float* pb = g_pc + (size_t)b * 9216;

    float ss = 0.f;
    int cbase = g * 32 + lane;
    for (int s = 0; s < 36; s++) {
        float v = pb[s * 256 + cbase];
        ss += v * v;
    }
    #pragma unroll
    for (int o = 16; o; o >>= 1) ss += __shfl_xor_sync(0xffffffffu, ss, o);
    if (lane == 0) s_scale[g] = sqrtf(ss) / (1.f + ss);
    __syncthreads();

    for (int idx2 = tid; idx2 < 9216; idx2 += 256) {
        int s = idx2 >> 8;
        int cch = idx2 & 255;
        s_val[cch * 36 + s] = pb[idx2] * s_scale[cch >> 5];
    }
    __syncthreads();

    float* outb = g_hT + (size_t)b * 9216;
    for (int o = tid; o < 9216; o += 256) {
        int pos = o >> 3;
        int g2 = o & 7;
        int cch = g2 * 32 + pos / 36;
        int s = pos % 36;
        outb[o] = s_val[cch * 36 + s];
    }
}

// ---------------------------------------------------------------------------
// u_hat (fp16 out): grid (1152, 2), block 320.
// ---------------------------------------------------------------------------
__global__ __launch_bounds__(320) void uhat_kernel(const float* __restrict__ W)
{
    int i = blockIdx.x;
    int bh = blockIdx.y * 256;
    __shared__ float sW[1280];
    __shared__ float sh[32 * 8];
    int tid = threadIdx.x;
    for (int j = tid; j < 1280; j += 320)
        sW[(j & 7) * 160 + (j >> 3)] = W[(size_t)i * 1280 + j];

    int half = tid / 160;
    int kd = tid - half * 160;

    for (int b0 = bh; b0 < bh + 256; b0 += 32) {
        __syncthreads();
        if (tid < 256)
            sh[tid] = g_hT[((size_t)(b0 + (tid >> 3)) * 1152 + i) * 8 + (tid & 7)];
        __syncthreads();
        int bb0 = half * 16;
        #pragma unroll 4
        for (int bb = bb0; bb < bb0 + 16; bb++) {
            float u = 0.f;
            #pragma unroll
            for (int e = 0; e < 8; e++) u += sW[e * 160 + kd] * sh[bb * 8 + e];
            g_uhat[((size_t)(b0 + bb) * 1152 + i) * 160 + kd] = __float2half(u);
        }
    }
}

// ---------------------------------------------------------------------------
// FUSED routing: one block per image; r0 + iter1 + iter2, vsum identity.
// ---------------------------------------------------------------------------
__global__ __launch_bounds__(256, 2) void routing_fused_kernel()
{
    __shared__ float c_s[11520];
    __shared__ float vsum_s[160];
    __shared__ float s_s[160];

    int b = blockIdx.x;
    int t = threadIdx.x;
    const __half* ub = g_uhat + (size_t)b * 184320;

    if (t < 160) {
        float s0 = 0.f, s1 = 0.f, s2 = 0.f, s3 = 0.f;
        for (int i = 0; i < 1152; i += 4) {
            s0 += __half2float(__ldg(ub + (i + 0) * 160 + t));
            s1 += __half2float(__ldg(ub + (i + 1) * 160 + t));
            s2 += __half2float(__ldg(ub + (i + 2) * 160 + t));
            s3 += __half2float(__ldg(ub + (i + 3) * 160 + t));
        }
        s_s[t] = 0.1f * ((s0 + s1) + (s2 + s3));
    }
    __syncthreads();
    if (t < 160) {
        int k = t >> 4;
        float n2 = 0.f;
        #pragma unroll
        for (int d = 0; d < 16; d++) {
            float v = s_s[k * 16 + d];
            n2 += v * v;
        }
        vsum_s[t] = s_s[t] * (sqrtf(n2) / (1.f + n2));
    }
    __syncthreads();

    #pragma unroll 1
    for (int r = 0; r < 2; r++) {
        for (int i = t; i < 1152; i += 256) {
            const uint4* u4 = (const uint4*)(ub + i * 160);
            float bl[10];
            float mx = -1e30f;
            #pragma unroll
            for (int k = 0; k < 10; k++) {
                uint4 ua = u4[2 * k];
                uint4 ubv = u4[2 * k + 1];
                const __half2* ha = (const __half2*)&ua;
                const __half2* hb = (const __half2*)&ubv;
                float dk = 0.f;
                #pragma unroll
                for (int j = 0; j < 4; j++) {
                    float2 f = __half22float2(ha[j]);
                    dk += f.x * vsum_s[k * 16 + 2 * j + 0];
                    dk += f.y * vsum_s[k * 16 + 2 * j + 1];
                }
                #pragma unroll
                for (int j = 0; j < 4; j++) {
                    float2 f = __half22float2(hb[j]);
                    dk += f.x * vsum_s[k * 16 + 8 + 2 * j + 0];
                    dk += f.y * vsum_s[k * 16 + 8 + 2 * j + 1];
                }
                bl[k] = dk;
                mx = fmaxf(mx, dk);
            }
            float sum = 0.f;
            #pragma unroll
            for (int k = 0; k < 10; k++) {
                float e = __expf(bl[k] - mx);
                bl[k] = e;
                sum += e;
            }
            float inv = 1.f / sum;
            #pragma unroll
            for (int k = 0; k < 10; k++) c_s[i * 10 + k] = bl[k] * inv;
        }
        __syncthreads();

        float s = 0.f;
        if (t < 160) {
            int k = t >> 4;
            float p0 = 0.f, p1 = 0.f, p2 = 0.f, p3 = 0.f;
            #pragma unroll 2
            for (int i = 0; i < 1152; i += 4) {
                p0 += c_s[(i + 0) * 10 + k] * __half2float(__ldg(ub + (i + 0) * 160 + t));
                p1 += c_s[(i + 1) * 10 + k] * __half2float(__ldg(ub + (i + 1) * 160 + t));
                p2 += c_s[(i + 2) * 10 + k] * __half2float(__ldg(ub + (i + 2) * 160 + t));
                p3 += c_s[(i + 3) * 10 + k] * __half2float(__ldg(ub + (i + 3) * 160 + t));
            }
            s = (p0 + p1) + (p2 + p3);
        }
        __syncthreads();
        if (t < 160) s_s[t] = s;
        __syncthreads();
        if (t < 160) {
            int k = t >> 4;
            float n2 = 0.f;
            #pragma unroll
            for (int d = 0; d < 16; d++) {
                float v = s_s[k * 16 + d];
                n2 += v * v;
            }
            float v = s_s[t] * (sqrtf(n2) / (1.f + n2));
            if (r == 1) g_v[b * 160 + t] = v;
            else vsum_s[t] += v;
        }
        __syncthreads();
    }
}

// ---------------------------------------------------------------------------
// GEMM: C[M,N] = act(A @ Wt^T + bias). SEL0 fuses mask (A = v * label).
// ---------------------------------------------------------------------------
template <int ACT, int SEL>
__global__ __launch_bounds__(256) void gemm_kernel(
    const float* __restrict__ Wt, const float* __restrict__ bias,
    const float* __restrict__ labels,
    float* __restrict__ outp, int M, int N, int K)
{
    const float* A = (SEL == 0) ? g_v : (SEL == 1) ? g_fc1 : g_fc2;
    float* C = (SEL == 0) ? g_fc1 : (SEL == 1) ? g_fc2 : outp;

    __shared__ float As[8][64];
    __shared__ float Bs[8][64];
    int n0 = blockIdx.x * 64;
    int m0 = blockIdx.y * 64;
    int tid = threadIdx.x;
    int tx = tid & 15;
    int ty = tid >> 4;

    float acc[4][4];
    #pragma unroll
    for (int i = 0; i < 4; i++)
        #pragma unroll
        for (int j = 0; j < 4; j++) acc[i][j] = 0.f;

    for (int k0 = 0; k0 < K; k0 += 8) {
        __syncthreads();
        #pragma unroll
        for (int l = 0; l < 2; l++) {
            int e = tid + l * 256;
            int r = e >> 3;
            int kk = e & 7;
            float a = A[(m0 + r) * K + k0 + kk];
            if (SEL == 0)
                a *= __ldg(labels + (m0 + r) * 10 + ((k0 + kk) >> 4));
            As[kk][r] = a;
            int n = n0 + r;
            Bs[kk][r] = (n < N) ? Wt[n * K + k0 + kk] : 0.f;
        }
        __syncthreads();
        #pragma unroll
        for (int kk = 0; kk < 8; kk++) {
            float4 a4 = *(const float4*)&As[kk][ty * 4];
            float4 b4 = *(const float4*)&Bs[kk][tx * 4];
            float a[4] = {a4.x, a4.y, a4.z, a4.w};
            float bb[4] = {b4.x, b4.y, b4.z, b4.w};
            #pragma unroll
            for (int i = 0; i < 4; i++)
                #pragma unroll
                for (int j = 0; j < 4; j++) acc[i][j] += a[i] * bb[j];
        }
    }

    #pragma unroll
    for (int i = 0; i < 4; i++) {
        int m = m0 + ty * 4 + i;
        #pragma unroll
        for (int j = 0; j < 4; j++) {
            int n = n0 + tx * 4 + j;
            if (n < N) {
                float v = acc[i][j] + bias[n];
                if (ACT == 0) v = fmaxf(v, 0.f);
                else v = 1.f / (1.f + __expf(-v));
                C[m * N + n] = v;
            }
        }
    }
}

// ---------------------------------------------------------------------------
__global__ void probs_kernel(float* __restrict__ out)
{
    int b = blockIdx.x * 128 + threadIdx.x;
    if (b < BATCH) {
        float nr[10];
        float mx = -1e30f;
        #pragma unroll
        for (int k = 0; k < 10; k++) {
            float n2 = 0.f;
            #pragma unroll
            for (int d = 0; d < 16; d++) {
                float v = g_v[b * 160 + k * 16 + d];
                n2 += v * v;
            }
            nr[k] = sqrtf(n2);
            mx = fmaxf(mx, nr[k]);
        }
        float sum = 0.f;
        #pragma unroll
        for (int k = 0; k < 10; k++) {
            nr[k] = __expf(nr[k] - mx);
            sum += nr[k];
        }
        float inv = 1.f / sum;
        #pragma unroll
        for (int k = 0; k < 10; k++) out[b * 10 + k] = nr[k] * inv;
    }
}

// ---------------------------------------------------------------------------
extern "C" void kernel_launch(void* const* d_in, const int* in_sizes, int n_in,
                              void* d_out, int out_size)
{
    const float* x       = (const float*)d_in[0];
    const float* labels  = (const float*)d_in[1];
    const float* conv1_w = (const float*)d_in[2];
    const float* conv1_b = (const float*)d_in[3];
    const float* pc_w    = (const float*)d_in[4];
    const float* pc_b    = (const float*)d_in[5];
    const float* W       = (const float*)d_in[6];
    const float* fc1_w   = (const float*)d_in[7];
    const float* fc1_b   = (const float*)d_in[8];
    const float* fc2_w   = (const float*)d_in[9];
    const float* fc2_b   = (const float*)d_in[10];
    const float* fc3_w   = (const float*)d_in[11];
    const float* fc3_b   = (const float*)d_in[12];
    float* out = (float*)d_out;

    cudaFuncSetAttribute(pcgemm_kernel,
                         cudaFuncAttributeMaxDynamicSharedMemorySize, PCG_SMEM);
    cudaFuncSetAttribute(conv1gemm_kernel,
                         cudaFuncAttributeMaxDynamicSharedMemorySize, C1_SMEM);
    cudaFuncSetAttribute(wrelayout_kernel,
                         cudaFuncAttributeMaxDynamicSharedMemorySize, 43008);

    wr1_kernel<<<256, 128>>>(conv1_w);
    wrelayout_kernel<<<256, 256, 43008>>>(pc_w);
    im2col_kernel<<<BATCH, 256>>>(x);
    conv1gemm_kernel<<<3200, 256, C1_SMEM>>>(conv1_b);
    pcgemm_kernel<<<288, 256, PCG_SMEM>>>(pc_b);
    squash_h_kernel<<<BATCH, 256>>>();
    uhat_kernel<<<dim3(1152, 2), 320>>>(W);
    routing_fused_kernel<<<BATCH, 256>>>();
    gemm_kernel<0, 0><<<dim3(8, 8), 256>>>(fc1_w, fc1_b, labels, out, 512, 512, 160);
    gemm_kernel<0, 1><<<dim3(16, 8), 256>>>(fc2_w, fc2_b, nullptr, out, 512, 1024, 512);
    gemm_kernel<1, 2><<<dim3(13, 8), 256>>>(fc3_w, fc3_b, nullptr, out + 5120, 512, 784, 1024);
    probs_kernel<<<4, 128>>>(out);
}

// round 17
// speedup vs baseline: 1.5084x; 1.0367x over previous
#include <cuda_runtime.h>
#include <cuda_bf16.h>
#include <cuda_fp16.h>
#include <cstdint>
#include <math.h>

// ---------------------------------------------------------------------------
// CapsNet forward. B=512.
//   conv1 as fp16 mma.sync GEMM (im2col; M=64 N=256 tiles, 2 CTA/SM) -> g_cl
//   pcconv: fp16 mma.sync implicit GEMM (cp.async 2-stage, M=64 N=256, 2 CTA/SM)
//           -> g_pc [b][pos][oc]
//   squash -> hT; u_hat (fp16, 320-thr); routing FUSED (vsum identity,
//   8-acc phase B); decoder FCs (M-tile 32, mask fused); probs
// Output: [probs (512*10)] then [dec (512*784)]
// ---------------------------------------------------------------------------

#define BATCH 512

__device__ __half g_i2c[BATCH * 400 * 128];       // conv1 im2col [npos][128]
__device__ __half g_wr1[256 * 128];               // conv1 w [oc][tap pad 128]
__device__ __half g_cl[BATCH * 400 * 256];        // conv1 out, channel-last fp16
__device__ __half g_wr[256 * 81 * 256];           // pc weights [oc][tap][ic] fp16
__device__ float g_pc[BATCH * 36 * 256];          // [b][pos][oc]
__device__ float g_hT[BATCH * 1152 * 8];
__device__ __half g_uhat[BATCH * 1152 * 160];     // fp16 storage
__device__ float g_v[BATCH * 160];
__device__ float g_fc1[BATCH * 512];
__device__ float g_fc2[BATCH * 1024];

// ---------------- helpers ---------------------------------------------------
__device__ __forceinline__ uint32_t smem_u32(const void* p) {
    uint32_t a;
    asm("{ .reg .u64 t; cvta.to.shared.u64 t, %1; cvt.u32.u64 %0, t; }"
        : "=r"(a) : "l"(p));
    return a;
}
__device__ __forceinline__ void ldsm_x4(uint32_t& d0, uint32_t& d1,
                                        uint32_t& d2, uint32_t& d3,
                                        uint32_t addr) {
    asm volatile("ldmatrix.sync.aligned.m8n8.x4.shared.b16 {%0,%1,%2,%3}, [%4];"
                 : "=r"(d0), "=r"(d1), "=r"(d2), "=r"(d3) : "r"(addr));
}
__device__ __forceinline__ void mma16816h(float* c, const uint32_t* a,
                                          const uint32_t* b) {
    asm volatile(
        "mma.sync.aligned.m16n8k16.row.col.f32.f16.f16.f32 "
        "{%0,%1,%2,%3}, {%4,%5,%6,%7}, {%8,%9}, {%0,%1,%2,%3};"
        : "+f"(c[0]), "+f"(c[1]), "+f"(c[2]), "+f"(c[3])
        : "r"(a[0]), "r"(a[1]), "r"(a[2]), "r"(a[3]), "r"(b[0]), "r"(b[1]));
}
#define CP16(dst, src) \
    asm volatile("cp.async.cg.shared.global [%0], [%1], 16;" \
                 :: "r"(dst), "l"(src) : "memory")
#define CP_COMMIT() asm volatile("cp.async.commit_group;" ::: "memory")
#define CP_WAIT1() asm volatile("cp.async.wait_group 1;" ::: "memory")
#define CP_WAIT0() asm volatile("cp.async.wait_group 0;" ::: "memory")

// ---------------------------------------------------------------------------
// conv1 weights -> fp16 [oc][tap pad 128]. grid 256, block 128.
// ---------------------------------------------------------------------------
__global__ void wr1_kernel(const float* __restrict__ w)
{
    int oc = blockIdx.x;
    int t = threadIdx.x;
    g_wr1[oc * 128 + t] = (t < 81) ? __float2half(w[oc * 81 + t])
                                   : __float2half(0.f);
}

// ---------------------------------------------------------------------------
// im2col (x fp32 read + convert inline): -> g_i2c [npos][tap pad 128].
// grid 512, block 256.
// ---------------------------------------------------------------------------
__global__ __launch_bounds__(256) void im2col_kernel(const float* __restrict__ x)
{
    __shared__ __half s_img[784];
    __shared__ int s_off[128];
    int b = blockIdx.x;
    int tid = threadIdx.x;

    for (int i = tid; i < 784; i += 256)
        s_img[i] = __float2half(x[b * 784 + i]);
    if (tid < 128)
        s_off[tid] = (tid < 81) ? (tid / 9) * 28 + (tid % 9) : -1;
    __syncthreads();

    for (int it = tid; it < 6400; it += 256) {
        int row = it >> 4;
        int q = it & 15;
        int oy = row / 20;
        int ox = row - oy * 20;
        int base = oy * 28 + ox;
        union { __half h[8]; uint4 u; } val;
        #pragma unroll
        for (int j = 0; j < 8; j++) {
            int off = s_off[q * 8 + j];
            val.h[j] = (off >= 0) ? s_img[base + off] : __float2half(0.f);
        }
        *(uint4*)(g_i2c + (size_t)b * 51200 + row * 128 + q * 8) = val.u;
    }
}

// ---------------------------------------------------------------------------
// conv1 GEMM: C[204800,256] = relu(i2c @ W1^T + bias) -> g_cl fp16.
// M=64 x N=256 per CTA, 2 CTAs/SM, grid 3200. Warps 2(M) x 4(N).
// ---------------------------------------------------------------------------
#define C1_A0 0
#define C1_A1 8192
#define C1_B0 16384
#define C1_B1 49152
#define C1_SMEM 81920

__global__ __launch_bounds__(256, 2) void conv1gemm_kernel(
    const float* __restrict__ bias)
{
    extern __shared__ char sm[];
    int tid = threadIdx.x;
    int wid = tid >> 5;
    int lane = tid & 31;
    int warp_m = wid & 1;
    int warp_n = wid >> 1;
    int m0 = blockIdx.x * 64;
    uint32_t smb = smem_u32(sm);

    int r0 = tid >> 3;
    int c = tid & 7;
    uint32_t dbase = (uint32_t)(r0 * 128) + (uint32_t)((c * 16) ^ ((r0 & 7) << 4));

    #pragma unroll
    for (int kc2 = 0; kc2 < 2; kc2++) {
        uint32_t abase = smb + (kc2 ? C1_A1 : C1_A0);
        uint32_t bbase = smb + (kc2 ? C1_B1 : C1_B0);
        CP16(abase + dbase,
             g_i2c + (size_t)(m0 + r0) * 128 + kc2 * 64 + c * 8);
        CP16(abase + dbase + 4096,
             g_i2c + (size_t)(m0 + r0 + 32) * 128 + kc2 * 64 + c * 8);
        #pragma unroll
        for (int t = 0; t < 8; t++)
            CP16(bbase + dbase + t * 4096,
                 g_wr1 + (r0 + 32 * t) * 128 + kc2 * 64 + c * 8);
    }
    CP_COMMIT();
    CP_WAIT0();
    __syncthreads();

    float acc[2][8][4];
    #pragma unroll
    for (int i = 0; i < 2; i++)
        #pragma unroll
        for (int j = 0; j < 8; j++)
            #pragma unroll
            for (int k = 0; k < 4; k++) acc[i][j][k] = 0.f;

    uint32_t swz = (uint32_t)(lane & 7) << 4;
    uint32_t a_row_off = (uint32_t)(warp_m * 32 + (lane & 15)) * 128;
    uint32_t akb = (uint32_t)(lane >> 4) << 4;
    uint32_t b_row_off =
        (uint32_t)(warp_n * 64 + (lane & 7) + ((lane >> 4) & 1) * 8) * 128;
    uint32_t bkb = (uint32_t)((lane >> 3) & 1) << 4;

    #pragma unroll
    for (int kc2 = 0; kc2 < 2; kc2++) {
        uint32_t a_row = smb + (kc2 ? C1_A1 : C1_A0) + a_row_off;
        uint32_t b_row = smb + (kc2 ? C1_B1 : C1_B0) + b_row_off;
        #pragma unroll
        for (int j = 0; j < 4; j++) {
            uint32_t ka = ((uint32_t)(j * 32) + akb) ^ swz;
            uint32_t ah[8];
            ldsm_x4(ah[0], ah[1], ah[2], ah[3], a_row + ka);
            ldsm_x4(ah[4], ah[5], ah[6], ah[7], a_row + 2048 + ka);
            uint32_t kb = ((uint32_t)(j * 32) + bkb) ^ swz;
            uint32_t bh[16];
            #pragma unroll
            for (int q = 0; q < 4; q++) {
                uint32_t bt = b_row + (uint32_t)(q * 2048) + kb;
                ldsm_x4(bh[4 * q], bh[4 * q + 1], bh[4 * q + 2], bh[4 * q + 3], bt);
            }
            #pragma unroll
            for (int q = 0; q < 4; q++) {
                #pragma unroll
                for (int sub = 0; sub < 2; sub++) {
                    int nn = q * 2 + sub;
                    #pragma unroll
                    for (int tm = 0; tm < 2; tm++)
                        mma16816h(acc[tm][nn], &ah[4 * tm], &bh[4 * q + 2 * sub]);
                }
            }
        }
    }

    int r_in8 = lane >> 2;
    int c_in8 = (lane & 3) * 2;
    #pragma unroll
    for (int tm = 0; tm < 2; tm++) {
        size_t row0 = (size_t)(m0 + warp_m * 32 + tm * 16 + r_in8);
        size_t row1 = row0 + 8;
        #pragma unroll
        for (int nn = 0; nn < 8; nn++) {
            int col = warp_n * 64 + nn * 8 + c_in8;
            float bv0 = __ldg(bias + col);
            float bv1 = __ldg(bias + col + 1);
            const float* cc2 = acc[tm][nn];
            ((__half2*)g_cl)[(row0 * 256 + col) >> 1] =
                __floats2half2_rn(fmaxf(cc2[0] + bv0, 0.f), fmaxf(cc2[1] + bv1, 0.f));
            ((__half2*)g_cl)[(row1 * 256 + col) >> 1] =
                __floats2half2_rn(fmaxf(cc2[2] + bv0, 0.f), fmaxf(cc2[3] + bv1, 0.f));
        }
    }
}

// ---------------------------------------------------------------------------
// weight relayout: pc_w [oc][ic][81] -> g_wr [oc][tap][ic] fp16.
// ---------------------------------------------------------------------------
__global__ __launch_bounds__(256) void wrelayout_kernel(const float* __restrict__ w)
{
    extern __shared__ char wsm[];
    __half* sh = (__half*)wsm;
    int oc = blockIdx.x;
    int tid = threadIdx.x;
    const float* src = w + (size_t)oc * 20736;

    for (int j = tid; j < 20736; j += 256) {
        int ic = j / 81;
        int e = j - ic * 81;
        sh[e * 256 + ic] = __float2half(src[j]);
    }
    __syncthreads();

    uint4* dh = (uint4*)(g_wr + (size_t)oc * 20736);
    const uint4* s4 = (const uint4*)sh;
    for (int j = tid; j < 2592; j += 256) dh[j] = s4[j];
}

// ---------------------------------------------------------------------------
// pcconv: fp16 implicit GEMM, cp.async 2-stage, M=64 x N=256, 2 CTAs/SM.
// grid 288, block 256. (best measured config, unchanged.)
// ---------------------------------------------------------------------------
#define SM_A 0
#define SM_B 8192
#define STAGE 40960
#define PCG_SMEM (2 * STAGE)

__global__ __launch_bounds__(256, 2) void pcgemm_kernel(const float* __restrict__ bias)
{
    extern __shared__ char sm[];
    __shared__ int s_rowbase[64];

    int tid = threadIdx.x;
    int wid = tid >> 5;
    int lane = tid & 31;
    int warp_m = wid & 1;
    int warp_n = wid >> 1;
    int m0 = blockIdx.x * 64;
    uint32_t smb = smem_u32(sm);

    if (tid < 64) {
        int npos = m0 + tid;
        int b = npos / 36;
        int pos = npos - b * 36;
        int y = pos / 6;
        int xq = pos - y * 6;
        s_rowbase[tid] = ((b * 20 + 2 * y) * 20 + 2 * xq) * 256;
    }
    __syncthreads();

    int r0 = tid >> 3;
    int c = tid & 7;
    uint32_t dbase = (uint32_t)(r0 * 128) + (uint32_t)((c * 16) ^ ((r0 & 7) << 4));
    int rb0 = s_rowbase[r0];
    int rb1 = s_rowbase[r0 + 32];
    int bbase0 = r0 * 20736;

#define PCG_ISSUE(K) do { \
    int _kykx = (K) >> 2; \
    int _ic0 = ((K) & 3) << 6; \
    int _ky = _kykx / 9; \
    int _kx = _kykx - _ky * 9; \
    int _asrc = (_ky * 20 + _kx) * 256 + _ic0 + c * 8; \
    int _bsrc = _kykx * 256 + _ic0 + c * 8; \
    uint32_t _st = smb + ((K) & 1) * STAGE; \
    CP16(_st + SM_A + dbase, g_cl + rb0 + _asrc); \
    CP16(_st + SM_A + dbase + 4096, g_cl + rb1 + _asrc); \
    _Pragma("unroll") \
    for (int _t = 0; _t < 8; _t++) \
        CP16(_st + SM_B + dbase + _t * 4096, g_wr + bbase0 + _t * 663552 + _bsrc); \
} while (0)

    float acc[2][8][4];
    #pragma unroll
    for (int i = 0; i < 2; i++)
        #pragma unroll
        for (int j = 0; j < 8; j++)
            #pragma unroll
            for (int k = 0; k < 4; k++) acc[i][j][k] = 0.f;

    uint32_t swz = (uint32_t)(lane & 7) << 4;
    uint32_t a_row_off = SM_A + (uint32_t)(warp_m * 32 + (lane & 15)) * 128;
    uint32_t akb = (uint32_t)(lane >> 4) << 4;
    uint32_t b_row_off = SM_B +
        (uint32_t)(warp_n * 64 + (lane & 7) + ((lane >> 4) & 1) * 8) * 128;
    uint32_t bkb = (uint32_t)((lane >> 3) & 1) << 4;

    PCG_ISSUE(0);
    CP_COMMIT();

    for (int kc = 0; kc < 324; kc++) {
        if (kc < 323) {
            PCG_ISSUE(kc + 1);
            CP_COMMIT();
            CP_WAIT1();
        } else {
            CP_WAIT0();
        }
        __syncthreads();

        uint32_t st = smb + (kc & 1) * STAGE;
        uint32_t a_row = st + a_row_off;
        uint32_t b_row = st + b_row_off;
        #pragma unroll
        for (int j = 0; j < 4; j++) {
            uint32_t ka = ((uint32_t)(j * 32) + akb) ^ swz;
            uint32_t ah[8];
            ldsm_x4(ah[0], ah[1], ah[2], ah[3], a_row + ka);
            ldsm_x4(ah[4], ah[5], ah[6], ah[7], a_row + 2048 + ka);
            uint32_t kb = ((uint32_t)(j * 32) + bkb) ^ swz;
            uint32_t bh[16];
            #pragma unroll
            for (int q = 0; q < 4; q++) {
                uint32_t bt = b_row + (uint32_t)(q * 2048) + kb;
                ldsm_x4(bh[4 * q], bh[4 * q + 1], bh[4 * q + 2], bh[4 * q + 3], bt);
            }
            #pragma unroll
            for (int q = 0; q < 4; q++) {
                #pragma unroll
                for (int sub = 0; sub < 2; sub++) {
                    int nn = q * 2 + sub;
                    #pragma unroll
                    for (int tm = 0; tm < 2; tm++)
                        mma16816h(acc[tm][nn], &ah[4 * tm], &bh[4 * q + 2 * sub]);
                }
            }
        }
        __syncthreads();
    }

    // epilogue -> g_pc [b][pos][oc], float2 coalesced
    int r_in8 = lane >> 2;
    int c_in8 = (lane & 3) * 2;
    #pragma unroll
    for (int tm = 0; tm < 2; tm++) {
        int row0 = m0 + warp_m * 32 + tm * 16 + r_in8;
        int b0i = row0 / 36, p0i = row0 - b0i * 36;
        int row1 = row0 + 8;
        int b1i = row1 / 36, p1i = row1 - b1i * 36;
        #pragma unroll
        for (int nn = 0; nn < 8; nn++) {
            int col = warp_n * 64 + nn * 8 + c_in8;
            float bv0 = __ldg(bias + col);
            float bv1 = __ldg(bias + col + 1);
            const float* cc2 = acc[tm][nn];
            float2 st0;
            st0.x = cc2[0] + bv0;
            st0.y = cc2[1] + bv1;
            *(float2*)(g_pc + (size_t)b0i * 9216 + p0i * 256 + col) = st0;
            float2 st1;
            st1.x = cc2[2] + bv0;
            st1.y = cc2[3] + bv1;
            *(float2*)(g_pc + (size_t)b1i * 9216 + p1i * 256 + col) = st1;
        }
    }
}

// ---------------------------------------------------------------------------
// squash + transpose to hT. g_pc is [b][pos=36][oc=256]. grid 512, block 256.
// ---------------------------------------------------------------------------
__global__ __launch_bounds__(256) void squash_h_kernel()
{
    int b = blockIdx.x;
    int tid = threadIdx.x;
    __shared__ float s_scale[8];
    __shared__ float s_val[9216];
    int g = tid >> 5;
    int lane = tid & 31;
    const float* pb = g_pc + (size_t)b * 9216;

    float ss = 0.f;
    int cbase = g * 32 + lane;
    for (int s = 0; s < 36; s++) {
        float v = pb[s * 256 + cbase];
        ss += v * v;
    }
    #pragma unroll
    for (int o = 16; o; o >>= 1) ss += __shfl_xor_sync(0xffffffffu, ss, o);
    if (lane == 0) s_scale[g] = sqrtf(ss) / (1.f + ss);
    __syncthreads();

    for (int idx2 = tid; idx2 < 9216; idx2 += 256) {
        int s = idx2 >> 8;
        int cch = idx2 & 255;
        s_val[cch * 36 + s] = pb[idx2] * s_scale[cch >> 5];
    }
    __syncthreads();

    float* outb = g_hT + (size_t)b * 9216;
    for (int o = tid; o < 9216; o += 256) {
        int pos = o >> 3;
        int g2 = o & 7;
        int cch = g2 * 32 + pos / 36;
        int s = pos % 36;
        outb[o] = s_val[cch * 36 + s];
    }
}

// ---------------------------------------------------------------------------
// u_hat (fp16 out): grid (1152, 2), block 320.
// ---------------------------------------------------------------------------
__global__ __launch_bounds__(320) void uhat_kernel(const float* __restrict__ W)
{
    int i = blockIdx.x;
    int bh = blockIdx.y * 256;
    __shared__ float sW[1280];
    __shared__ float sh[32 * 8];
    int tid = threadIdx.x;
    for (int j = tid; j < 1280; j += 320)
        sW[(j & 7) * 160 + (j >> 3)] = W[(size_t)i * 1280 + j];

    int half = tid / 160;
    int kd = tid - half * 160;

    for (int b0 = bh; b0 < bh + 256; b0 += 32) {
        __syncthreads();
        if (tid < 256)
            sh[tid] = g_hT[((size_t)(b0 + (tid >> 3)) * 1152 + i) * 8 + (tid & 7)];
        __syncthreads();
        int bb0 = half * 16;
        #pragma unroll 4
        for (int bb = bb0; bb < bb0 + 16; bb++) {
            float u = 0.f;
            #pragma unroll
            for (int e = 0; e < 8; e++) u += sW[e * 160 + kd] * sh[bb * 8 + e];
            g_uhat[((size_t)(b0 + bb) * 1152 + i) * 160 + kd] = __float2half(u);
        }
    }
}

// ---------------------------------------------------------------------------
// FUSED routing: one block per image; r0 + iter1 + iter2, vsum identity.
// Phase B / r0 use 8 independent accumulators (MLP 8).
// ---------------------------------------------------------------------------
__global__ __launch_bounds__(256, 2) void routing_fused_kernel()
{
    __shared__ float c_s[11520];
    __shared__ float vsum_s[160];
    __shared__ float s_s[160];

    int b = blockIdx.x;
    int t = threadIdx.x;
    const __half* ub = g_uhat + (size_t)b * 184320;

    if (t < 160) {
        float p[8];
        #pragma unroll
        for (int q = 0; q < 8; q++) p[q] = 0.f;
        for (int i = 0; i < 1152; i += 8) {
            #pragma unroll
            for (int q = 0; q < 8; q++)
                p[q] += __half2float(__ldg(ub + (i + q) * 160 + t));
        }
        s_s[t] = 0.1f * (((p[0] + p[1]) + (p[2] + p[3])) +
                         ((p[4] + p[5]) + (p[6] + p[7])));
    }
    __syncthreads();
    if (t < 160) {
        int k = t >> 4;
        float n2 = 0.f;
        #pragma unroll
        for (int d = 0; d < 16; d++) {
            float v = s_s[k * 16 + d];
            n2 += v * v;
        }
        vsum_s[t] = s_s[t] * (sqrtf(n2) / (1.f + n2));
    }
    __syncthreads();

    #pragma unroll 1
    for (int r = 0; r < 2; r++) {
        for (int i = t; i < 1152; i += 256) {
            const uint4* u4 = (const uint4*)(ub + i * 160);
            float bl[10];
            float mx = -1e30f;
            #pragma unroll
            for (int k = 0; k < 10; k++) {
                uint4 ua = u4[2 * k];
                uint4 ubv = u4[2 * k + 1];
                const __half2* ha = (const __half2*)&ua;
                const __half2* hb = (const __half2*)&ubv;
                float dk = 0.f;
                #pragma unroll
                for (int j = 0; j < 4; j++) {
                    float2 f = __half22float2(ha[j]);
                    dk += f.x * vsum_s[k * 16 + 2 * j + 0];
                    dk += f.y * vsum_s[k * 16 + 2 * j + 1];
                }
                #pragma unroll
                for (int j = 0; j < 4; j++) {
                    float2 f = __half22float2(hb[j]);
                    dk += f.x * vsum_s[k * 16 + 8 + 2 * j + 0];
                    dk += f.y * vsum_s[k * 16 + 8 + 2 * j + 1];
                }
                bl[k] = dk;
                mx = fmaxf(mx, dk);
            }
            float sum = 0.f;
            #pragma unroll
            for (int k = 0; k < 10; k++) {
                float e = __expf(bl[k] - mx);
                bl[k] = e;
                sum += e;
            }
            float inv = 1.f / sum;
            #pragma unroll
            for (int k = 0; k < 10; k++) c_s[i * 10 + k] = bl[k] * inv;
        }
        __syncthreads();

        float s = 0.f;
        if (t < 160) {
            int k = t >> 4;
            float p[8];
            #pragma unroll
            for (int q = 0; q < 8; q++) p[q] = 0.f;
            for (int i = 0; i < 1152; i += 8) {
                #pragma unroll
                for (int q = 0; q < 8; q++)
                    p[q] += c_s[(i + q) * 10 + k] *
                            __half2float(__ldg(ub + (i + q) * 160 + t));
            }
            s = (((p[0] + p[1]) + (p[2] + p[3])) +
                 ((p[4] + p[5]) + (p[6] + p[7])));
        }
        __syncthreads();
        if (t < 160) s_s[t] = s;
        __syncthreads();
        if (t < 160) {
            int k = t >> 4;
            float n2 = 0.f;
            #pragma unroll
            for (int d = 0; d < 16; d++) {
                float v = s_s[k * 16 + d];
                n2 += v * v;
            }
            float v = s_s[t] * (sqrtf(n2) / (1.f + n2));
            if (r == 1) g_v[b * 160 + t] = v;
            else vsum_s[t] += v;
        }
        __syncthreads();
    }
}

// ---------------------------------------------------------------------------
// GEMM: C[M,N] = act(A @ Wt^T + bias). M-tile 32, N-tile 64 (2x4 per thread).
// SEL0 fuses mask (A = v * label).
// ---------------------------------------------------------------------------
template <int ACT, int SEL>
__global__ __launch_bounds__(256) void gemm_kernel(
    const float* __restrict__ Wt, const float* __restrict__ bias,
    const float* __restrict__ labels,
    float* __restrict__ outp, int M, int N, int K)
{
    const float* A = (SEL == 0) ? g_v : (SEL == 1) ? g_fc1 : g_fc2;
    float* C = (SEL == 0) ? g_fc1 : (SEL == 1) ? g_fc2 : outp;

    __shared__ float As[8][32];
    __shared__ float Bs[8][64];
    int n0 = blockIdx.x * 64;
    int m0 = blockIdx.y * 32;
    int tid = threadIdx.x;
    int tx = tid & 15;
    int ty = tid >> 4;

    float acc[2][4];
    #pragma unroll
    for (int i = 0; i < 2; i++)
        #pragma unroll
        for (int j = 0; j < 4; j++) acc[i][j] = 0.f;

    for (int k0 = 0; k0 < K; k0 += 8) {
        __syncthreads();
        {
            // A: 32 rows x 8 k = 256 elems, one per thread
            int r = tid >> 3;
            int kk = tid & 7;
            float a = A[(m0 + r) * K + k0 + kk];
            if (SEL == 0)
                a *= __ldg(labels + (m0 + r) * 10 + ((k0 + kk) >> 4));
            As[kk][r] = a;
            // B: 64 rows x 8 k = 512 elems, two per thread
            #pragma unroll
            for (int l = 0; l < 2; l++) {
                int e = tid + l * 256;
                int rb = e >> 3;
                int kb = e & 7;
                int n = n0 + rb;
                Bs[kb][rb] = (n < N) ? Wt[n * K + k0 + kb] : 0.f;
            }
        }
        __syncthreads();
        #pragma unroll
        for (int kk = 0; kk < 8; kk++) {
            float2 a2 = *(const float2*)&As[kk][ty * 2];
            float4 b4 = *(const float4*)&Bs[kk][tx * 4];
            float a[2] = {a2.x, a2.y};
            float bb[4] = {b4.x, b4.y, b4.z, b4.w};
            #pragma unroll
            for (int i = 0; i < 2; i++)
                #pragma unroll
                for (int j = 0; j < 4; j++) acc[i][j] += a[i] * bb[j];
        }
    }

    #pragma unroll
    for (int i = 0; i < 2; i++) {
        int m = m0 + ty * 2 + i;
        #pragma unroll
        for (int j = 0; j < 4; j++) {
            int n = n0 + tx * 4 + j;
            if (n < N) {
                float v = acc[i][j] + bias[n];
                if (ACT == 0) v = fmaxf(v, 0.f);
                else v = 1.f / (1.f + __expf(-v));
                C[m * N + n] = v;
            }
        }
    }
}

// ---------------------------------------------------------------------------
__global__ void probs_kernel(float* __restrict__ out)
{
    int b = blockIdx.x * 128 + threadIdx.x;
    if (b < BATCH) {
        float nr[10];
        float mx = -1e30f;
        #pragma unroll
        for (int k = 0; k < 10; k++) {
            float n2 = 0.f;
            #pragma unroll
            for (int d = 0; d < 16; d++) {
                float v = g_v[b * 160 + k * 16 + d];
                n2 += v * v;
            }
            nr[k] = sqrtf(n2);
            mx = fmaxf(mx, nr[k]);
        }
        float sum = 0.f;
        #pragma unroll
        for (int k = 0; k < 10; k++) {
            nr[k] = __expf(nr[k] - mx);
            sum += nr[k];
        }
        float inv = 1.f / sum;
        #pragma unroll
        for (int k = 0; k < 10; k++) out[b * 10 + k] = nr[k] * inv;
    }
}

// ---------------------------------------------------------------------------
extern "C" void kernel_launch(void* const* d_in, const int* in_sizes, int n_in,
                              void* d_out, int out_size)
{
    const float* x       = (const float*)d_in[0];
    const float* labels  = (const float*)d_in[1];
    const float* conv1_w = (const float*)d_in[2];
    const float* conv1_b = (const float*)d_in[3];
    const float* pc_w    = (const float*)d_in[4];
    const float* pc_b    = (const float*)d_in[5];
    const float* W       = (const float*)d_in[6];
    const float* fc1_w   = (const float*)d_in[7];
    const float* fc1_b   = (const float*)d_in[8];
    const float* fc2_w   = (const float*)d_in[9];
    const float* fc2_b   = (const float*)d_in[10];
    const float* fc3_w   = (const float*)d_in[11];
    const float* fc3_b   = (const float*)d_in[12];
    float* out = (float*)d_out;

    cudaFuncSetAttribute(pcgemm_kernel,
                         cudaFuncAttributeMaxDynamicSharedMemorySize, PCG_SMEM);
    cudaFuncSetAttribute(conv1gemm_kernel,
                         cudaFuncAttributeMaxDynamicSharedMemorySize, C1_SMEM);
    cudaFuncSetAttribute(wrelayout_kernel,
                         cudaFuncAttributeMaxDynamicSharedMemorySize, 43008);

    wr1_kernel<<<256, 128>>>(conv1_w);
    wrelayout_kernel<<<256, 256, 43008>>>(pc_w);
    im2col_kernel<<<BATCH, 256>>>(x);
    conv1gemm_kernel<<<3200, 256, C1_SMEM>>>(conv1_b);
    pcgemm_kernel<<<288, 256, PCG_SMEM>>>(pc_b);
    squash_h_kernel<<<BATCH, 256>>>();
    uhat_kernel<<<dim3(1152, 2), 320>>>(W);
    routing_fused_kernel<<<BATCH, 256>>>();
    gemm_kernel<0, 0><<<dim3(8, 16), 256>>>(fc1_w, fc1_b, labels, out, 512, 512, 160);
    gemm_kernel<0, 1><<<dim3(16, 16), 256>>>(fc2_w, fc2_b, nullptr, out, 512, 1024, 512);
    gemm_kernel<1, 2><<<dim3(13, 16), 256>>>(fc3_w, fc3_b, nullptr, out + 5120, 512, 784, 1024);
    probs_kernel<<<4, 128>>>(out);
}